// round 10
// baseline (speedup 1.0000x reference)
#include <cuda_runtime.h>
#include <cuda_bf16.h>
#include <cstdint>
#include <math.h>

// ---------------- problem constants ----------------
#define S_   2048
#define H_   2048
#define NH_  16
#define NOPE_ 128
#define ROPE_ 64
#define QHD_ 192     // NOPE+ROPE
#define VHD_ 128
#define QLR_ 1536
#define KVLR_ 512
#define FF_  8192
#define CKVD_ (KVLR_ + ROPE_)   // 576
#define QDIM_ (NH_*QHD_)        // 3072
#define KVDIM_ (NH_*(NOPE_+VHD_)) // 4096
#define SCALE_ 0.07216878364870323f  // 192^-0.5

// ---------------- scratch (static device globals; no runtime alloc) ----------------
__device__ float g_xnorm [S_*H_];
__device__ float g_qlat  [S_*QLR_];
__device__ float g_q     [S_*QDIM_];
__device__ float g_ckv   [S_*CKVD_];
__device__ float g_kvn   [S_*KVLR_];
__device__ float g_kv    [S_*KVDIM_];
__device__ float g_kpe   [S_*ROPE_];
__device__ float g_attn  [S_*H_];
__device__ float g_hid2  [S_*H_];
__device__ float g_ynorm [S_*H_];
__device__ float g_gate  [S_*FF_];
__device__ float g_up    [S_*FF_];

// ---------------- helpers ----------------
__device__ __forceinline__ float tf32r(float x) {
    uint32_t u = __float_as_uint(x), r;
    asm("cvt.rna.tf32.f32 %0, %1;" : "=r"(r) : "r"(u));
    return __uint_as_float(r);
}
__device__ __forceinline__ uint32_t tf32u(float x) {
    uint32_t u = __float_as_uint(x), r;
    asm("cvt.rna.tf32.f32 %0, %1;" : "=r"(r) : "r"(u));
    return r;
}

__device__ __forceinline__ float warp_sum(float v) {
    #pragma unroll
    for (int o = 16; o; o >>= 1) v += __shfl_xor_sync(0xffffffffu, v, o);
    return v;
}

__device__ __forceinline__ void mma_tf32(float* d, const uint32_t* a, const uint32_t* b) {
    asm volatile(
        "mma.sync.aligned.m16n8k8.row.col.f32.tf32.tf32.f32 "
        "{%0,%1,%2,%3}, {%4,%5,%6,%7}, {%8,%9}, {%0,%1,%2,%3};"
        : "+f"(d[0]), "+f"(d[1]), "+f"(d[2]), "+f"(d[3])
        : "r"(a[0]), "r"(a[1]), "r"(a[2]), "r"(a[3]), "r"(b[0]), "r"(b[1]));
}

// ---------------- rmsnorm: one block per row, tf32-rounded output ----------------
__global__ void rms_kernel(const float* __restrict__ in, const float* __restrict__ w,
                           float* __restrict__ out, int dim, int istride, int ostride) {
    int row = blockIdx.x;
    const float* x = in + (size_t)row * istride;
    float* y = out + (size_t)row * ostride;
    float s = 0.f;
    for (int i = threadIdx.x; i < dim; i += blockDim.x) { float v = x[i]; s += v * v; }
    __shared__ float red[8];
    int lane = threadIdx.x & 31, wid = threadIdx.x >> 5;
    s = warp_sum(s);
    if (lane == 0) red[wid] = s;
    __syncthreads();
    if (wid == 0) {
        float r = (lane < (int)(blockDim.x >> 5)) ? red[lane] : 0.f;
        r = warp_sum(r);
        if (lane == 0) red[0] = r;
    }
    __syncthreads();
    float inv = rsqrtf(red[0] / (float)dim + 1e-6f);
    for (int i = threadIdx.x; i < dim; i += blockDim.x) y[i] = tf32r(x[i] * inv * w[i]);
}

// ---------------- tf32 tensor-core GEMM: C = A@B (+ Cadd) ----------------
// A [M,K] row-major (pre-rounded tf32 activations), B [K,N] raw fp32 (rounded
// in-register). M%128==0, N%BN==0, K%32==0.
// 256 threads, BM=128, BN template, BK=32; 3-stage cp.async pipeline with ONE
// __syncthreads per K-tile: at iter kt, tile kt+1 is in flight, tile kt+2 is
// issued before compute(kt) -> memory latency fully overlapped with MMAs.
#define APITCH_ 36

template<int BN>
__global__ __launch_bounds__(256, 2) void gemm_tf32(
        const float* __restrict__ A, const float* __restrict__ B,
        const float* __restrict__ Cadd, float* __restrict__ C,
        int M, int N, int K) {
    constexpr int BPITCH = BN + 8;                  // %32==8 -> conflict-free frags
    constexpr int NT = BN / 16;
    constexpr int STAGE = 128 * APITCH_ + 32 * BPITCH;
    extern __shared__ float smem[];
    const int t = threadIdx.x;
    const int warp = t >> 5, lane = t & 31;
    const int wm = warp >> 1, wn = warp & 1;
    const int g = lane >> 2, t4 = lane & 3;
    const int m0 = blockIdx.y * 128, n0 = blockIdx.x * BN;

    float acc[2][NT][4] = {};

    auto load_stage = [&](int st, int kt) {
        float* as = smem + st * STAGE;
        float* bs = as + 128 * APITCH_;
        const int k0 = kt * 32;
        #pragma unroll
        for (int i = 0; i < 4; i++) {               // A: 128x32 = 1024 16B chunks
            int id = t + i * 256;
            int row = id >> 3, c = id & 7;
            uint32_t dst = (uint32_t)__cvta_generic_to_shared(as + row * APITCH_ + c * 4);
            const float* src = A + (size_t)(m0 + row) * K + k0 + c * 4;
            asm volatile("cp.async.cg.shared.global [%0], [%1], 16;\n" :: "r"(dst), "l"(src));
        }
        #pragma unroll
        for (int i = 0; i < BN / 32; i++) {         // B: 32xBN 16B chunks
            int id = t + i * 256;
            int row, c;
            if (BN == 128) { row = id >> 5; c = id & 31; }
            else           { row = id >> 4; c = id & 15; }
            uint32_t dst = (uint32_t)__cvta_generic_to_shared(bs + row * BPITCH + c * 4);
            const float* src = B + (size_t)(k0 + row) * N + n0 + c * 4;
            asm volatile("cp.async.cg.shared.global [%0], [%1], 16;\n" :: "r"(dst), "l"(src));
        }
        asm volatile("cp.async.commit_group;\n");
    };

    auto compute = [&](int st) {
        const float* as = smem + st * STAGE;
        const float* bs = as + 128 * APITCH_;
        #pragma unroll
        for (int ks = 0; ks < 4; ks++) {
            const int k0 = ks * 8;
            uint32_t af[2][4], bf[NT][2];
            #pragma unroll
            for (int i = 0; i < 2; i++) {
                int rbase = wm * 32 + i * 16;
                af[i][0] = __float_as_uint(as[(rbase + g    ) * APITCH_ + k0 + t4]);
                af[i][1] = __float_as_uint(as[(rbase + 8 + g) * APITCH_ + k0 + t4]);
                af[i][2] = __float_as_uint(as[(rbase + g    ) * APITCH_ + k0 + 4 + t4]);
                af[i][3] = __float_as_uint(as[(rbase + 8 + g) * APITCH_ + k0 + 4 + t4]);
            }
            #pragma unroll
            for (int j = 0; j < NT; j++) {
                int cbase = wn * (BN / 2) + j * 8 + g;
                bf[j][0] = tf32u(bs[(k0 + t4    ) * BPITCH + cbase]);
                bf[j][1] = tf32u(bs[(k0 + 4 + t4) * BPITCH + cbase]);
            }
            #pragma unroll
            for (int i = 0; i < 2; i++)
                #pragma unroll
                for (int j = 0; j < NT; j++)
                    mma_tf32(acc[i][j], af[i], bf[j]);
        }
    };

    const int nk = K / 32;
    // prologue: tiles 0 and 1 in flight
    load_stage(0, 0);
    if (nk > 1) load_stage(1, 1);

    for (int kt = 0; kt < nk; kt++) {
        // wait for tile kt: after this, at most tile kt+1 remains in flight
        if (kt + 1 < nk) { asm volatile("cp.async.wait_group 1;\n"); }
        else             { asm volatile("cp.async.wait_group 0;\n"); }
        __syncthreads();   // all warps done with compute(kt-1); tile kt visible
        if (kt + 2 < nk) load_stage((kt + 2) % 3, kt + 2);   // overwrites tile kt-1's stage
        compute(kt % 3);
    }

    // epilogue
    #pragma unroll
    for (int i = 0; i < 2; i++) {
        int r0 = m0 + wm * 32 + i * 16 + g;
        #pragma unroll
        for (int j = 0; j < NT; j++) {
            int cc = n0 + wn * (BN / 2) + j * 8 + 2 * t4;
            size_t o0 = (size_t)r0 * N + cc;
            size_t o1 = (size_t)(r0 + 8) * N + cc;
            float v0 = acc[i][j][0], v1 = acc[i][j][1];
            float v2 = acc[i][j][2], v3 = acc[i][j][3];
            if (Cadd) { v0 += Cadd[o0]; v1 += Cadd[o0 + 1]; v2 += Cadd[o1]; v3 += Cadd[o1 + 1]; }
            C[o0] = v0; C[o0 + 1] = v1; C[o1] = v2; C[o1 + 1] = v3;
        }
    }
}

#define GEMM_SMEM_128 (3 * (128*APITCH_ + 32*136) * 4)
#define GEMM_SMEM_64  (3 * (128*APITCH_ + 32*72)  * 4)

// ---------------- RoPE (interleaved permute + rotate-half) ----------------
__global__ void rope_kernel(float* __restrict__ q, const float* __restrict__ ckv,
                            float* __restrict__ kpe,
                            const float* __restrict__ cosb, const float* __restrict__ sinb,
                            const int* __restrict__ pos_ids) {
    int s = blockIdx.x;
    int pos = pos_ids[s];
    const float* c  = cosb + (size_t)pos * ROPE_;
    const float* sn = sinb + (size_t)pos * ROPE_;
    int t = threadIdx.x;
    float ox[4], oy[4];
    #pragma unroll
    for (int it = 0; it < 4; it++) {
        int item = t + it * 128;
        int h = item >> 5, i = item & 31;
        float* base = q + (size_t)s * QDIM_ + h * QHD_ + NOPE_;
        float x0 = base[2 * i], x1 = base[2 * i + 1];
        ox[it] = x0 * c[i]      - x1 * sn[i];
        oy[it] = x1 * c[i + 32] + x0 * sn[i + 32];
    }
    __syncthreads();
    #pragma unroll
    for (int it = 0; it < 4; it++) {
        int item = t + it * 128;
        int h = item >> 5, i = item & 31;
        float* base = q + (size_t)s * QDIM_ + h * QHD_ + NOPE_;
        base[i]      = ox[it];
        base[i + 32] = oy[it];
    }
    if (t < 32) {
        const float* kb = ckv + (size_t)s * CKVD_ + KVLR_;
        float x0 = kb[2 * t], x1 = kb[2 * t + 1];
        kpe[(size_t)s * ROPE_ + t]      = x0 * c[t]      - x1 * sn[t];
        kpe[(size_t)s * ROPE_ + 32 + t] = x1 * c[t + 32] + x0 * sn[t + 32];
    }
}

// ---------------- tensor-core causal flash attention (tf32 mma) ----------------
#define QP_ 196
#define KP_ 196
#define VP_ 136
#define PP_ 68
#define ATT_SMEM_FLOATS (64*QP_ + 64*KP_ + 64*VP_ + 64*PP_)

__global__ __launch_bounds__(128, 1) void attn_mma_kernel(
        const float* __restrict__ q, const float* __restrict__ kv,
        const float* __restrict__ kpe, float* __restrict__ out) {
    extern __shared__ float smem[];
    float* qs = smem;                 // [64][QP_]
    float* ks = qs + 64 * QP_;        // [64][KP_]
    float* vs = ks + 64 * KP_;        // [64][VP_]
    float* ps = vs + 64 * VP_;        // [64][PP_]

    const int h = blockIdx.y;
    const int qblk = (int)gridDim.x - 1 - (int)blockIdx.x;
    const int t = threadIdx.x;
    const int warp = t >> 5, lane = t & 31;
    const int g = lane >> 2, t4 = lane & 3;
    const int qbase = qblk * 64;
    const int wrow = warp * 16;

    for (int idx = t * 4; idx < 64 * 192; idx += 128 * 4) {
        int row = idx / 192, col = idx - row * 192;
        float4 v = *(const float4*)&q[(size_t)(qbase + row) * QDIM_ + h * QHD_ + col];
        *(float4*)&qs[row * QP_ + col] = v;
    }

    float oa[16][4];
    #pragma unroll
    for (int j = 0; j < 16; j++)
        #pragma unroll
        for (int c = 0; c < 4; c++) oa[j][c] = 0.f;
    float m0 = -1e30f, m1 = -1e30f, l0 = 0.f, l1 = 0.f;

    for (int kt = 0; kt <= qblk; kt++) {
        const int kbase = kt * 64;
        __syncthreads();
        for (int idx = t * 4; idx < 64 * 192; idx += 128 * 4) {
            int row = idx / 192, col = idx - row * 192;
            int key = kbase + row;
            float4 v = (col < 128)
                ? *(const float4*)&kv[(size_t)key * KVDIM_ + h * 256 + col]
                : *(const float4*)&kpe[(size_t)key * ROPE_ + (col - 128)];
            *(float4*)&ks[row * KP_ + col] = v;
        }
        for (int idx = t * 4; idx < 64 * 128; idx += 128 * 4) {
            int row = idx >> 7, col = idx & 127;
            float4 v = *(const float4*)&kv[(size_t)(kbase + row) * KVDIM_ + h * 256 + 128 + col];
            *(float4*)&vs[row * VP_ + col] = v;
        }
        __syncthreads();

        float sa[8][4];
        #pragma unroll
        for (int j = 0; j < 8; j++)
            #pragma unroll
            for (int c = 0; c < 4; c++) sa[j][c] = 0.f;
        #pragma unroll
        for (int kc = 0; kc < 24; kc++) {
            const int k0 = kc * 8;
            uint32_t af[4], bf[8][2];
            af[0] = __float_as_uint(qs[(wrow + g    ) * QP_ + k0 + t4]);
            af[1] = __float_as_uint(qs[(wrow + 8 + g) * QP_ + k0 + t4]);
            af[2] = __float_as_uint(qs[(wrow + g    ) * QP_ + k0 + 4 + t4]);
            af[3] = __float_as_uint(qs[(wrow + 8 + g) * QP_ + k0 + 4 + t4]);
            #pragma unroll
            for (int j = 0; j < 8; j++) {
                bf[j][0] = __float_as_uint(ks[(j * 8 + g) * KP_ + k0 + t4]);
                bf[j][1] = __float_as_uint(ks[(j * 8 + g) * KP_ + k0 + 4 + t4]);
            }
            #pragma unroll
            for (int j = 0; j < 8; j++) mma_tf32(sa[j], af, bf[j]);
        }

        const int r0 = qbase + wrow + g;
        const int r1 = r0 + 8;
        const bool diag = (kt == qblk);
        #pragma unroll
        for (int j = 0; j < 8; j++) {
            int c0 = kbase + j * 8 + 2 * t4, c1 = c0 + 1;
            sa[j][0] *= SCALE_; sa[j][1] *= SCALE_;
            sa[j][2] *= SCALE_; sa[j][3] *= SCALE_;
            if (diag) {
                if (c0 > r0) sa[j][0] = -1e30f;
                if (c1 > r0) sa[j][1] = -1e30f;
                if (c0 > r1) sa[j][2] = -1e30f;
                if (c1 > r1) sa[j][3] = -1e30f;
            }
        }

        float tm0 = -1e30f, tm1 = -1e30f;
        #pragma unroll
        for (int j = 0; j < 8; j++) {
            tm0 = fmaxf(tm0, fmaxf(sa[j][0], sa[j][1]));
            tm1 = fmaxf(tm1, fmaxf(sa[j][2], sa[j][3]));
        }
        tm0 = fmaxf(tm0, __shfl_xor_sync(0xffffffffu, tm0, 1));
        tm0 = fmaxf(tm0, __shfl_xor_sync(0xffffffffu, tm0, 2));
        tm1 = fmaxf(tm1, __shfl_xor_sync(0xffffffffu, tm1, 1));
        tm1 = fmaxf(tm1, __shfl_xor_sync(0xffffffffu, tm1, 2));
        float m0n = fmaxf(m0, tm0), m1n = fmaxf(m1, tm1);
        float a0 = __expf(m0 - m0n), a1 = __expf(m1 - m1n);
        float ps0 = 0.f, ps1 = 0.f;
        #pragma unroll
        for (int j = 0; j < 8; j++) {
            sa[j][0] = __expf(sa[j][0] - m0n); sa[j][1] = __expf(sa[j][1] - m0n);
            sa[j][2] = __expf(sa[j][2] - m1n); sa[j][3] = __expf(sa[j][3] - m1n);
            ps0 += sa[j][0] + sa[j][1];
            ps1 += sa[j][2] + sa[j][3];
        }
        ps0 += __shfl_xor_sync(0xffffffffu, ps0, 1);
        ps0 += __shfl_xor_sync(0xffffffffu, ps0, 2);
        ps1 += __shfl_xor_sync(0xffffffffu, ps1, 1);
        ps1 += __shfl_xor_sync(0xffffffffu, ps1, 2);
        l0 = l0 * a0 + ps0; l1 = l1 * a1 + ps1;
        m0 = m0n; m1 = m1n;
        #pragma unroll
        for (int j = 0; j < 16; j++) {
            oa[j][0] *= a0; oa[j][1] *= a0;
            oa[j][2] *= a1; oa[j][3] *= a1;
        }
        #pragma unroll
        for (int j = 0; j < 8; j++) {
            int cc = j * 8 + 2 * t4;
            ps[(wrow + g    ) * PP_ + cc]     = sa[j][0];
            ps[(wrow + g    ) * PP_ + cc + 1] = sa[j][1];
            ps[(wrow + 8 + g) * PP_ + cc]     = sa[j][2];
            ps[(wrow + 8 + g) * PP_ + cc + 1] = sa[j][3];
        }
        __syncwarp();

        #pragma unroll
        for (int kc = 0; kc < 8; kc++) {
            const int k0 = kc * 8;
            uint32_t af[4], bf[16][2];
            af[0] = __float_as_uint(ps[(wrow + g    ) * PP_ + k0 + t4]);
            af[1] = __float_as_uint(ps[(wrow + 8 + g) * PP_ + k0 + t4]);
            af[2] = __float_as_uint(ps[(wrow + g    ) * PP_ + k0 + 4 + t4]);
            af[3] = __float_as_uint(ps[(wrow + 8 + g) * PP_ + k0 + 4 + t4]);
            #pragma unroll
            for (int j = 0; j < 16; j++) {
                bf[j][0] = __float_as_uint(vs[(k0 + t4    ) * VP_ + j * 8 + g]);
                bf[j][1] = __float_as_uint(vs[(k0 + 4 + t4) * VP_ + j * 8 + g]);
            }
            #pragma unroll
            for (int j = 0; j < 16; j++) mma_tf32(oa[j], af, bf[j]);
        }
    }

    float i0 = 1.f / l0, i1 = 1.f / l1;
    const int r0 = qbase + wrow + g;
    float* o0 = out + (size_t)r0 * H_ + h * VHD_;
    float* o1 = out + (size_t)(r0 + 8) * H_ + h * VHD_;
    #pragma unroll
    for (int j = 0; j < 16; j++) {
        int cc = j * 8 + 2 * t4;
        o0[cc]     = tf32r(oa[j][0] * i0);
        o0[cc + 1] = tf32r(oa[j][1] * i0);
        o1[cc]     = tf32r(oa[j][2] * i1);
        o1[cc + 1] = tf32r(oa[j][3] * i1);
    }
}

// ---------------- silu(gate) * up, in place into gate (tf32-rounded) ----------------
__global__ void silu_mul_kernel(float* __restrict__ g, const float* __restrict__ u, int n) {
    int i = blockIdx.x * blockDim.x + threadIdx.x;
    if (i < n) {
        float x = g[i];
        float s = x / (1.f + __expf(-x));
        g[i] = tf32r(s * u[i]);
    }
}

// ---------------- launcher ----------------
extern "C" void kernel_launch(void* const* d_in, const int* in_sizes, int n_in,
                              void* d_out, int out_size) {
    const float* hidden  = (const float*)d_in[0];
    const float* sinb    = (const float*)d_in[1];
    const float* cosb    = (const float*)d_in[2];
    const float* wq_a    = (const float*)d_in[3];
    const float* q_a_ln  = (const float*)d_in[4];
    const float* wq_b    = (const float*)d_in[5];
    const float* wkv_a   = (const float*)d_in[6];
    const float* kv_a_ln = (const float*)d_in[7];
    const float* wkv_b   = (const float*)d_in[8];
    const float* wo      = (const float*)d_in[9];
    const float* in_ln   = (const float*)d_in[10];
    const float* post_ln = (const float*)d_in[11];
    const float* w_gate  = (const float*)d_in[12];
    const float* w_up    = (const float*)d_in[13];
    const float* w_down  = (const float*)d_in[14];
    const int*   pos     = (const int*)d_in[15];
    float* outp = (float*)d_out;

    float *xnorm, *qlat, *qb, *ckv, *kvn, *kvb, *kpe, *attn, *hid2, *ynorm, *gate, *up;
    cudaGetSymbolAddress((void**)&xnorm, g_xnorm);
    cudaGetSymbolAddress((void**)&qlat,  g_qlat);
    cudaGetSymbolAddress((void**)&qb,    g_q);
    cudaGetSymbolAddress((void**)&ckv,   g_ckv);
    cudaGetSymbolAddress((void**)&kvn,   g_kvn);
    cudaGetSymbolAddress((void**)&kvb,   g_kv);
    cudaGetSymbolAddress((void**)&kpe,   g_kpe);
    cudaGetSymbolAddress((void**)&attn,  g_attn);
    cudaGetSymbolAddress((void**)&hid2,  g_hid2);
    cudaGetSymbolAddress((void**)&ynorm, g_ynorm);
    cudaGetSymbolAddress((void**)&gate,  g_gate);
    cudaGetSymbolAddress((void**)&up,    g_up);

    const size_t attn_smem = ATT_SMEM_FLOATS * sizeof(float);
    cudaFuncSetAttribute(attn_mma_kernel, cudaFuncAttributeMaxDynamicSharedMemorySize, (int)attn_smem);
    cudaFuncSetAttribute(gemm_tf32<128>, cudaFuncAttributeMaxDynamicSharedMemorySize, GEMM_SMEM_128);
    cudaFuncSetAttribute(gemm_tf32<64>,  cudaFuncAttributeMaxDynamicSharedMemorySize, GEMM_SMEM_64);

    dim3 blk256(256);
    auto gemm128 = [&](const float* A, const float* B, const float* Cadd, float* C,
                       int M, int N, int K) {
        gemm_tf32<128><<<dim3(N / 128, M / 128), blk256, GEMM_SMEM_128>>>(A, B, Cadd, C, M, N, K);
    };
    auto gemm64 = [&](const float* A, const float* B, const float* Cadd, float* C,
                      int M, int N, int K) {
        gemm_tf32<64><<<dim3(N / 64, M / 128), blk256, GEMM_SMEM_64>>>(A, B, Cadd, C, M, N, K);
    };

    // 1) x = rms(hidden, in_ln)
    rms_kernel<<<S_, 256>>>(hidden, in_ln, xnorm, H_, H_, H_);
    // 2) q_lat = x @ wq_a
    gemm128(xnorm, wq_a, nullptr, qlat, S_, QLR_, H_);
    // 3) q_lat = rms(q_lat, q_a_ln)
    rms_kernel<<<S_, 256>>>(qlat, q_a_ln, qlat, QLR_, QLR_, QLR_);
    // 4) q = q_lat @ wq_b
    gemm128(qlat, wq_b, nullptr, qb, S_, QDIM_, QLR_);
    // 5) ckv = x @ wkv_a   (N=576 -> BN=64)
    gemm64(xnorm, wkv_a, nullptr, ckv, S_, CKVD_, H_);
    // 6) kv_n = rms(ckv[:, :512], kv_a_ln)
    rms_kernel<<<S_, 256>>>(ckv, kv_a_ln, kvn, KVLR_, CKVD_, KVLR_);
    // 7) kv = kv_n @ wkv_b
    gemm128(kvn, wkv_b, nullptr, kvb, S_, KVDIM_, KVLR_);
    // 8) RoPE
    rope_kernel<<<S_, 128>>>(qb, ckv, kpe, cosb, sinb, pos);
    // 9) attention (tensor-core flash)
    attn_mma_kernel<<<dim3(S_/64, NH_), 128, attn_smem>>>(qb, kvb, kpe, attn);
    // 10) hid2 = hidden + attn @ wo
    gemm128(attn, wo, hidden, hid2, S_, H_, H_);
    // 11) y = rms(hid2, post_ln)
    rms_kernel<<<S_, 256>>>(hid2, post_ln, ynorm, H_, H_, H_);
    // 12) gate = y @ w_gate
    gemm128(ynorm, w_gate, nullptr, gate, S_, FF_, H_);
    // 13) up = y @ w_up
    gemm128(ynorm, w_up, nullptr, up, S_, FF_, H_);
    // 14) gate = silu(gate) * up
    {
        int n = S_ * FF_;
        silu_mul_kernel<<<(n + 255) / 256, 256>>>(gate, up, n);
    }
    // 15) out = hid2 + gate @ w_down
    gemm128(gate, w_down, hid2, outp, S_, H_, FF_);
}

// round 11
// speedup vs baseline: 1.4585x; 1.4585x over previous
#include <cuda_runtime.h>
#include <cuda_fp16.h>
#include <cuda_bf16.h>
#include <cstdint>
#include <math.h>

// ---------------- problem constants ----------------
#define S_   2048
#define H_   2048
#define NH_  16
#define NOPE_ 128
#define ROPE_ 64
#define QHD_ 192     // NOPE+ROPE
#define VHD_ 128
#define QLR_ 1536
#define KVLR_ 512
#define FF_  8192
#define CKVD_ (KVLR_ + ROPE_)   // 576
#define QDIM_ (NH_*QHD_)        // 3072
#define KVDIM_ (NH_*(NOPE_+VHD_)) // 4096
#define SCALE_ 0.07216878364870323f  // 192^-0.5

// ---------------- scratch (static device globals; no runtime alloc) ----------------
__device__ float  g_qlat  [S_*QLR_];
__device__ float  g_q     [S_*QDIM_];
__device__ float  g_ckv   [S_*CKVD_];
__device__ float  g_kv    [S_*KVDIM_];
__device__ float  g_kpe   [S_*ROPE_];
__device__ float  g_hid2  [S_*H_];
__device__ float  g_gate  [S_*FF_];
__device__ float  g_up    [S_*FF_];

__device__ __half g_xnorm16 [S_*H_];
__device__ __half g_qlat16  [S_*QLR_];
__device__ __half g_kvn16   [S_*KVLR_];
__device__ __half g_attn16  [S_*H_];
__device__ __half g_ynorm16 [S_*H_];
__device__ __half g_gate16  [S_*FF_];

// fp16 weights, k-pair-interleaved: word (p,n) = (w[2p][n], w[2p+1][n])
__device__ uint32_t g_wqa16  [(H_/2)*QLR_];
__device__ uint32_t g_wqb16  [(QLR_/2)*QDIM_];
__device__ uint32_t g_wkva16 [(H_/2)*CKVD_];
__device__ uint32_t g_wkvb16 [(KVLR_/2)*KVDIM_];
__device__ uint32_t g_wo16   [(H_/2)*H_];
__device__ uint32_t g_wg16   [(H_/2)*FF_];
__device__ uint32_t g_wu16   [(H_/2)*FF_];
__device__ uint32_t g_wd16   [(FF_/2)*H_];

// ---------------- helpers ----------------
__device__ __forceinline__ float tf32r(float x) {
    uint32_t u = __float_as_uint(x), r;
    asm("cvt.rna.tf32.f32 %0, %1;" : "=r"(r) : "r"(u));
    return __uint_as_float(r);
}

__device__ __forceinline__ float warp_sum(float v) {
    #pragma unroll
    for (int o = 16; o; o >>= 1) v += __shfl_xor_sync(0xffffffffu, v, o);
    return v;
}

__device__ __forceinline__ void mma_tf32(float* d, const uint32_t* a, const uint32_t* b) {
    asm volatile(
        "mma.sync.aligned.m16n8k8.row.col.f32.tf32.tf32.f32 "
        "{%0,%1,%2,%3}, {%4,%5,%6,%7}, {%8,%9}, {%0,%1,%2,%3};"
        : "+f"(d[0]), "+f"(d[1]), "+f"(d[2]), "+f"(d[3])
        : "r"(a[0]), "r"(a[1]), "r"(a[2]), "r"(a[3]), "r"(b[0]), "r"(b[1]));
}

__device__ __forceinline__ void mma_fp16(float* d, const uint32_t* a, const uint32_t* b) {
    asm volatile(
        "mma.sync.aligned.m16n8k16.row.col.f32.f16.f16.f32 "
        "{%0,%1,%2,%3}, {%4,%5,%6,%7}, {%8,%9}, {%0,%1,%2,%3};"
        : "+f"(d[0]), "+f"(d[1]), "+f"(d[2]), "+f"(d[3])
        : "r"(a[0]), "r"(a[1]), "r"(a[2]), "r"(a[3]), "r"(b[0]), "r"(b[1]));
}

// ---------------- weight convert: fp32 [K][N] -> u32 pair words [K/2][N] ----------------
__global__ void cvt_pair_kernel(const float* __restrict__ w, uint32_t* __restrict__ o,
                                int K2, int N) {
    int idx = blockIdx.x * blockDim.x + threadIdx.x;
    if (idx < K2 * N) {
        int p = idx / N, n = idx - p * N;
        __half lo = __float2half(w[(size_t)(2 * p) * N + n]);
        __half hi = __float2half(w[(size_t)(2 * p + 1) * N + n]);
        __half2 h2 = __halves2half2(lo, hi);
        o[idx] = *(uint32_t*)&h2;
    }
}

// ---------------- rmsnorm: one block per row, fp16 output ----------------
__global__ void rms_kernel(const float* __restrict__ in, const float* __restrict__ w,
                           __half* __restrict__ out, int dim, int istride, int ostride) {
    int row = blockIdx.x;
    const float* x = in + (size_t)row * istride;
    __half* y = out + (size_t)row * ostride;
    float s = 0.f;
    for (int i = threadIdx.x; i < dim; i += blockDim.x) { float v = x[i]; s += v * v; }
    __shared__ float red[8];
    int lane = threadIdx.x & 31, wid = threadIdx.x >> 5;
    s = warp_sum(s);
    if (lane == 0) red[wid] = s;
    __syncthreads();
    if (wid == 0) {
        float r = (lane < (int)(blockDim.x >> 5)) ? red[lane] : 0.f;
        r = warp_sum(r);
        if (lane == 0) red[0] = r;
    }
    __syncthreads();
    float inv = rsqrtf(red[0] / (float)dim + 1e-6f);
    for (int i = threadIdx.x; i < dim; i += blockDim.x)
        y[i] = __float2half(x[i] * inv * w[i]);
}

// ---------------- fp16 tensor-core GEMM: C = A@B (+ Cadd), fp32 accumulate --------
// A [M,K] fp16 row-major. Bw: pair-interleaved u32 words [K/2][N].
// M%128==0, N%BN==0, K%32==0. 256 threads, BM=128, BK=32, 3-stage cp.async.
#define AP16 20    // A pitch in u32 words (16 data + 4 pad); (g*20+t4)%32 unique

template<int BN>
__global__ __launch_bounds__(256, 2) void gemm_fp16(
        const __half* __restrict__ A, const uint32_t* __restrict__ Bw,
        const float* __restrict__ Cadd, float* __restrict__ C,
        int M, int N, int K) {
    constexpr int BP16 = BN + 8;                  // pitch%32==8 -> frag conflict-free
    constexpr int NT = BN / 16;                   // n8-tiles per warp
    constexpr int STAGE = 128 * AP16 + 16 * BP16; // u32 words
    extern __shared__ uint32_t smw[];
    const int t = threadIdx.x;
    const int warp = t >> 5, lane = t & 31;
    const int wm = warp >> 1, wn = warp & 1;      // 4x2 warps: 32 rows x BN/2 cols
    const int g = lane >> 2, t4 = lane & 3;
    const int m0 = blockIdx.y * 128, n0 = blockIdx.x * BN;

    float acc[2][NT][4] = {};

    auto load_stage = [&](int st, int kt) {
        uint32_t* as = smw + st * STAGE;
        uint32_t* bs = as + 128 * AP16;
        // A: 128 rows x 32 halves = 512 chunks of 16B (8 halves)
        #pragma unroll
        for (int i = 0; i < 2; i++) {
            int id = t + i * 256;
            int row = id >> 2, c = id & 3;
            uint32_t dst = (uint32_t)__cvta_generic_to_shared(as + row * AP16 + c * 4);
            const __half* src = A + (size_t)(m0 + row) * K + kt * 32 + c * 8;
            asm volatile("cp.async.cg.shared.global [%0], [%1], 16;\n" :: "r"(dst), "l"(src));
        }
        // B: 16 pair-rows x BN words
        #pragma unroll
        for (int i = 0; i < BN / 64; i++) {
            int id = t + i * 256;
            int prow, c;
            if (BN == 128) { prow = id >> 5; c = id & 31; }
            else           { prow = id >> 4; c = id & 15; }
            uint32_t dst = (uint32_t)__cvta_generic_to_shared(bs + prow * BP16 + c * 4);
            const uint32_t* src = Bw + (size_t)(kt * 16 + prow) * N + n0 + c * 4;
            asm volatile("cp.async.cg.shared.global [%0], [%1], 16;\n" :: "r"(dst), "l"(src));
        }
        asm volatile("cp.async.commit_group;\n");
    };

    auto compute = [&](int st) {
        const uint32_t* as = smw + st * STAGE;
        const uint32_t* bs = as + 128 * AP16;
        #pragma unroll
        for (int kc = 0; kc < 2; kc++) {          // two k16 chunks per K-tile
            const int kw = kc * 8;
            uint32_t af[2][4], bf[NT][2];
            #pragma unroll
            for (int i = 0; i < 2; i++) {
                int rbase = wm * 32 + i * 16;
                af[i][0] = as[(rbase + g    ) * AP16 + kw + t4];
                af[i][1] = as[(rbase + 8 + g) * AP16 + kw + t4];
                af[i][2] = as[(rbase + g    ) * AP16 + kw + 4 + t4];
                af[i][3] = as[(rbase + 8 + g) * AP16 + kw + 4 + t4];
            }
            #pragma unroll
            for (int j = 0; j < NT; j++) {
                int cbase = wn * (BN / 2) + j * 8 + g;
                bf[j][0] = bs[(kw + t4    ) * BP16 + cbase];
                bf[j][1] = bs[(kw + 4 + t4) * BP16 + cbase];
            }
            #pragma unroll
            for (int i = 0; i < 2; i++)
                #pragma unroll
                for (int j = 0; j < NT; j++)
                    mma_fp16(acc[i][j], af[i], bf[j]);
        }
    };

    const int nk = K / 32;
    load_stage(0, 0);
    if (nk > 1) load_stage(1, 1);

    for (int kt = 0; kt < nk; kt++) {
        if (kt + 1 < nk) { asm volatile("cp.async.wait_group 1;\n"); }
        else             { asm volatile("cp.async.wait_group 0;\n"); }
        __syncthreads();
        if (kt + 2 < nk) load_stage((kt + 2) % 3, kt + 2);
        compute(kt % 3);
    }

    // epilogue (same acc layout as m16n8k8)
    #pragma unroll
    for (int i = 0; i < 2; i++) {
        int r0 = m0 + wm * 32 + i * 16 + g;
        #pragma unroll
        for (int j = 0; j < NT; j++) {
            int cc = n0 + wn * (BN / 2) + j * 8 + 2 * t4;
            size_t o0 = (size_t)r0 * N + cc;
            size_t o1 = (size_t)(r0 + 8) * N + cc;
            float v0 = acc[i][j][0], v1 = acc[i][j][1];
            float v2 = acc[i][j][2], v3 = acc[i][j][3];
            if (Cadd) { v0 += Cadd[o0]; v1 += Cadd[o0 + 1]; v2 += Cadd[o1]; v3 += Cadd[o1 + 1]; }
            C[o0] = v0; C[o0 + 1] = v1; C[o1] = v2; C[o1 + 1] = v3;
        }
    }
}

#define GEMMF_SMEM_128 (3 * (128*AP16 + 16*136) * 4)
#define GEMMF_SMEM_64  (3 * (128*AP16 + 16*72)  * 4)

// ---------------- RoPE (interleaved permute + rotate-half) ----------------
__global__ void rope_kernel(float* __restrict__ q, const float* __restrict__ ckv,
                            float* __restrict__ kpe,
                            const float* __restrict__ cosb, const float* __restrict__ sinb,
                            const int* __restrict__ pos_ids) {
    int s = blockIdx.x;
    int pos = pos_ids[s];
    const float* c  = cosb + (size_t)pos * ROPE_;
    const float* sn = sinb + (size_t)pos * ROPE_;
    int t = threadIdx.x;
    float ox[4], oy[4];
    #pragma unroll
    for (int it = 0; it < 4; it++) {
        int item = t + it * 128;
        int h = item >> 5, i = item & 31;
        float* base = q + (size_t)s * QDIM_ + h * QHD_ + NOPE_;
        float x0 = base[2 * i], x1 = base[2 * i + 1];
        ox[it] = x0 * c[i]      - x1 * sn[i];
        oy[it] = x1 * c[i + 32] + x0 * sn[i + 32];
    }
    __syncthreads();
    #pragma unroll
    for (int it = 0; it < 4; it++) {
        int item = t + it * 128;
        int h = item >> 5, i = item & 31;
        float* base = q + (size_t)s * QDIM_ + h * QHD_ + NOPE_;
        base[i]      = ox[it];
        base[i + 32] = oy[it];
    }
    if (t < 32) {
        const float* kb = ckv + (size_t)s * CKVD_ + KVLR_;
        float x0 = kb[2 * t], x1 = kb[2 * t + 1];
        kpe[(size_t)s * ROPE_ + t]      = x0 * c[t]      - x1 * sn[t];
        kpe[(size_t)s * ROPE_ + 32 + t] = x1 * c[t + 32] + x0 * sn[t + 32];
    }
}

// ---------------- tensor-core causal flash attention (tf32 mma, fp16 output) ------
#define QP_ 196
#define KP_ 196
#define VP_ 136
#define PP_ 68
#define ATT_SMEM_FLOATS (64*QP_ + 64*KP_ + 64*VP_ + 64*PP_)

__global__ __launch_bounds__(128, 1) void attn_mma_kernel(
        const float* __restrict__ q, const float* __restrict__ kv,
        const float* __restrict__ kpe, __half* __restrict__ out) {
    extern __shared__ float smem[];
    float* qs = smem;                 // [64][QP_]
    float* ks = qs + 64 * QP_;        // [64][KP_]
    float* vs = ks + 64 * KP_;        // [64][VP_]
    float* ps = vs + 64 * VP_;        // [64][PP_]

    const int h = blockIdx.y;
    const int qblk = (int)gridDim.x - 1 - (int)blockIdx.x;
    const int t = threadIdx.x;
    const int warp = t >> 5, lane = t & 31;
    const int g = lane >> 2, t4 = lane & 3;
    const int qbase = qblk * 64;
    const int wrow = warp * 16;

    for (int idx = t * 4; idx < 64 * 192; idx += 128 * 4) {
        int row = idx / 192, col = idx - row * 192;
        float4 v = *(const float4*)&q[(size_t)(qbase + row) * QDIM_ + h * QHD_ + col];
        *(float4*)&qs[row * QP_ + col] = v;
    }

    float oa[16][4];
    #pragma unroll
    for (int j = 0; j < 16; j++)
        #pragma unroll
        for (int c = 0; c < 4; c++) oa[j][c] = 0.f;
    float m0 = -1e30f, m1 = -1e30f, l0 = 0.f, l1 = 0.f;

    for (int kt = 0; kt <= qblk; kt++) {
        const int kbase = kt * 64;
        __syncthreads();
        for (int idx = t * 4; idx < 64 * 192; idx += 128 * 4) {
            int row = idx / 192, col = idx - row * 192;
            int key = kbase + row;
            float4 v = (col < 128)
                ? *(const float4*)&kv[(size_t)key * KVDIM_ + h * 256 + col]
                : *(const float4*)&kpe[(size_t)key * ROPE_ + (col - 128)];
            *(float4*)&ks[row * KP_ + col] = v;
        }
        for (int idx = t * 4; idx < 64 * 128; idx += 128 * 4) {
            int row = idx >> 7, col = idx & 127;
            float4 v = *(const float4*)&kv[(size_t)(kbase + row) * KVDIM_ + h * 256 + 128 + col];
            *(float4*)&vs[row * VP_ + col] = v;
        }
        __syncthreads();

        float sa[8][4];
        #pragma unroll
        for (int j = 0; j < 8; j++)
            #pragma unroll
            for (int c = 0; c < 4; c++) sa[j][c] = 0.f;
        #pragma unroll
        for (int kc = 0; kc < 24; kc++) {
            const int k0 = kc * 8;
            uint32_t af[4], bf[8][2];
            af[0] = __float_as_uint(qs[(wrow + g    ) * QP_ + k0 + t4]);
            af[1] = __float_as_uint(qs[(wrow + 8 + g) * QP_ + k0 + t4]);
            af[2] = __float_as_uint(qs[(wrow + g    ) * QP_ + k0 + 4 + t4]);
            af[3] = __float_as_uint(qs[(wrow + 8 + g) * QP_ + k0 + 4 + t4]);
            #pragma unroll
            for (int j = 0; j < 8; j++) {
                bf[j][0] = __float_as_uint(ks[(j * 8 + g) * KP_ + k0 + t4]);
                bf[j][1] = __float_as_uint(ks[(j * 8 + g) * KP_ + k0 + 4 + t4]);
            }
            #pragma unroll
            for (int j = 0; j < 8; j++) mma_tf32(sa[j], af, bf[j]);
        }

        const int r0 = qbase + wrow + g;
        const int r1 = r0 + 8;
        const bool diag = (kt == qblk);
        #pragma unroll
        for (int j = 0; j < 8; j++) {
            int c0 = kbase + j * 8 + 2 * t4, c1 = c0 + 1;
            sa[j][0] *= SCALE_; sa[j][1] *= SCALE_;
            sa[j][2] *= SCALE_; sa[j][3] *= SCALE_;
            if (diag) {
                if (c0 > r0) sa[j][0] = -1e30f;
                if (c1 > r0) sa[j][1] = -1e30f;
                if (c0 > r1) sa[j][2] = -1e30f;
                if (c1 > r1) sa[j][3] = -1e30f;
            }
        }

        float tm0 = -1e30f, tm1 = -1e30f;
        #pragma unroll
        for (int j = 0; j < 8; j++) {
            tm0 = fmaxf(tm0, fmaxf(sa[j][0], sa[j][1]));
            tm1 = fmaxf(tm1, fmaxf(sa[j][2], sa[j][3]));
        }
        tm0 = fmaxf(tm0, __shfl_xor_sync(0xffffffffu, tm0, 1));
        tm0 = fmaxf(tm0, __shfl_xor_sync(0xffffffffu, tm0, 2));
        tm1 = fmaxf(tm1, __shfl_xor_sync(0xffffffffu, tm1, 1));
        tm1 = fmaxf(tm1, __shfl_xor_sync(0xffffffffu, tm1, 2));
        float m0n = fmaxf(m0, tm0), m1n = fmaxf(m1, tm1);
        float a0 = __expf(m0 - m0n), a1 = __expf(m1 - m1n);
        float ps0 = 0.f, ps1 = 0.f;
        #pragma unroll
        for (int j = 0; j < 8; j++) {
            sa[j][0] = __expf(sa[j][0] - m0n); sa[j][1] = __expf(sa[j][1] - m0n);
            sa[j][2] = __expf(sa[j][2] - m1n); sa[j][3] = __expf(sa[j][3] - m1n);
            ps0 += sa[j][0] + sa[j][1];
            ps1 += sa[j][2] + sa[j][3];
        }
        ps0 += __shfl_xor_sync(0xffffffffu, ps0, 1);
        ps0 += __shfl_xor_sync(0xffffffffu, ps0, 2);
        ps1 += __shfl_xor_sync(0xffffffffu, ps1, 1);
        ps1 += __shfl_xor_sync(0xffffffffu, ps1, 2);
        l0 = l0 * a0 + ps0; l1 = l1 * a1 + ps1;
        m0 = m0n; m1 = m1n;
        #pragma unroll
        for (int j = 0; j < 16; j++) {
            oa[j][0] *= a0; oa[j][1] *= a0;
            oa[j][2] *= a1; oa[j][3] *= a1;
        }
        #pragma unroll
        for (int j = 0; j < 8; j++) {
            int cc = j * 8 + 2 * t4;
            ps[(wrow + g    ) * PP_ + cc]     = sa[j][0];
            ps[(wrow + g    ) * PP_ + cc + 1] = sa[j][1];
            ps[(wrow + 8 + g) * PP_ + cc]     = sa[j][2];
            ps[(wrow + 8 + g) * PP_ + cc + 1] = sa[j][3];
        }
        __syncwarp();

        #pragma unroll
        for (int kc = 0; kc < 8; kc++) {
            const int k0 = kc * 8;
            uint32_t af[4], bf[16][2];
            af[0] = __float_as_uint(ps[(wrow + g    ) * PP_ + k0 + t4]);
            af[1] = __float_as_uint(ps[(wrow + 8 + g) * PP_ + k0 + t4]);
            af[2] = __float_as_uint(ps[(wrow + g    ) * PP_ + k0 + 4 + t4]);
            af[3] = __float_as_uint(ps[(wrow + 8 + g) * PP_ + k0 + 4 + t4]);
            #pragma unroll
            for (int j = 0; j < 16; j++) {
                bf[j][0] = __float_as_uint(vs[(k0 + t4    ) * VP_ + j * 8 + g]);
                bf[j][1] = __float_as_uint(vs[(k0 + 4 + t4) * VP_ + j * 8 + g]);
            }
            #pragma unroll
            for (int j = 0; j < 16; j++) mma_tf32(oa[j], af, bf[j]);
        }
    }

    float i0 = 1.f / l0, i1 = 1.f / l1;
    const int r0 = qbase + wrow + g;
    __half* o0 = out + (size_t)r0 * H_ + h * VHD_;
    __half* o1 = out + (size_t)(r0 + 8) * H_ + h * VHD_;
    #pragma unroll
    for (int j = 0; j < 16; j++) {
        int cc = j * 8 + 2 * t4;
        o0[cc]     = __float2half(oa[j][0] * i0);
        o0[cc + 1] = __float2half(oa[j][1] * i0);
        o1[cc]     = __float2half(oa[j][2] * i1);
        o1[cc + 1] = __float2half(oa[j][3] * i1);
    }
}

// ---------------- silu(gate) * up -> fp16 ----------------
__global__ void silu_mul_kernel(const float* __restrict__ g, const float* __restrict__ u,
                                __half* __restrict__ o, int n) {
    int i = blockIdx.x * blockDim.x + threadIdx.x;
    if (i < n) {
        float x = g[i];
        float s = x / (1.f + __expf(-x));
        o[i] = __float2half(s * u[i]);
    }
}

// ---------------- launcher ----------------
extern "C" void kernel_launch(void* const* d_in, const int* in_sizes, int n_in,
                              void* d_out, int out_size) {
    const float* hidden  = (const float*)d_in[0];
    const float* sinb    = (const float*)d_in[1];
    const float* cosb    = (const float*)d_in[2];
    const float* wq_a    = (const float*)d_in[3];
    const float* q_a_ln  = (const float*)d_in[4];
    const float* wq_b    = (const float*)d_in[5];
    const float* wkv_a   = (const float*)d_in[6];
    const float* kv_a_ln = (const float*)d_in[7];
    const float* wkv_b   = (const float*)d_in[8];
    const float* wo      = (const float*)d_in[9];
    const float* in_ln   = (const float*)d_in[10];
    const float* post_ln = (const float*)d_in[11];
    const float* w_gate  = (const float*)d_in[12];
    const float* w_up    = (const float*)d_in[13];
    const float* w_down  = (const float*)d_in[14];
    const int*   pos     = (const int*)d_in[15];
    float* outp = (float*)d_out;

    float *qlat, *qb, *ckv, *kvb, *kpe, *hid2, *gate, *up;
    __half *xnorm16, *qlat16, *kvn16, *attn16, *ynorm16, *gate16;
    uint32_t *wqa16, *wqb16, *wkva16, *wkvb16, *wo16, *wg16, *wu16, *wd16;
    cudaGetSymbolAddress((void**)&qlat,  g_qlat);
    cudaGetSymbolAddress((void**)&qb,    g_q);
    cudaGetSymbolAddress((void**)&ckv,   g_ckv);
    cudaGetSymbolAddress((void**)&kvb,   g_kv);
    cudaGetSymbolAddress((void**)&kpe,   g_kpe);
    cudaGetSymbolAddress((void**)&hid2,  g_hid2);
    cudaGetSymbolAddress((void**)&gate,  g_gate);
    cudaGetSymbolAddress((void**)&up,    g_up);
    cudaGetSymbolAddress((void**)&xnorm16, g_xnorm16);
    cudaGetSymbolAddress((void**)&qlat16,  g_qlat16);
    cudaGetSymbolAddress((void**)&kvn16,   g_kvn16);
    cudaGetSymbolAddress((void**)&attn16,  g_attn16);
    cudaGetSymbolAddress((void**)&ynorm16, g_ynorm16);
    cudaGetSymbolAddress((void**)&gate16,  g_gate16);
    cudaGetSymbolAddress((void**)&wqa16,  g_wqa16);
    cudaGetSymbolAddress((void**)&wqb16,  g_wqb16);
    cudaGetSymbolAddress((void**)&wkva16, g_wkva16);
    cudaGetSymbolAddress((void**)&wkvb16, g_wkvb16);
    cudaGetSymbolAddress((void**)&wo16,   g_wo16);
    cudaGetSymbolAddress((void**)&wg16,   g_wg16);
    cudaGetSymbolAddress((void**)&wu16,   g_wu16);
    cudaGetSymbolAddress((void**)&wd16,   g_wd16);

    const size_t attn_smem = ATT_SMEM_FLOATS * sizeof(float);
    cudaFuncSetAttribute(attn_mma_kernel, cudaFuncAttributeMaxDynamicSharedMemorySize, (int)attn_smem);
    cudaFuncSetAttribute(gemm_fp16<128>, cudaFuncAttributeMaxDynamicSharedMemorySize, GEMMF_SMEM_128);
    cudaFuncSetAttribute(gemm_fp16<64>,  cudaFuncAttributeMaxDynamicSharedMemorySize, GEMMF_SMEM_64);

    // 0) convert weights to fp16 pair-interleaved layout
    auto cvt = [&](const float* w, uint32_t* o, int K, int N) {
        int n = (K / 2) * N;
        cvt_pair_kernel<<<(n + 255) / 256, 256>>>(w, o, K / 2, N);
    };
    cvt(wq_a,   wqa16,  H_,    QLR_);
    cvt(wq_b,   wqb16,  QLR_,  QDIM_);
    cvt(wkv_a,  wkva16, H_,    CKVD_);
    cvt(wkv_b,  wkvb16, KVLR_, KVDIM_);
    cvt(wo,     wo16,   H_,    H_);
    cvt(w_gate, wg16,   H_,    FF_);
    cvt(w_up,   wu16,   H_,    FF_);
    cvt(w_down, wd16,   FF_,   H_);

    dim3 blk256(256);
    auto gemm128 = [&](const __half* A, const uint32_t* Bw, const float* Cadd, float* C,
                       int M, int N, int K) {
        gemm_fp16<128><<<dim3(N / 128, M / 128), blk256, GEMMF_SMEM_128>>>(A, Bw, Cadd, C, M, N, K);
    };
    auto gemm64 = [&](const __half* A, const uint32_t* Bw, const float* Cadd, float* C,
                      int M, int N, int K) {
        gemm_fp16<64><<<dim3(N / 64, M / 128), blk256, GEMMF_SMEM_64>>>(A, Bw, Cadd, C, M, N, K);
    };

    // 1) xnorm16 = rms(hidden, in_ln)
    rms_kernel<<<S_, 256>>>(hidden, in_ln, xnorm16, H_, H_, H_);
    // 2) q_lat = xnorm16 @ wq_a  (fp32 out)
    gemm128(xnorm16, wqa16, nullptr, qlat, S_, QLR_, H_);
    // 3) qlat16 = rms(q_lat, q_a_ln)
    rms_kernel<<<S_, 256>>>(qlat, q_a_ln, qlat16, QLR_, QLR_, QLR_);
    // 4) q = qlat16 @ wq_b
    gemm128(qlat16, wqb16, nullptr, qb, S_, QDIM_, QLR_);
    // 5) ckv = xnorm16 @ wkv_a   (N=576 -> BN=64)
    gemm64(xnorm16, wkva16, nullptr, ckv, S_, CKVD_, H_);
    // 6) kvn16 = rms(ckv[:, :512], kv_a_ln)
    rms_kernel<<<S_, 256>>>(ckv, kv_a_ln, kvn16, KVLR_, CKVD_, KVLR_);
    // 7) kv = kvn16 @ wkv_b
    gemm128(kvn16, wkvb16, nullptr, kvb, S_, KVDIM_, KVLR_);
    // 8) RoPE (fp32, in place on q; kpe out)
    rope_kernel<<<S_, 128>>>(qb, ckv, kpe, cosb, sinb, pos);
    // 9) attention (tf32 mma; fp16 output)
    attn_mma_kernel<<<dim3(S_/64, NH_), 128, attn_smem>>>(qb, kvb, kpe, attn16);
    // 10) hid2 = hidden + attn16 @ wo
    gemm128(attn16, wo16, hidden, hid2, S_, H_, H_);
    // 11) ynorm16 = rms(hid2, post_ln)
    rms_kernel<<<S_, 256>>>(hid2, post_ln, ynorm16, H_, H_, H_);
    // 12) gate = ynorm16 @ w_gate
    gemm128(ynorm16, wg16, nullptr, gate, S_, FF_, H_);
    // 13) up = ynorm16 @ w_up
    gemm128(ynorm16, wu16, nullptr, up, S_, FF_, H_);
    // 14) gate16 = silu(gate) * up
    {
        int n = S_ * FF_;
        silu_mul_kernel<<<(n + 255) / 256, 256>>>(gate, up, gate16, n);
    }
    // 15) out = hid2 + gate16 @ w_down
    gemm128(gate16, wd16, hid2, outp, S_, H_, FF_);
}

// round 12
// speedup vs baseline: 1.5686x; 1.0755x over previous
#include <cuda_runtime.h>
#include <cuda_fp16.h>
#include <cuda_bf16.h>
#include <cstdint>
#include <math.h>

// ---------------- problem constants ----------------
#define S_   2048
#define H_   2048
#define NH_  16
#define NOPE_ 128
#define ROPE_ 64
#define QHD_ 192     // NOPE+ROPE
#define VHD_ 128
#define QLR_ 1536
#define KVLR_ 512
#define FF_  8192
#define CKVD_ (KVLR_ + ROPE_)   // 576
#define QDIM_ (NH_*QHD_)        // 3072
#define KVDIM_ (NH_*(NOPE_+VHD_)) // 4096
#define SCALE_ 0.07216878364870323f  // 192^-0.5

// ---------------- scratch (static device globals; no runtime alloc) ----------------
__device__ float  g_qlat  [S_*QLR_];
__device__ float  g_q     [S_*QDIM_];
__device__ float  g_ckv   [S_*CKVD_];
__device__ float  g_kv    [S_*KVDIM_];
__device__ float  g_kpe   [S_*ROPE_];
__device__ float  g_hid2  [S_*H_];
__device__ float  g_gate  [S_*FF_];
__device__ float  g_up    [S_*FF_];

__device__ __half g_xnorm16 [S_*H_];
__device__ __half g_qlat16  [S_*QLR_];
__device__ __half g_kvn16   [S_*KVLR_];
__device__ __half g_attn16  [S_*H_];
__device__ __half g_ynorm16 [S_*H_];
__device__ __half g_gate16  [S_*FF_];

// fp16 weights, k-pair-interleaved: word (p,n) = (w[2p][n], w[2p+1][n])
__device__ uint32_t g_wqa16  [(H_/2)*QLR_];
__device__ uint32_t g_wqb16  [(QLR_/2)*QDIM_];
__device__ uint32_t g_wkva16 [(H_/2)*CKVD_];
__device__ uint32_t g_wkvb16 [(KVLR_/2)*KVDIM_];
__device__ uint32_t g_wo16   [(H_/2)*H_];
__device__ uint32_t g_wg16   [(H_/2)*FF_];
__device__ uint32_t g_wu16   [(H_/2)*FF_];
__device__ uint32_t g_wd16   [(FF_/2)*H_];

// ---------------- helpers ----------------
__device__ __forceinline__ float warp_sum(float v) {
    #pragma unroll
    for (int o = 16; o; o >>= 1) v += __shfl_xor_sync(0xffffffffu, v, o);
    return v;
}

__device__ __forceinline__ void mma_fp16(float* d, const uint32_t* a, const uint32_t* b) {
    asm volatile(
        "mma.sync.aligned.m16n8k16.row.col.f32.f16.f16.f32 "
        "{%0,%1,%2,%3}, {%4,%5,%6,%7}, {%8,%9}, {%0,%1,%2,%3};"
        : "+f"(d[0]), "+f"(d[1]), "+f"(d[2]), "+f"(d[3])
        : "r"(a[0]), "r"(a[1]), "r"(a[2]), "r"(a[3]), "r"(b[0]), "r"(b[1]));
}

__device__ __forceinline__ uint32_t packh2(float lo, float hi) {
    __half2 h = __floats2half2_rn(lo, hi);
    return *(uint32_t*)&h;
}

// ---------------- weight convert: fp32 [K][N] -> u32 pair words [K/2][N] ----------------
__global__ void cvt_pair_kernel(const float* __restrict__ w, uint32_t* __restrict__ o,
                                int K2, int N) {
    int idx = blockIdx.x * blockDim.x + threadIdx.x;
    if (idx < K2 * N) {
        int p = idx / N, n = idx - p * N;
        o[idx] = packh2(w[(size_t)(2 * p) * N + n], w[(size_t)(2 * p + 1) * N + n]);
    }
}

// ---------------- rmsnorm: one block per row, fp16 output ----------------
__global__ void rms_kernel(const float* __restrict__ in, const float* __restrict__ w,
                           __half* __restrict__ out, int dim, int istride, int ostride) {
    int row = blockIdx.x;
    const float* x = in + (size_t)row * istride;
    __half* y = out + (size_t)row * ostride;
    float s = 0.f;
    for (int i = threadIdx.x; i < dim; i += blockDim.x) { float v = x[i]; s += v * v; }
    __shared__ float red[8];
    int lane = threadIdx.x & 31, wid = threadIdx.x >> 5;
    s = warp_sum(s);
    if (lane == 0) red[wid] = s;
    __syncthreads();
    if (wid == 0) {
        float r = (lane < (int)(blockDim.x >> 5)) ? red[lane] : 0.f;
        r = warp_sum(r);
        if (lane == 0) red[0] = r;
    }
    __syncthreads();
    float inv = rsqrtf(red[0] / (float)dim + 1e-6f);
    for (int i = threadIdx.x; i < dim; i += blockDim.x)
        y[i] = __float2half(x[i] * inv * w[i]);
}

// ---------------- fp16 tensor-core GEMM: C = A@B (+ Cadd), fp32 accumulate --------
#define AP16 20

template<int BN>
__global__ __launch_bounds__(256, 2) void gemm_fp16(
        const __half* __restrict__ A, const uint32_t* __restrict__ Bw,
        const float* __restrict__ Cadd, float* __restrict__ C,
        int M, int N, int K) {
    constexpr int BP16 = BN + 8;
    constexpr int NT = BN / 16;
    constexpr int STAGE = 128 * AP16 + 16 * BP16;
    extern __shared__ uint32_t smw[];
    const int t = threadIdx.x;
    const int warp = t >> 5, lane = t & 31;
    const int wm = warp >> 1, wn = warp & 1;
    const int g = lane >> 2, t4 = lane & 3;
    const int m0 = blockIdx.y * 128, n0 = blockIdx.x * BN;

    float acc[2][NT][4] = {};

    auto load_stage = [&](int st, int kt) {
        uint32_t* as = smw + st * STAGE;
        uint32_t* bs = as + 128 * AP16;
        #pragma unroll
        for (int i = 0; i < 2; i++) {
            int id = t + i * 256;
            int row = id >> 2, c = id & 3;
            uint32_t dst = (uint32_t)__cvta_generic_to_shared(as + row * AP16 + c * 4);
            const __half* src = A + (size_t)(m0 + row) * K + kt * 32 + c * 8;
            asm volatile("cp.async.cg.shared.global [%0], [%1], 16;\n" :: "r"(dst), "l"(src));
        }
        #pragma unroll
        for (int i = 0; i < BN / 64; i++) {
            int id = t + i * 256;
            int prow, c;
            if (BN == 128) { prow = id >> 5; c = id & 31; }
            else           { prow = id >> 4; c = id & 15; }
            uint32_t dst = (uint32_t)__cvta_generic_to_shared(bs + prow * BP16 + c * 4);
            const uint32_t* src = Bw + (size_t)(kt * 16 + prow) * N + n0 + c * 4;
            asm volatile("cp.async.cg.shared.global [%0], [%1], 16;\n" :: "r"(dst), "l"(src));
        }
        asm volatile("cp.async.commit_group;\n");
    };

    auto compute = [&](int st) {
        const uint32_t* as = smw + st * STAGE;
        const uint32_t* bs = as + 128 * AP16;
        #pragma unroll
        for (int kc = 0; kc < 2; kc++) {
            const int kw = kc * 8;
            uint32_t af[2][4], bf[NT][2];
            #pragma unroll
            for (int i = 0; i < 2; i++) {
                int rbase = wm * 32 + i * 16;
                af[i][0] = as[(rbase + g    ) * AP16 + kw + t4];
                af[i][1] = as[(rbase + 8 + g) * AP16 + kw + t4];
                af[i][2] = as[(rbase + g    ) * AP16 + kw + 4 + t4];
                af[i][3] = as[(rbase + 8 + g) * AP16 + kw + 4 + t4];
            }
            #pragma unroll
            for (int j = 0; j < NT; j++) {
                int cbase = wn * (BN / 2) + j * 8 + g;
                bf[j][0] = bs[(kw + t4    ) * BP16 + cbase];
                bf[j][1] = bs[(kw + 4 + t4) * BP16 + cbase];
            }
            #pragma unroll
            for (int i = 0; i < 2; i++)
                #pragma unroll
                for (int j = 0; j < NT; j++)
                    mma_fp16(acc[i][j], af[i], bf[j]);
        }
    };

    const int nk = K / 32;
    load_stage(0, 0);
    if (nk > 1) load_stage(1, 1);

    for (int kt = 0; kt < nk; kt++) {
        if (kt + 1 < nk) { asm volatile("cp.async.wait_group 1;\n"); }
        else             { asm volatile("cp.async.wait_group 0;\n"); }
        __syncthreads();
        if (kt + 2 < nk) load_stage((kt + 2) % 3, kt + 2);
        compute(kt % 3);
    }

    #pragma unroll
    for (int i = 0; i < 2; i++) {
        int r0 = m0 + wm * 32 + i * 16 + g;
        #pragma unroll
        for (int j = 0; j < NT; j++) {
            int cc = n0 + wn * (BN / 2) + j * 8 + 2 * t4;
            size_t o0 = (size_t)r0 * N + cc;
            size_t o1 = (size_t)(r0 + 8) * N + cc;
            float v0 = acc[i][j][0], v1 = acc[i][j][1];
            float v2 = acc[i][j][2], v3 = acc[i][j][3];
            if (Cadd) { v0 += Cadd[o0]; v1 += Cadd[o0 + 1]; v2 += Cadd[o1]; v3 += Cadd[o1 + 1]; }
            C[o0] = v0; C[o0 + 1] = v1; C[o1] = v2; C[o1 + 1] = v3;
        }
    }
}

#define GEMMF_SMEM_128 (3 * (128*AP16 + 16*136) * 4)
#define GEMMF_SMEM_64  (3 * (128*AP16 + 16*72)  * 4)

// ---------------- RoPE (interleaved permute + rotate-half) ----------------
__global__ void rope_kernel(float* __restrict__ q, const float* __restrict__ ckv,
                            float* __restrict__ kpe,
                            const float* __restrict__ cosb, const float* __restrict__ sinb,
                            const int* __restrict__ pos_ids) {
    int s = blockIdx.x;
    int pos = pos_ids[s];
    const float* c  = cosb + (size_t)pos * ROPE_;
    const float* sn = sinb + (size_t)pos * ROPE_;
    int t = threadIdx.x;
    float ox[4], oy[4];
    #pragma unroll
    for (int it = 0; it < 4; it++) {
        int item = t + it * 128;
        int h = item >> 5, i = item & 31;
        float* base = q + (size_t)s * QDIM_ + h * QHD_ + NOPE_;
        float x0 = base[2 * i], x1 = base[2 * i + 1];
        ox[it] = x0 * c[i]      - x1 * sn[i];
        oy[it] = x1 * c[i + 32] + x0 * sn[i + 32];
    }
    __syncthreads();
    #pragma unroll
    for (int it = 0; it < 4; it++) {
        int item = t + it * 128;
        int h = item >> 5, i = item & 31;
        float* base = q + (size_t)s * QDIM_ + h * QHD_ + NOPE_;
        base[i]      = ox[it];
        base[i + 32] = oy[it];
    }
    if (t < 32) {
        const float* kb = ckv + (size_t)s * CKVD_ + KVLR_;
        float x0 = kb[2 * t], x1 = kb[2 * t + 1];
        kpe[(size_t)s * ROPE_ + t]      = x0 * c[t]      - x1 * sn[t];
        kpe[(size_t)s * ROPE_ + 32 + t] = x1 * c[t + 32] + x0 * sn[t + 32];
    }
}

// ---------------- fp16 tensor-core causal flash attention ----------------
// Q/K tiles: half2 words [64 rows][96 data words], pitch 100 (bank-perm for frags).
// V tile: TRANSPOSED pair-words [128 vdim][32 key-pairs], pitch 36.
// P tile: half2 words [64 q][32 key-pair words], pitch 36.
#define AQW 100
#define AKW 100
#define AVW 36
#define APW 36
#define ATT_SMEM_WORDS (64*AQW + 64*AKW + 128*AVW + 64*APW)   // 19712 w = 78848 B

__global__ __launch_bounds__(128, 2) void attn_mma_kernel(
        const float* __restrict__ q, const float* __restrict__ kv,
        const float* __restrict__ kpe, __half* __restrict__ out) {
    extern __shared__ uint32_t smw[];
    uint32_t* qw  = smw;                 // [64][AQW]
    uint32_t* kww = qw + 64 * AQW;       // [64][AKW]
    uint32_t* vt  = kww + 64 * AKW;      // [128][AVW]
    uint32_t* pw  = vt + 128 * AVW;      // [64][APW]

    const int h = blockIdx.y;
    const int qblk = (int)gridDim.x - 1 - (int)blockIdx.x;   // heavy blocks first
    const int t = threadIdx.x;
    const int warp = t >> 5, lane = t & 31;
    const int g = lane >> 2, t4 = lane & 3;
    const int qbase = qblk * 64;
    const int wrow = warp * 16;

    // load Q tile: fp32 -> half2 words
    for (int idx = t; idx < 64 * 48; idx += 128) {
        int row = idx / 48, c = idx - row * 48;
        float4 v = *(const float4*)&q[(size_t)(qbase + row) * QDIM_ + h * QHD_ + c * 4];
        uint2 pk = { packh2(v.x, v.y), packh2(v.z, v.w) };
        *(uint2*)&qw[row * AQW + c * 2] = pk;
    }

    float oa[16][4];
    #pragma unroll
    for (int j = 0; j < 16; j++)
        #pragma unroll
        for (int c = 0; c < 4; c++) oa[j][c] = 0.f;
    float m0 = -1e30f, m1 = -1e30f, l0 = 0.f, l1 = 0.f;

    for (int kt = 0; kt <= qblk; kt++) {
        const int kbase = kt * 64;
        __syncthreads();
        // K tile: nope (cols 0..127) from kv, rope (128..191) from kpe
        for (int idx = t; idx < 64 * 48; idx += 128) {
            int row = idx / 48, c = idx - row * 48;
            int key = kbase + row;
            float4 v = (c < 32)
                ? *(const float4*)&kv[(size_t)key * KVDIM_ + h * 256 + c * 4]
                : *(const float4*)&kpe[(size_t)key * ROPE_ + (c - 32) * 4];
            uint2 pk = { packh2(v.x, v.y), packh2(v.z, v.w) };
            *(uint2*)&kww[row * AKW + c * 2] = pk;
        }
        // V tile, transposed: word (vd, p) = (V[2p][vd], V[2p+1][vd])
        for (int idx = t; idx < 32 * 128; idx += 128) {
            int vd = idx & 127, p = idx >> 7;
            float lo = kv[(size_t)(kbase + 2 * p    ) * KVDIM_ + h * 256 + 128 + vd];
            float hi = kv[(size_t)(kbase + 2 * p + 1) * KVDIM_ + h * 256 + 128 + vd];
            vt[vd * AVW + p] = packh2(lo, hi);
        }
        __syncthreads();

        // ---- S = Q @ K^T (fp16 m16n8k16: 12 k-chunks, 8 n-tiles) ----
        float sa[8][4];
        #pragma unroll
        for (int j = 0; j < 8; j++)
            #pragma unroll
            for (int c = 0; c < 4; c++) sa[j][c] = 0.f;
        #pragma unroll
        for (int kc = 0; kc < 12; kc++) {
            const int kw0 = kc * 8;
            uint32_t af[4], bf[8][2];
            af[0] = qw[(wrow + g    ) * AQW + kw0 + t4];
            af[1] = qw[(wrow + 8 + g) * AQW + kw0 + t4];
            af[2] = qw[(wrow + g    ) * AQW + kw0 + 4 + t4];
            af[3] = qw[(wrow + 8 + g) * AQW + kw0 + 4 + t4];
            #pragma unroll
            for (int j = 0; j < 8; j++) {
                bf[j][0] = kww[(j * 8 + g) * AKW + kw0 + t4];
                bf[j][1] = kww[(j * 8 + g) * AKW + kw0 + 4 + t4];
            }
            #pragma unroll
            for (int j = 0; j < 8; j++) mma_fp16(sa[j], af, bf[j]);
        }

        // ---- mask + scale ----
        const int r0 = qbase + wrow + g;
        const int r1 = r0 + 8;
        const bool diag = (kt == qblk);
        #pragma unroll
        for (int j = 0; j < 8; j++) {
            int c0 = kbase + j * 8 + 2 * t4, c1 = c0 + 1;
            sa[j][0] *= SCALE_; sa[j][1] *= SCALE_;
            sa[j][2] *= SCALE_; sa[j][3] *= SCALE_;
            if (diag) {
                if (c0 > r0) sa[j][0] = -1e30f;
                if (c1 > r0) sa[j][1] = -1e30f;
                if (c0 > r1) sa[j][2] = -1e30f;
                if (c1 > r1) sa[j][3] = -1e30f;
            }
        }

        // ---- online softmax (quad reductions) ----
        float tm0 = -1e30f, tm1 = -1e30f;
        #pragma unroll
        for (int j = 0; j < 8; j++) {
            tm0 = fmaxf(tm0, fmaxf(sa[j][0], sa[j][1]));
            tm1 = fmaxf(tm1, fmaxf(sa[j][2], sa[j][3]));
        }
        tm0 = fmaxf(tm0, __shfl_xor_sync(0xffffffffu, tm0, 1));
        tm0 = fmaxf(tm0, __shfl_xor_sync(0xffffffffu, tm0, 2));
        tm1 = fmaxf(tm1, __shfl_xor_sync(0xffffffffu, tm1, 1));
        tm1 = fmaxf(tm1, __shfl_xor_sync(0xffffffffu, tm1, 2));
        float m0n = fmaxf(m0, tm0), m1n = fmaxf(m1, tm1);
        float a0 = __expf(m0 - m0n), a1 = __expf(m1 - m1n);
        float ps0 = 0.f, ps1 = 0.f;
        #pragma unroll
        for (int j = 0; j < 8; j++) {
            sa[j][0] = __expf(sa[j][0] - m0n); sa[j][1] = __expf(sa[j][1] - m0n);
            sa[j][2] = __expf(sa[j][2] - m1n); sa[j][3] = __expf(sa[j][3] - m1n);
            ps0 += sa[j][0] + sa[j][1];
            ps1 += sa[j][2] + sa[j][3];
        }
        ps0 += __shfl_xor_sync(0xffffffffu, ps0, 1);
        ps0 += __shfl_xor_sync(0xffffffffu, ps0, 2);
        ps1 += __shfl_xor_sync(0xffffffffu, ps1, 1);
        ps1 += __shfl_xor_sync(0xffffffffu, ps1, 2);
        l0 = l0 * a0 + ps0; l1 = l1 * a1 + ps1;
        m0 = m0n; m1 = m1n;
        #pragma unroll
        for (int j = 0; j < 16; j++) {
            oa[j][0] *= a0; oa[j][1] *= a0;
            oa[j][2] *= a1; oa[j][3] *= a1;
        }
        // P -> fp16 pair words (own warp's 16-row slice only)
        #pragma unroll
        for (int j = 0; j < 8; j++) {
            pw[(wrow + g    ) * APW + j * 4 + t4] = packh2(sa[j][0], sa[j][1]);
            pw[(wrow + 8 + g) * APW + j * 4 + t4] = packh2(sa[j][2], sa[j][3]);
        }
        __syncwarp();

        // ---- O += P @ V (fp16: 4 k-chunks over 64 keys, 16 n-tiles over 128 vdim) ----
        #pragma unroll
        for (int kc = 0; kc < 4; kc++) {
            const int kw0 = kc * 8;
            uint32_t af[4], bf[16][2];
            af[0] = pw[(wrow + g    ) * APW + kw0 + t4];
            af[1] = pw[(wrow + 8 + g) * APW + kw0 + t4];
            af[2] = pw[(wrow + g    ) * APW + kw0 + 4 + t4];
            af[3] = pw[(wrow + 8 + g) * APW + kw0 + 4 + t4];
            #pragma unroll
            for (int j = 0; j < 16; j++) {
                bf[j][0] = vt[(j * 8 + g) * AVW + kw0 + t4];
                bf[j][1] = vt[(j * 8 + g) * AVW + kw0 + 4 + t4];
            }
            #pragma unroll
            for (int j = 0; j < 16; j++) mma_fp16(oa[j], af, bf[j]);
        }
    }

    // ---- epilogue ----
    float i0 = 1.f / l0, i1 = 1.f / l1;
    const int r0 = qbase + wrow + g;
    __half* o0 = out + (size_t)r0 * H_ + h * VHD_;
    __half* o1 = out + (size_t)(r0 + 8) * H_ + h * VHD_;
    #pragma unroll
    for (int j = 0; j < 16; j++) {
        int cc = j * 8 + 2 * t4;
        o0[cc]     = __float2half(oa[j][0] * i0);
        o0[cc + 1] = __float2half(oa[j][1] * i0);
        o1[cc]     = __float2half(oa[j][2] * i1);
        o1[cc + 1] = __float2half(oa[j][3] * i1);
    }
}

// ---------------- silu(gate) * up -> fp16 ----------------
__global__ void silu_mul_kernel(const float* __restrict__ g, const float* __restrict__ u,
                                __half* __restrict__ o, int n) {
    int i = blockIdx.x * blockDim.x + threadIdx.x;
    if (i < n) {
        float x = g[i];
        float s = x / (1.f + __expf(-x));
        o[i] = __float2half(s * u[i]);
    }
}

// ---------------- launcher ----------------
extern "C" void kernel_launch(void* const* d_in, const int* in_sizes, int n_in,
                              void* d_out, int out_size) {
    const float* hidden  = (const float*)d_in[0];
    const float* sinb    = (const float*)d_in[1];
    const float* cosb    = (const float*)d_in[2];
    const float* wq_a    = (const float*)d_in[3];
    const float* q_a_ln  = (const float*)d_in[4];
    const float* wq_b    = (const float*)d_in[5];
    const float* wkv_a   = (const float*)d_in[6];
    const float* kv_a_ln = (const float*)d_in[7];
    const float* wkv_b   = (const float*)d_in[8];
    const float* wo      = (const float*)d_in[9];
    const float* in_ln   = (const float*)d_in[10];
    const float* post_ln = (const float*)d_in[11];
    const float* w_gate  = (const float*)d_in[12];
    const float* w_up    = (const float*)d_in[13];
    const float* w_down  = (const float*)d_in[14];
    const int*   pos     = (const int*)d_in[15];
    float* outp = (float*)d_out;

    float *qlat, *qb, *ckv, *kvb, *kpe, *hid2, *gate, *up;
    __half *xnorm16, *qlat16, *kvn16, *attn16, *ynorm16, *gate16;
    uint32_t *wqa16, *wqb16, *wkva16, *wkvb16, *wo16, *wg16, *wu16, *wd16;
    cudaGetSymbolAddress((void**)&qlat,  g_qlat);
    cudaGetSymbolAddress((void**)&qb,    g_q);
    cudaGetSymbolAddress((void**)&ckv,   g_ckv);
    cudaGetSymbolAddress((void**)&kvb,   g_kv);
    cudaGetSymbolAddress((void**)&kpe,   g_kpe);
    cudaGetSymbolAddress((void**)&hid2,  g_hid2);
    cudaGetSymbolAddress((void**)&gate,  g_gate);
    cudaGetSymbolAddress((void**)&up,    g_up);
    cudaGetSymbolAddress((void**)&xnorm16, g_xnorm16);
    cudaGetSymbolAddress((void**)&qlat16,  g_qlat16);
    cudaGetSymbolAddress((void**)&kvn16,   g_kvn16);
    cudaGetSymbolAddress((void**)&attn16,  g_attn16);
    cudaGetSymbolAddress((void**)&ynorm16, g_ynorm16);
    cudaGetSymbolAddress((void**)&gate16,  g_gate16);
    cudaGetSymbolAddress((void**)&wqa16,  g_wqa16);
    cudaGetSymbolAddress((void**)&wqb16,  g_wqb16);
    cudaGetSymbolAddress((void**)&wkva16, g_wkva16);
    cudaGetSymbolAddress((void**)&wkvb16, g_wkvb16);
    cudaGetSymbolAddress((void**)&wo16,   g_wo16);
    cudaGetSymbolAddress((void**)&wg16,   g_wg16);
    cudaGetSymbolAddress((void**)&wu16,   g_wu16);
    cudaGetSymbolAddress((void**)&wd16,   g_wd16);

    const size_t attn_smem = ATT_SMEM_WORDS * sizeof(uint32_t);
    cudaFuncSetAttribute(attn_mma_kernel, cudaFuncAttributeMaxDynamicSharedMemorySize, (int)attn_smem);
    cudaFuncSetAttribute(gemm_fp16<128>, cudaFuncAttributeMaxDynamicSharedMemorySize, GEMMF_SMEM_128);
    cudaFuncSetAttribute(gemm_fp16<64>,  cudaFuncAttributeMaxDynamicSharedMemorySize, GEMMF_SMEM_64);

    // 0) convert weights to fp16 pair-interleaved layout
    auto cvt = [&](const float* w, uint32_t* o, int K, int N) {
        int n = (K / 2) * N;
        cvt_pair_kernel<<<(n + 255) / 256, 256>>>(w, o, K / 2, N);
    };
    cvt(wq_a,   wqa16,  H_,    QLR_);
    cvt(wq_b,   wqb16,  QLR_,  QDIM_);
    cvt(wkv_a,  wkva16, H_,    CKVD_);
    cvt(wkv_b,  wkvb16, KVLR_, KVDIM_);
    cvt(wo,     wo16,   H_,    H_);
    cvt(w_gate, wg16,   H_,    FF_);
    cvt(w_up,   wu16,   H_,    FF_);
    cvt(w_down, wd16,   FF_,   H_);

    dim3 blk256(256);
    auto gemm128 = [&](const __half* A, const uint32_t* Bw, const float* Cadd, float* C,
                       int M, int N, int K) {
        gemm_fp16<128><<<dim3(N / 128, M / 128), blk256, GEMMF_SMEM_128>>>(A, Bw, Cadd, C, M, N, K);
    };
    auto gemm64 = [&](const __half* A, const uint32_t* Bw, const float* Cadd, float* C,
                      int M, int N, int K) {
        gemm_fp16<64><<<dim3(N / 64, M / 128), blk256, GEMMF_SMEM_64>>>(A, Bw, Cadd, C, M, N, K);
    };

    // 1) xnorm16 = rms(hidden, in_ln)
    rms_kernel<<<S_, 256>>>(hidden, in_ln, xnorm16, H_, H_, H_);
    // 2) q_lat = xnorm16 @ wq_a  (fp32 out)
    gemm128(xnorm16, wqa16, nullptr, qlat, S_, QLR_, H_);
    // 3) qlat16 = rms(q_lat, q_a_ln)
    rms_kernel<<<S_, 256>>>(qlat, q_a_ln, qlat16, QLR_, QLR_, QLR_);
    // 4) q = qlat16 @ wq_b
    gemm128(qlat16, wqb16, nullptr, qb, S_, QDIM_, QLR_);
    // 5) ckv = xnorm16 @ wkv_a   (N=576 -> BN=64)
    gemm64(xnorm16, wkva16, nullptr, ckv, S_, CKVD_, H_);
    // 6) kvn16 = rms(ckv[:, :512], kv_a_ln)
    rms_kernel<<<S_, 256>>>(ckv, kv_a_ln, kvn16, KVLR_, CKVD_, KVLR_);
    // 7) kv = kvn16 @ wkv_b
    gemm128(kvn16, wkvb16, nullptr, kvb, S_, KVDIM_, KVLR_);
    // 8) RoPE (fp32, in place on q; kpe out)
    rope_kernel<<<S_, 128>>>(qb, ckv, kpe, cosb, sinb, pos);
    // 9) attention (fp16 mma; fp16 output)
    attn_mma_kernel<<<dim3(S_/64, NH_), 128, attn_smem>>>(qb, kvb, kpe, attn16);
    // 10) hid2 = hidden + attn16 @ wo
    gemm128(attn16, wo16, hidden, hid2, S_, H_, H_);
    // 11) ynorm16 = rms(hid2, post_ln)
    rms_kernel<<<S_, 256>>>(hid2, post_ln, ynorm16, H_, H_, H_);
    // 12) gate = ynorm16 @ w_gate
    gemm128(ynorm16, wg16, nullptr, gate, S_, FF_, H_);
    // 13) up = ynorm16 @ w_up
    gemm128(ynorm16, wu16, nullptr, up, S_, FF_, H_);
    // 14) gate16 = silu(gate) * up
    {
        int n = S_ * FF_;
        silu_mul_kernel<<<(n + 255) / 256, 256>>>(gate, up, gate16, n);
    }
    // 15) out = hid2 + gate16 @ w_down
    gemm128(gate16, wd16, hid2, outp, S_, H_, FF_);
}

// round 13
// speedup vs baseline: 1.6246x; 1.0357x over previous
#include <cuda_runtime.h>
#include <cuda_fp16.h>
#include <cuda_bf16.h>
#include <cstdint>
#include <math.h>

// ---------------- problem constants ----------------
#define S_   2048
#define H_   2048
#define NH_  16
#define NOPE_ 128
#define ROPE_ 64
#define QHD_ 192     // NOPE+ROPE
#define VHD_ 128
#define QLR_ 1536
#define KVLR_ 512
#define FF_  8192
#define CKVD_ (KVLR_ + ROPE_)   // 576
#define QDIM_ (NH_*QHD_)        // 3072
#define KVDIM_ (NH_*(NOPE_+VHD_)) // 4096
#define SCALE_ 0.07216878364870323f  // 192^-0.5

#define NC1_ 2176      // combined wq_a(1536) + wkv_a(576) + pad(64)
#define NC2_ 16384     // combined gate(8192) + up(8192)

// ---------------- scratch (static device globals; no runtime alloc) ----------------
__device__ float  g_comb1 [S_*NC1_];    // [:,0:1536]=q_lat, [:,1536:2112]=ckv
__device__ float  g_comb2 [S_*NC2_];    // [:,0:8192]=gate, [:,8192:]=up
__device__ float  g_q     [S_*QDIM_];
__device__ float  g_kv    [S_*KVDIM_];
__device__ float  g_kpe   [S_*ROPE_];
__device__ float  g_hid2  [S_*H_];

__device__ __half g_xnorm16 [S_*H_];
__device__ __half g_qlat16  [S_*QLR_];
__device__ __half g_kvn16   [S_*KVLR_];
__device__ __half g_attn16  [S_*H_];
__device__ __half g_ynorm16 [S_*H_];
__device__ __half g_gate16  [S_*FF_];

// fp16 weights, k-pair-interleaved: word (p,n) = (w[2p][n], w[2p+1][n])
__device__ uint32_t g_wqakva16 [(H_/2)*NC1_];   // pad cols [2112:2176) stay zero
__device__ uint32_t g_wqb16    [(QLR_/2)*QDIM_];
__device__ uint32_t g_wkvb16   [(KVLR_/2)*KVDIM_];
__device__ uint32_t g_wo16     [(H_/2)*H_];
__device__ uint32_t g_wgu16    [(H_/2)*NC2_];
__device__ uint32_t g_wd16     [(FF_/2)*H_];

// ---------------- helpers ----------------
__device__ __forceinline__ float warp_sum(float v) {
    #pragma unroll
    for (int o = 16; o; o >>= 1) v += __shfl_xor_sync(0xffffffffu, v, o);
    return v;
}

__device__ __forceinline__ void mma_fp16(float* d, const uint32_t* a, const uint32_t* b) {
    asm volatile(
        "mma.sync.aligned.m16n8k16.row.col.f32.f16.f16.f32 "
        "{%0,%1,%2,%3}, {%4,%5,%6,%7}, {%8,%9}, {%0,%1,%2,%3};"
        : "+f"(d[0]), "+f"(d[1]), "+f"(d[2]), "+f"(d[3])
        : "r"(a[0]), "r"(a[1]), "r"(a[2]), "r"(a[3]), "r"(b[0]), "r"(b[1]));
}

__device__ __forceinline__ uint32_t packh2(float lo, float hi) {
    __half2 h = __floats2half2_rn(lo, hi);
    return *(uint32_t*)&h;
}

// ---------------- weight convert: fp32 [K][Nsrc] -> u32 pair words, strided dest ----
__global__ void cvt_pair_kernel(const float* __restrict__ w, uint32_t* __restrict__ o,
                                int K2, int Nsrc, int dstStride, int colOff) {
    int idx = blockIdx.x * blockDim.x + threadIdx.x;
    if (idx < K2 * Nsrc) {
        int p = idx / Nsrc, n = idx - p * Nsrc;
        o[(size_t)p * dstStride + colOff + n] =
            packh2(w[(size_t)(2 * p) * Nsrc + n], w[(size_t)(2 * p + 1) * Nsrc + n]);
    }
}

// ---------------- rmsnorm: one block per row, fp16 output ----------------
__global__ void rms_kernel(const float* __restrict__ in, const float* __restrict__ w,
                           __half* __restrict__ out, int dim, int istride, int ostride) {
    int row = blockIdx.x;
    const float* x = in + (size_t)row * istride;
    __half* y = out + (size_t)row * ostride;
    float s = 0.f;
    for (int i = threadIdx.x; i < dim; i += blockDim.x) { float v = x[i]; s += v * v; }
    __shared__ float red[8];
    int lane = threadIdx.x & 31, wid = threadIdx.x >> 5;
    s = warp_sum(s);
    if (lane == 0) red[wid] = s;
    __syncthreads();
    if (wid == 0) {
        float r = (lane < (int)(blockDim.x >> 5)) ? red[lane] : 0.f;
        r = warp_sum(r);
        if (lane == 0) red[0] = r;
    }
    __syncthreads();
    float inv = rsqrtf(red[0] / (float)dim + 1e-6f);
    for (int i = threadIdx.x; i < dim; i += blockDim.x)
        y[i] = __float2half(x[i] * inv * w[i]);
}

// ---------------- fp16 tensor-core GEMM: C = A@B (+ Cadd), fp32 accumulate --------
#define AP16 20
#define BP16 136
#define GSTAGE (128*AP16 + 16*BP16)

__global__ __launch_bounds__(256, 2) void gemm_fp16(
        const __half* __restrict__ A, const uint32_t* __restrict__ Bw,
        const float* __restrict__ Cadd, float* __restrict__ C,
        int M, int N, int K) {
    extern __shared__ uint32_t smw[];
    const int t = threadIdx.x;
    const int warp = t >> 5, lane = t & 31;
    const int wm = warp >> 1, wn = warp & 1;
    const int g = lane >> 2, t4 = lane & 3;
    const int m0 = blockIdx.y * 128, n0 = blockIdx.x * 128;

    float acc[2][8][4] = {};

    auto load_stage = [&](int st, int kt) {
        uint32_t* as = smw + st * GSTAGE;
        uint32_t* bs = as + 128 * AP16;
        #pragma unroll
        for (int i = 0; i < 2; i++) {
            int id = t + i * 256;
            int row = id >> 2, c = id & 3;
            uint32_t dst = (uint32_t)__cvta_generic_to_shared(as + row * AP16 + c * 4);
            const __half* src = A + (size_t)(m0 + row) * K + kt * 32 + c * 8;
            asm volatile("cp.async.cg.shared.global [%0], [%1], 16;\n" :: "r"(dst), "l"(src));
        }
        #pragma unroll
        for (int i = 0; i < 2; i++) {
            int id = t + i * 256;
            int prow = id >> 5, c = id & 31;
            uint32_t dst = (uint32_t)__cvta_generic_to_shared(bs + prow * BP16 + c * 4);
            const uint32_t* src = Bw + (size_t)(kt * 16 + prow) * N + n0 + c * 4;
            asm volatile("cp.async.cg.shared.global [%0], [%1], 16;\n" :: "r"(dst), "l"(src));
        }
        asm volatile("cp.async.commit_group;\n");
    };

    auto compute = [&](int st) {
        const uint32_t* as = smw + st * GSTAGE;
        const uint32_t* bs = as + 128 * AP16;
        #pragma unroll
        for (int kc = 0; kc < 2; kc++) {
            const int kw = kc * 8;
            uint32_t af[2][4], bf[8][2];
            #pragma unroll
            for (int i = 0; i < 2; i++) {
                int rbase = wm * 32 + i * 16;
                af[i][0] = as[(rbase + g    ) * AP16 + kw + t4];
                af[i][1] = as[(rbase + 8 + g) * AP16 + kw + t4];
                af[i][2] = as[(rbase + g    ) * AP16 + kw + 4 + t4];
                af[i][3] = as[(rbase + 8 + g) * AP16 + kw + 4 + t4];
            }
            #pragma unroll
            for (int j = 0; j < 8; j++) {
                int cbase = wn * 64 + j * 8 + g;
                bf[j][0] = bs[(kw + t4    ) * BP16 + cbase];
                bf[j][1] = bs[(kw + 4 + t4) * BP16 + cbase];
            }
            #pragma unroll
            for (int i = 0; i < 2; i++)
                #pragma unroll
                for (int j = 0; j < 8; j++)
                    mma_fp16(acc[i][j], af[i], bf[j]);
        }
    };

    const int nk = K / 32;
    load_stage(0, 0);
    if (nk > 1) load_stage(1, 1);

    for (int kt = 0; kt < nk; kt++) {
        if (kt + 1 < nk) { asm volatile("cp.async.wait_group 1;\n"); }
        else             { asm volatile("cp.async.wait_group 0;\n"); }
        __syncthreads();
        if (kt + 2 < nk) load_stage((kt + 2) % 3, kt + 2);
        compute(kt % 3);
    }

    #pragma unroll
    for (int i = 0; i < 2; i++) {
        int r0 = m0 + wm * 32 + i * 16 + g;
        #pragma unroll
        for (int j = 0; j < 8; j++) {
            int cc = n0 + wn * 64 + j * 8 + 2 * t4;
            size_t o0 = (size_t)r0 * N + cc;
            size_t o1 = (size_t)(r0 + 8) * N + cc;
            float v0 = acc[i][j][0], v1 = acc[i][j][1];
            float v2 = acc[i][j][2], v3 = acc[i][j][3];
            if (Cadd) { v0 += Cadd[o0]; v1 += Cadd[o0 + 1]; v2 += Cadd[o1]; v3 += Cadd[o1 + 1]; }
            C[o0] = v0; C[o0 + 1] = v1; C[o1] = v2; C[o1 + 1] = v3;
        }
    }
}

#define GEMMF_SMEM (3 * GSTAGE * 4)

// ---------------- RoPE (interleaved permute + rotate-half) ----------------
__global__ void rope_kernel(float* __restrict__ q, const float* __restrict__ ckv_base,
                            int ckv_stride, float* __restrict__ kpe,
                            const float* __restrict__ cosb, const float* __restrict__ sinb,
                            const int* __restrict__ pos_ids) {
    int s = blockIdx.x;
    int pos = pos_ids[s];
    const float* c  = cosb + (size_t)pos * ROPE_;
    const float* sn = sinb + (size_t)pos * ROPE_;
    int t = threadIdx.x;
    float ox[4], oy[4];
    #pragma unroll
    for (int it = 0; it < 4; it++) {
        int item = t + it * 128;
        int h = item >> 5, i = item & 31;
        float* base = q + (size_t)s * QDIM_ + h * QHD_ + NOPE_;
        float x0 = base[2 * i], x1 = base[2 * i + 1];
        ox[it] = x0 * c[i]      - x1 * sn[i];
        oy[it] = x1 * c[i + 32] + x0 * sn[i + 32];
    }
    __syncthreads();
    #pragma unroll
    for (int it = 0; it < 4; it++) {
        int item = t + it * 128;
        int h = item >> 5, i = item & 31;
        float* base = q + (size_t)s * QDIM_ + h * QHD_ + NOPE_;
        base[i]      = ox[it];
        base[i + 32] = oy[it];
    }
    if (t < 32) {
        const float* kb = ckv_base + (size_t)s * ckv_stride + KVLR_;
        float x0 = kb[2 * t], x1 = kb[2 * t + 1];
        kpe[(size_t)s * ROPE_ + t]      = x0 * c[t]      - x1 * sn[t];
        kpe[(size_t)s * ROPE_ + 32 + t] = x1 * c[t + 32] + x0 * sn[t + 32];
    }
}

// ---------------- fp16 tensor-core causal flash attention ----------------
#define AQW 100
#define AKW 100
#define AVW 36
#define APW 36
#define ATT_SMEM_WORDS (64*AQW + 64*AKW + 128*AVW + 64*APW)

__global__ __launch_bounds__(128, 2) void attn_mma_kernel(
        const float* __restrict__ q, const float* __restrict__ kv,
        const float* __restrict__ kpe, __half* __restrict__ out) {
    extern __shared__ uint32_t smw[];
    uint32_t* qw  = smw;
    uint32_t* kww = qw + 64 * AQW;
    uint32_t* vt  = kww + 64 * AKW;
    uint32_t* pw  = vt + 128 * AVW;

    const int h = blockIdx.y;
    const int qblk = (int)gridDim.x - 1 - (int)blockIdx.x;
    const int t = threadIdx.x;
    const int warp = t >> 5, lane = t & 31;
    const int g = lane >> 2, t4 = lane & 3;
    const int qbase = qblk * 64;
    const int wrow = warp * 16;

    for (int idx = t; idx < 64 * 48; idx += 128) {
        int row = idx / 48, c = idx - row * 48;
        float4 v = *(const float4*)&q[(size_t)(qbase + row) * QDIM_ + h * QHD_ + c * 4];
        uint2 pk = { packh2(v.x, v.y), packh2(v.z, v.w) };
        *(uint2*)&qw[row * AQW + c * 2] = pk;
    }

    float oa[16][4];
    #pragma unroll
    for (int j = 0; j < 16; j++)
        #pragma unroll
        for (int c = 0; c < 4; c++) oa[j][c] = 0.f;
    float m0 = -1e30f, m1 = -1e30f, l0 = 0.f, l1 = 0.f;

    for (int kt = 0; kt <= qblk; kt++) {
        const int kbase = kt * 64;
        __syncthreads();
        for (int idx = t; idx < 64 * 48; idx += 128) {
            int row = idx / 48, c = idx - row * 48;
            int key = kbase + row;
            float4 v = (c < 32)
                ? *(const float4*)&kv[(size_t)key * KVDIM_ + h * 256 + c * 4]
                : *(const float4*)&kpe[(size_t)key * ROPE_ + (c - 32) * 4];
            uint2 pk = { packh2(v.x, v.y), packh2(v.z, v.w) };
            *(uint2*)&kww[row * AKW + c * 2] = pk;
        }
        for (int idx = t; idx < 32 * 128; idx += 128) {
            int vd = idx & 127, p = idx >> 7;
            float lo = kv[(size_t)(kbase + 2 * p    ) * KVDIM_ + h * 256 + 128 + vd];
            float hi = kv[(size_t)(kbase + 2 * p + 1) * KVDIM_ + h * 256 + 128 + vd];
            vt[vd * AVW + p] = packh2(lo, hi);
        }
        __syncthreads();

        float sa[8][4];
        #pragma unroll
        for (int j = 0; j < 8; j++)
            #pragma unroll
            for (int c = 0; c < 4; c++) sa[j][c] = 0.f;
        #pragma unroll
        for (int kc = 0; kc < 12; kc++) {
            const int kw0 = kc * 8;
            uint32_t af[4], bf[8][2];
            af[0] = qw[(wrow + g    ) * AQW + kw0 + t4];
            af[1] = qw[(wrow + 8 + g) * AQW + kw0 + t4];
            af[2] = qw[(wrow + g    ) * AQW + kw0 + 4 + t4];
            af[3] = qw[(wrow + 8 + g) * AQW + kw0 + 4 + t4];
            #pragma unroll
            for (int j = 0; j < 8; j++) {
                bf[j][0] = kww[(j * 8 + g) * AKW + kw0 + t4];
                bf[j][1] = kww[(j * 8 + g) * AKW + kw0 + 4 + t4];
            }
            #pragma unroll
            for (int j = 0; j < 8; j++) mma_fp16(sa[j], af, bf[j]);
        }

        const int r0 = qbase + wrow + g;
        const int r1 = r0 + 8;
        const bool diag = (kt == qblk);
        #pragma unroll
        for (int j = 0; j < 8; j++) {
            int c0 = kbase + j * 8 + 2 * t4, c1 = c0 + 1;
            sa[j][0] *= SCALE_; sa[j][1] *= SCALE_;
            sa[j][2] *= SCALE_; sa[j][3] *= SCALE_;
            if (diag) {
                if (c0 > r0) sa[j][0] = -1e30f;
                if (c1 > r0) sa[j][1] = -1e30f;
                if (c0 > r1) sa[j][2] = -1e30f;
                if (c1 > r1) sa[j][3] = -1e30f;
            }
        }

        float tm0 = -1e30f, tm1 = -1e30f;
        #pragma unroll
        for (int j = 0; j < 8; j++) {
            tm0 = fmaxf(tm0, fmaxf(sa[j][0], sa[j][1]));
            tm1 = fmaxf(tm1, fmaxf(sa[j][2], sa[j][3]));
        }
        tm0 = fmaxf(tm0, __shfl_xor_sync(0xffffffffu, tm0, 1));
        tm0 = fmaxf(tm0, __shfl_xor_sync(0xffffffffu, tm0, 2));
        tm1 = fmaxf(tm1, __shfl_xor_sync(0xffffffffu, tm1, 1));
        tm1 = fmaxf(tm1, __shfl_xor_sync(0xffffffffu, tm1, 2));
        float m0n = fmaxf(m0, tm0), m1n = fmaxf(m1, tm1);
        float a0 = __expf(m0 - m0n), a1 = __expf(m1 - m1n);
        float ps0 = 0.f, ps1 = 0.f;
        #pragma unroll
        for (int j = 0; j < 8; j++) {
            sa[j][0] = __expf(sa[j][0] - m0n); sa[j][1] = __expf(sa[j][1] - m0n);
            sa[j][2] = __expf(sa[j][2] - m1n); sa[j][3] = __expf(sa[j][3] - m1n);
            ps0 += sa[j][0] + sa[j][1];
            ps1 += sa[j][2] + sa[j][3];
        }
        ps0 += __shfl_xor_sync(0xffffffffu, ps0, 1);
        ps0 += __shfl_xor_sync(0xffffffffu, ps0, 2);
        ps1 += __shfl_xor_sync(0xffffffffu, ps1, 1);
        ps1 += __shfl_xor_sync(0xffffffffu, ps1, 2);
        l0 = l0 * a0 + ps0; l1 = l1 * a1 + ps1;
        m0 = m0n; m1 = m1n;
        #pragma unroll
        for (int j = 0; j < 16; j++) {
            oa[j][0] *= a0; oa[j][1] *= a0;
            oa[j][2] *= a1; oa[j][3] *= a1;
        }
        #pragma unroll
        for (int j = 0; j < 8; j++) {
            pw[(wrow + g    ) * APW + j * 4 + t4] = packh2(sa[j][0], sa[j][1]);
            pw[(wrow + 8 + g) * APW + j * 4 + t4] = packh2(sa[j][2], sa[j][3]);
        }
        __syncwarp();

        #pragma unroll
        for (int kc = 0; kc < 4; kc++) {
            const int kw0 = kc * 8;
            uint32_t af[4], bf[16][2];
            af[0] = pw[(wrow + g    ) * APW + kw0 + t4];
            af[1] = pw[(wrow + 8 + g) * APW + kw0 + t4];
            af[2] = pw[(wrow + g    ) * APW + kw0 + 4 + t4];
            af[3] = pw[(wrow + 8 + g) * APW + kw0 + 4 + t4];
            #pragma unroll
            for (int j = 0; j < 16; j++) {
                bf[j][0] = vt[(j * 8 + g) * AVW + kw0 + t4];
                bf[j][1] = vt[(j * 8 + g) * AVW + kw0 + 4 + t4];
            }
            #pragma unroll
            for (int j = 0; j < 16; j++) mma_fp16(oa[j], af, bf[j]);
        }
    }

    float i0 = 1.f / l0, i1 = 1.f / l1;
    const int r0 = qbase + wrow + g;
    __half* o0 = out + (size_t)r0 * H_ + h * VHD_;
    __half* o1 = out + (size_t)(r0 + 8) * H_ + h * VHD_;
    #pragma unroll
    for (int j = 0; j < 16; j++) {
        int cc = j * 8 + 2 * t4;
        o0[cc]     = __float2half(oa[j][0] * i0);
        o0[cc + 1] = __float2half(oa[j][1] * i0);
        o1[cc]     = __float2half(oa[j][2] * i1);
        o1[cc + 1] = __float2half(oa[j][3] * i1);
    }
}

// ---------------- silu(comb2.gate) * comb2.up -> fp16 ----------------
__global__ void silu_mul_kernel(const float* __restrict__ comb2,
                                __half* __restrict__ o, int n) {
    int i = blockIdx.x * blockDim.x + threadIdx.x;
    if (i < n) {
        int s = i / FF_, c = i - s * FF_;
        float x = comb2[(size_t)s * NC2_ + c];
        float u = comb2[(size_t)s * NC2_ + FF_ + c];
        float sg = x / (1.f + __expf(-x));
        o[i] = __float2half(sg * u);
    }
}

// ---------------- launcher ----------------
extern "C" void kernel_launch(void* const* d_in, const int* in_sizes, int n_in,
                              void* d_out, int out_size) {
    const float* hidden  = (const float*)d_in[0];
    const float* sinb    = (const float*)d_in[1];
    const float* cosb    = (const float*)d_in[2];
    const float* wq_a    = (const float*)d_in[3];
    const float* q_a_ln  = (const float*)d_in[4];
    const float* wq_b    = (const float*)d_in[5];
    const float* wkv_a   = (const float*)d_in[6];
    const float* kv_a_ln = (const float*)d_in[7];
    const float* wkv_b   = (const float*)d_in[8];
    const float* wo      = (const float*)d_in[9];
    const float* in_ln   = (const float*)d_in[10];
    const float* post_ln = (const float*)d_in[11];
    const float* w_gate  = (const float*)d_in[12];
    const float* w_up    = (const float*)d_in[13];
    const float* w_down  = (const float*)d_in[14];
    const int*   pos     = (const int*)d_in[15];
    float* outp = (float*)d_out;

    float *comb1, *comb2, *qb, *kvb, *kpe, *hid2;
    __half *xnorm16, *qlat16, *kvn16, *attn16, *ynorm16, *gate16;
    uint32_t *wqakva16, *wqb16, *wkvb16, *wo16, *wgu16, *wd16;
    cudaGetSymbolAddress((void**)&comb1, g_comb1);
    cudaGetSymbolAddress((void**)&comb2, g_comb2);
    cudaGetSymbolAddress((void**)&qb,    g_q);
    cudaGetSymbolAddress((void**)&kvb,   g_kv);
    cudaGetSymbolAddress((void**)&kpe,   g_kpe);
    cudaGetSymbolAddress((void**)&hid2,  g_hid2);
    cudaGetSymbolAddress((void**)&xnorm16, g_xnorm16);
    cudaGetSymbolAddress((void**)&qlat16,  g_qlat16);
    cudaGetSymbolAddress((void**)&kvn16,   g_kvn16);
    cudaGetSymbolAddress((void**)&attn16,  g_attn16);
    cudaGetSymbolAddress((void**)&ynorm16, g_ynorm16);
    cudaGetSymbolAddress((void**)&gate16,  g_gate16);
    cudaGetSymbolAddress((void**)&wqakva16, g_wqakva16);
    cudaGetSymbolAddress((void**)&wqb16,    g_wqb16);
    cudaGetSymbolAddress((void**)&wkvb16,   g_wkvb16);
    cudaGetSymbolAddress((void**)&wo16,     g_wo16);
    cudaGetSymbolAddress((void**)&wgu16,    g_wgu16);
    cudaGetSymbolAddress((void**)&wd16,     g_wd16);

    const size_t attn_smem = ATT_SMEM_WORDS * sizeof(uint32_t);
    cudaFuncSetAttribute(attn_mma_kernel, cudaFuncAttributeMaxDynamicSharedMemorySize, (int)attn_smem);
    cudaFuncSetAttribute(gemm_fp16, cudaFuncAttributeMaxDynamicSharedMemorySize, GEMMF_SMEM);

    // 0) convert weights (pair-interleaved, fused destinations)
    auto cvt = [&](const float* w, uint32_t* o, int K, int Nsrc, int dstStride, int colOff) {
        int n = (K / 2) * Nsrc;
        cvt_pair_kernel<<<(n + 255) / 256, 256>>>(w, o, K / 2, Nsrc, dstStride, colOff);
    };
    cvt(wq_a,   wqakva16, H_,    QLR_,   NC1_, 0);
    cvt(wkv_a,  wqakva16, H_,    CKVD_,  NC1_, QLR_);
    cvt(wq_b,   wqb16,    QLR_,  QDIM_,  QDIM_, 0);
    cvt(wkv_b,  wkvb16,   KVLR_, KVDIM_, KVDIM_, 0);
    cvt(wo,     wo16,     H_,    H_,     H_, 0);
    cvt(w_gate, wgu16,    H_,    FF_,    NC2_, 0);
    cvt(w_up,   wgu16,    H_,    FF_,    NC2_, FF_);
    cvt(w_down, wd16,     FF_,   H_,     H_, 0);

    dim3 blk256(256);
    auto gemm = [&](const __half* A, const uint32_t* Bw, const float* Cadd, float* C,
                    int M, int N, int K) {
        gemm_fp16<<<dim3(N / 128, M / 128), blk256, GEMMF_SMEM>>>(A, Bw, Cadd, C, M, N, K);
    };

    // 1) xnorm16 = rms(hidden, in_ln)
    rms_kernel<<<S_, 256>>>(hidden, in_ln, xnorm16, H_, H_, H_);
    // 2+5) comb1 = xnorm16 @ [wq_a | wkv_a]   (N=2176, single launch)
    gemm(xnorm16, wqakva16, nullptr, comb1, S_, NC1_, H_);
    // 3) qlat16 = rms(comb1[:, :1536], q_a_ln)
    rms_kernel<<<S_, 256>>>(comb1, q_a_ln, qlat16, QLR_, NC1_, QLR_);
    // 6) kvn16 = rms(comb1[:, 1536:2048], kv_a_ln)
    rms_kernel<<<S_, 256>>>(comb1 + QLR_, kv_a_ln, kvn16, KVLR_, NC1_, KVLR_);
    // 4) q = qlat16 @ wq_b
    gemm(qlat16, wqb16, nullptr, qb, S_, QDIM_, QLR_);
    // 7) kv = kvn16 @ wkv_b
    gemm(kvn16, wkvb16, nullptr, kvb, S_, KVDIM_, KVLR_);
    // 8) RoPE (q in place; kpe from comb1's ckv columns)
    rope_kernel<<<S_, 128>>>(qb, comb1 + QLR_, NC1_, kpe, cosb, sinb, pos);
    // 9) attention
    attn_mma_kernel<<<dim3(S_/64, NH_), 128, attn_smem>>>(qb, kvb, kpe, attn16);
    // 10) hid2 = hidden + attn16 @ wo
    gemm(attn16, wo16, hidden, hid2, S_, H_, H_);
    // 11) ynorm16 = rms(hid2, post_ln)
    rms_kernel<<<S_, 256>>>(hid2, post_ln, ynorm16, H_, H_, H_);
    // 12+13) comb2 = ynorm16 @ [w_gate | w_up]   (N=16384, single launch)
    gemm(ynorm16, wgu16, nullptr, comb2, S_, NC2_, H_);
    // 14) gate16 = silu(comb2.gate) * comb2.up
    {
        int n = S_ * FF_;
        silu_mul_kernel<<<(n + 255) / 256, 256>>>(comb2, gate16, n);
    }
    // 15) out = hid2 + gate16 @ w_down
    gemm(gate16, wd16, hid2, outp, S_, H_, FF_);
}

// round 14
// speedup vs baseline: 1.8950x; 1.1664x over previous
#include <cuda_runtime.h>
#include <cuda_fp16.h>
#include <cuda_bf16.h>
#include <cstdint>
#include <math.h>

// ---------------- problem constants ----------------
#define S_   2048
#define H_   2048
#define NH_  16
#define NOPE_ 128
#define ROPE_ 64
#define QHD_ 192     // NOPE+ROPE
#define VHD_ 128
#define QLR_ 1536
#define KVLR_ 512
#define FF_  8192
#define CKVD_ (KVLR_ + ROPE_)   // 576
#define QDIM_ (NH_*QHD_)        // 3072
#define KVDIM_ (NH_*(NOPE_+VHD_)) // 4096
#define SCALE_ 0.07216878364870323f  // 192^-0.5

#define NC1_ 2176      // combined wq_a(1536) + wkv_a(576) + pad(64)
#define NC2_ 16384     // combined gate(8192) + up(8192)

// ---------------- scratch (static device globals; no runtime alloc) ----------------
__device__ float  g_comb1 [S_*NC1_];    // [:,0:1536]=q_lat, [:,1536:2112]=ckv
__device__ float  g_comb2 [S_*NC2_];    // [:,0:8192]=gate, [:,8192:]=up
__device__ float  g_q     [S_*QDIM_];
__device__ float  g_hid2  [S_*H_];

__device__ __half g_kv16  [S_*KVDIM_];
__device__ __half g_kpe16 [S_*ROPE_];
__device__ uint32_t g_vt  [NH_*VHD_*(S_/2)];   // V transposed pair-words [h][vd][S/2]

__device__ __half g_xnorm16 [S_*H_];
__device__ __half g_qlat16  [S_*QLR_];
__device__ __half g_kvn16   [S_*KVLR_];
__device__ __half g_attn16  [S_*H_];
__device__ __half g_ynorm16 [S_*H_];
__device__ __half g_gate16  [S_*FF_];

// fp16 weights, k-pair-interleaved: word (p,n) = (w[2p][n], w[2p+1][n])
__device__ uint32_t g_wqakva16 [(H_/2)*NC1_];   // pad cols [2112:2176) stay zero
__device__ uint32_t g_wqb16    [(QLR_/2)*QDIM_];
__device__ uint32_t g_wkvb16   [(KVLR_/2)*KVDIM_];
__device__ uint32_t g_wo16     [(H_/2)*H_];
__device__ uint32_t g_wgu16    [(H_/2)*NC2_];
__device__ uint32_t g_wd16     [(FF_/2)*H_];

// ---------------- helpers ----------------
__device__ __forceinline__ float warp_sum(float v) {
    #pragma unroll
    for (int o = 16; o; o >>= 1) v += __shfl_xor_sync(0xffffffffu, v, o);
    return v;
}

__device__ __forceinline__ void mma_fp16(float* d, const uint32_t* a, const uint32_t* b) {
    asm volatile(
        "mma.sync.aligned.m16n8k16.row.col.f32.f16.f16.f32 "
        "{%0,%1,%2,%3}, {%4,%5,%6,%7}, {%8,%9}, {%0,%1,%2,%3};"
        : "+f"(d[0]), "+f"(d[1]), "+f"(d[2]), "+f"(d[3])
        : "r"(a[0]), "r"(a[1]), "r"(a[2]), "r"(a[3]), "r"(b[0]), "r"(b[1]));
}

__device__ __forceinline__ uint32_t packh2(float lo, float hi) {
    __half2 h = __floats2half2_rn(lo, hi);
    return *(uint32_t*)&h;
}

// ---------------- weight convert: fp32 [K][Nsrc] -> u32 pair words, strided dest ----
__global__ void cvt_pair_kernel(const float* __restrict__ w, uint32_t* __restrict__ o,
                                int K2, int Nsrc, int dstStride, int colOff) {
    int idx = blockIdx.x * blockDim.x + threadIdx.x;
    if (idx < K2 * Nsrc) {
        int p = idx / Nsrc, n = idx - p * Nsrc;
        o[(size_t)p * dstStride + colOff + n] =
            packh2(w[(size_t)(2 * p) * Nsrc + n], w[(size_t)(2 * p + 1) * Nsrc + n]);
    }
}

// ---------------- rmsnorm: one block per row, fp16 output ----------------
__global__ void rms_kernel(const float* __restrict__ in, const float* __restrict__ w,
                           __half* __restrict__ out, int dim, int istride, int ostride) {
    int row = blockIdx.x;
    const float* x = in + (size_t)row * istride;
    __half* y = out + (size_t)row * ostride;
    float s = 0.f;
    for (int i = threadIdx.x; i < dim; i += blockDim.x) { float v = x[i]; s += v * v; }
    __shared__ float red[8];
    int lane = threadIdx.x & 31, wid = threadIdx.x >> 5;
    s = warp_sum(s);
    if (lane == 0) red[wid] = s;
    __syncthreads();
    if (wid == 0) {
        float r = (lane < (int)(blockDim.x >> 5)) ? red[lane] : 0.f;
        r = warp_sum(r);
        if (lane == 0) red[0] = r;
    }
    __syncthreads();
    float inv = rsqrtf(red[0] / (float)dim + 1e-6f);
    for (int i = threadIdx.x; i < dim; i += blockDim.x)
        y[i] = __float2half(x[i] * inv * w[i]);
}

// ---------------- V transpose pre-pass: kv16 V-part -> vt[h][vd][S/2] pair words ----
__global__ void vtr_kernel(const __half* __restrict__ kv16, uint32_t* __restrict__ vt) {
    __shared__ __half sm[64 * 130];
    int h = blockIdx.y, kb = blockIdx.x * 64;
    int t = threadIdx.x;
    for (int idx = t; idx < 64 * 64; idx += 128) {
        int row = idx >> 6, w = idx & 63;
        *(uint32_t*)&sm[row * 130 + 2 * w] =
            *(const uint32_t*)(kv16 + (size_t)(kb + row) * KVDIM_ + h * 256 + 128 + 2 * w);
    }
    __syncthreads();
    for (int idx = t; idx < 128 * 32; idx += 128) {
        int vd = idx >> 5, p = idx & 31;
        __half2 hh = __halves2half2(sm[(2 * p) * 130 + vd], sm[(2 * p + 1) * 130 + vd]);
        vt[((size_t)(h * 128 + vd) << 10) + blockIdx.x * 32 + p] = *(uint32_t*)&hh;
    }
}

// ---------------- fp16 tensor-core GEMM: C = A@B (+ Cadd), fp32 accumulate --------
#define AP16 20
#define BP16 136
#define GSTAGE (128*AP16 + 16*BP16)

template<typename CT>
__global__ __launch_bounds__(256, 2) void gemm_fp16(
        const __half* __restrict__ A, const uint32_t* __restrict__ Bw,
        const float* __restrict__ Cadd, CT* __restrict__ C,
        int M, int N, int K) {
    extern __shared__ uint32_t smw[];
    const int t = threadIdx.x;
    const int warp = t >> 5, lane = t & 31;
    const int wm = warp >> 1, wn = warp & 1;
    const int g = lane >> 2, t4 = lane & 3;
    const int m0 = blockIdx.y * 128, n0 = blockIdx.x * 128;

    float acc[2][8][4] = {};

    auto load_stage = [&](int st, int kt) {
        uint32_t* as = smw + st * GSTAGE;
        uint32_t* bs = as + 128 * AP16;
        #pragma unroll
        for (int i = 0; i < 2; i++) {
            int id = t + i * 256;
            int row = id >> 2, c = id & 3;
            uint32_t dst = (uint32_t)__cvta_generic_to_shared(as + row * AP16 + c * 4);
            const __half* src = A + (size_t)(m0 + row) * K + kt * 32 + c * 8;
            asm volatile("cp.async.cg.shared.global [%0], [%1], 16;\n" :: "r"(dst), "l"(src));
        }
        #pragma unroll
        for (int i = 0; i < 2; i++) {
            int id = t + i * 256;
            int prow = id >> 5, c = id & 31;
            uint32_t dst = (uint32_t)__cvta_generic_to_shared(bs + prow * BP16 + c * 4);
            const uint32_t* src = Bw + (size_t)(kt * 16 + prow) * N + n0 + c * 4;
            asm volatile("cp.async.cg.shared.global [%0], [%1], 16;\n" :: "r"(dst), "l"(src));
        }
        asm volatile("cp.async.commit_group;\n");
    };

    auto compute = [&](int st) {
        const uint32_t* as = smw + st * GSTAGE;
        const uint32_t* bs = as + 128 * AP16;
        #pragma unroll
        for (int kc = 0; kc < 2; kc++) {
            const int kw = kc * 8;
            uint32_t af[2][4], bf[8][2];
            #pragma unroll
            for (int i = 0; i < 2; i++) {
                int rbase = wm * 32 + i * 16;
                af[i][0] = as[(rbase + g    ) * AP16 + kw + t4];
                af[i][1] = as[(rbase + 8 + g) * AP16 + kw + t4];
                af[i][2] = as[(rbase + g    ) * AP16 + kw + 4 + t4];
                af[i][3] = as[(rbase + 8 + g) * AP16 + kw + 4 + t4];
            }
            #pragma unroll
            for (int j = 0; j < 8; j++) {
                int cbase = wn * 64 + j * 8 + g;
                bf[j][0] = bs[(kw + t4    ) * BP16 + cbase];
                bf[j][1] = bs[(kw + 4 + t4) * BP16 + cbase];
            }
            #pragma unroll
            for (int i = 0; i < 2; i++)
                #pragma unroll
                for (int j = 0; j < 8; j++)
                    mma_fp16(acc[i][j], af[i], bf[j]);
        }
    };

    const int nk = K / 32;
    load_stage(0, 0);
    if (nk > 1) load_stage(1, 1);

    for (int kt = 0; kt < nk; kt++) {
        if (kt + 1 < nk) { asm volatile("cp.async.wait_group 1;\n"); }
        else             { asm volatile("cp.async.wait_group 0;\n"); }
        __syncthreads();
        if (kt + 2 < nk) load_stage((kt + 2) % 3, kt + 2);
        compute(kt % 3);
    }

    #pragma unroll
    for (int i = 0; i < 2; i++) {
        int r0 = m0 + wm * 32 + i * 16 + g;
        #pragma unroll
        for (int j = 0; j < 8; j++) {
            int cc = n0 + wn * 64 + j * 8 + 2 * t4;
            size_t o0 = (size_t)r0 * N + cc;
            size_t o1 = (size_t)(r0 + 8) * N + cc;
            float v0 = acc[i][j][0], v1 = acc[i][j][1];
            float v2 = acc[i][j][2], v3 = acc[i][j][3];
            if (Cadd) { v0 += Cadd[o0]; v1 += Cadd[o0 + 1]; v2 += Cadd[o1]; v3 += Cadd[o1 + 1]; }
            if constexpr (sizeof(CT) == 4) {
                C[o0] = v0; C[o0 + 1] = v1; C[o1] = v2; C[o1 + 1] = v3;
            } else {
                *(uint32_t*)&C[o0] = packh2(v0, v1);
                *(uint32_t*)&C[o1] = packh2(v2, v3);
            }
        }
    }
}

#define GEMMF_SMEM (3 * GSTAGE * 4)

// ---------------- RoPE (interleaved permute + rotate-half); kpe out fp16 ----------
__global__ void rope_kernel(float* __restrict__ q, const float* __restrict__ ckv_base,
                            int ckv_stride, __half* __restrict__ kpe16,
                            const float* __restrict__ cosb, const float* __restrict__ sinb,
                            const int* __restrict__ pos_ids) {
    int s = blockIdx.x;
    int pos = pos_ids[s];
    const float* c  = cosb + (size_t)pos * ROPE_;
    const float* sn = sinb + (size_t)pos * ROPE_;
    int t = threadIdx.x;
    float ox[4], oy[4];
    #pragma unroll
    for (int it = 0; it < 4; it++) {
        int item = t + it * 128;
        int h = item >> 5, i = item & 31;
        float* base = q + (size_t)s * QDIM_ + h * QHD_ + NOPE_;
        float x0 = base[2 * i], x1 = base[2 * i + 1];
        ox[it] = x0 * c[i]      - x1 * sn[i];
        oy[it] = x1 * c[i + 32] + x0 * sn[i + 32];
    }
    __syncthreads();
    #pragma unroll
    for (int it = 0; it < 4; it++) {
        int item = t + it * 128;
        int h = item >> 5, i = item & 31;
        float* base = q + (size_t)s * QDIM_ + h * QHD_ + NOPE_;
        base[i]      = ox[it];
        base[i + 32] = oy[it];
    }
    if (t < 32) {
        const float* kb = ckv_base + (size_t)s * ckv_stride + KVLR_;
        float x0 = kb[2 * t], x1 = kb[2 * t + 1];
        kpe16[(size_t)s * ROPE_ + t]      = __float2half(x0 * c[t]      - x1 * sn[t]);
        kpe16[(size_t)s * ROPE_ + 32 + t] = __float2half(x1 * c[t + 32] + x0 * sn[t + 32]);
    }
}

// ---------------- fp16 flash attention, cp.async pipelined ----------------
// smem: qw[64][100]; K double-buffer 2x[64][100]; V single [128][36]; P [64][36]
#define AQW 100
#define AKW 100
#define AVW 36
#define APW 36
#define ATT_SMEM_WORDS (64*AQW + 2*64*AKW + 128*AVW + 64*APW)   // 26112 w = 104448 B

__global__ __launch_bounds__(128, 2) void attn_mma_kernel(
        const float* __restrict__ q, const __half* __restrict__ kv16,
        const uint32_t* __restrict__ vt, const __half* __restrict__ kpe16,
        __half* __restrict__ out) {
    extern __shared__ uint32_t smw[];
    uint32_t* qw  = smw;                     // [64][AQW]
    uint32_t* kst = qw + 64 * AQW;           // 2 x [64][AKW]
    uint32_t* vst = kst + 2 * 64 * AKW;      // [128][AVW]
    uint32_t* pw  = vst + 128 * AVW;         // [64][APW]

    const int h = blockIdx.y;
    const int qblk = (int)gridDim.x - 1 - (int)blockIdx.x;   // heavy blocks first
    const int t = threadIdx.x;
    const int warp = t >> 5, lane = t & 31;
    const int g = lane >> 2, t4 = lane & 3;
    const int qbase = qblk * 64;
    const int wrow = warp * 16;

    auto load_k = [&](int kt, int st) {
        uint32_t* ks = kst + st * 64 * AKW;
        const int kbase = kt * 64;
        for (int idx = t; idx < 64 * 24; idx += 128) {
            int row = idx / 24, c = idx - row * 24;
            uint32_t dst;
            const __half* src;
            if (c < 16) {
                dst = (uint32_t)__cvta_generic_to_shared(ks + row * AKW + c * 4);
                src = kv16 + (size_t)(kbase + row) * KVDIM_ + h * 256 + c * 8;
            } else {
                dst = (uint32_t)__cvta_generic_to_shared(ks + row * AKW + 64 + (c - 16) * 4);
                src = kpe16 + (size_t)(kbase + row) * ROPE_ + (c - 16) * 8;
            }
            asm volatile("cp.async.cg.shared.global [%0], [%1], 16;\n" :: "r"(dst), "l"(src));
        }
        asm volatile("cp.async.commit_group;\n");
    };
    auto load_v = [&](int kt) {
        const uint32_t* base = vt + ((size_t)(h * 128) << 10) + kt * 32;
        for (int idx = t; idx < 128 * 8; idx += 128) {
            int vd = idx >> 3, c = idx & 7;
            uint32_t dst = (uint32_t)__cvta_generic_to_shared(vst + vd * AVW + c * 4);
            const uint32_t* src = base + ((size_t)vd << 10) + c * 4;
            asm volatile("cp.async.cg.shared.global [%0], [%1], 16;\n" :: "r"(dst), "l"(src));
        }
        asm volatile("cp.async.commit_group;\n");
    };

    // K(0) in flight; Q loaded meanwhile (fp32 -> fp16 words)
    load_k(0, 0);
    for (int idx = t; idx < 64 * 48; idx += 128) {
        int row = idx / 48, c = idx - row * 48;
        float4 v = *(const float4*)&q[(size_t)(qbase + row) * QDIM_ + h * QHD_ + c * 4];
        uint2 pk = { packh2(v.x, v.y), packh2(v.z, v.w) };
        *(uint2*)&qw[row * AQW + c * 2] = pk;
    }

    float oa[16][4];
    #pragma unroll
    for (int j = 0; j < 16; j++)
        #pragma unroll
        for (int c = 0; c < 4; c++) oa[j][c] = 0.f;
    float m0 = -1e30f, m1 = -1e30f, l0 = 0.f, l1 = 0.f;

    for (int kt = 0; kt <= qblk; kt++) {
        const int kbase = kt * 64;
        const bool havenext = (kt + 1 <= qblk);
        asm volatile("cp.async.wait_group 0;\n");   // K(kt) arrived
        __syncthreads();                            // K visible; prior PV done
        load_v(kt);                                 // overlaps S compute
        if (havenext) load_k(kt + 1, (kt + 1) & 1);

        // ---- S = Q @ K^T ----
        const uint32_t* ks = kst + (kt & 1) * 64 * AKW;
        float sa[8][4];
        #pragma unroll
        for (int j = 0; j < 8; j++)
            #pragma unroll
            for (int c = 0; c < 4; c++) sa[j][c] = 0.f;
        #pragma unroll
        for (int kc = 0; kc < 12; kc++) {
            const int kw0 = kc * 8;
            uint32_t af[4], bf[8][2];
            af[0] = qw[(wrow + g    ) * AQW + kw0 + t4];
            af[1] = qw[(wrow + 8 + g) * AQW + kw0 + t4];
            af[2] = qw[(wrow + g    ) * AQW + kw0 + 4 + t4];
            af[3] = qw[(wrow + 8 + g) * AQW + kw0 + 4 + t4];
            #pragma unroll
            for (int j = 0; j < 8; j++) {
                bf[j][0] = ks[(j * 8 + g) * AKW + kw0 + t4];
                bf[j][1] = ks[(j * 8 + g) * AKW + kw0 + 4 + t4];
            }
            #pragma unroll
            for (int j = 0; j < 8; j++) mma_fp16(sa[j], af, bf[j]);
        }

        // ---- mask + scale ----
        const int r0 = qbase + wrow + g;
        const int r1 = r0 + 8;
        const bool diag = (kt == qblk);
        #pragma unroll
        for (int j = 0; j < 8; j++) {
            int c0 = kbase + j * 8 + 2 * t4, c1 = c0 + 1;
            sa[j][0] *= SCALE_; sa[j][1] *= SCALE_;
            sa[j][2] *= SCALE_; sa[j][3] *= SCALE_;
            if (diag) {
                if (c0 > r0) sa[j][0] = -1e30f;
                if (c1 > r0) sa[j][1] = -1e30f;
                if (c0 > r1) sa[j][2] = -1e30f;
                if (c1 > r1) sa[j][3] = -1e30f;
            }
        }

        // ---- online softmax ----
        float tm0 = -1e30f, tm1 = -1e30f;
        #pragma unroll
        for (int j = 0; j < 8; j++) {
            tm0 = fmaxf(tm0, fmaxf(sa[j][0], sa[j][1]));
            tm1 = fmaxf(tm1, fmaxf(sa[j][2], sa[j][3]));
        }
        tm0 = fmaxf(tm0, __shfl_xor_sync(0xffffffffu, tm0, 1));
        tm0 = fmaxf(tm0, __shfl_xor_sync(0xffffffffu, tm0, 2));
        tm1 = fmaxf(tm1, __shfl_xor_sync(0xffffffffu, tm1, 1));
        tm1 = fmaxf(tm1, __shfl_xor_sync(0xffffffffu, tm1, 2));
        float m0n = fmaxf(m0, tm0), m1n = fmaxf(m1, tm1);
        float a0 = __expf(m0 - m0n), a1 = __expf(m1 - m1n);
        float ps0 = 0.f, ps1 = 0.f;
        #pragma unroll
        for (int j = 0; j < 8; j++) {
            sa[j][0] = __expf(sa[j][0] - m0n); sa[j][1] = __expf(sa[j][1] - m0n);
            sa[j][2] = __expf(sa[j][2] - m1n); sa[j][3] = __expf(sa[j][3] - m1n);
            ps0 += sa[j][0] + sa[j][1];
            ps1 += sa[j][2] + sa[j][3];
        }
        ps0 += __shfl_xor_sync(0xffffffffu, ps0, 1);
        ps0 += __shfl_xor_sync(0xffffffffu, ps0, 2);
        ps1 += __shfl_xor_sync(0xffffffffu, ps1, 1);
        ps1 += __shfl_xor_sync(0xffffffffu, ps1, 2);
        l0 = l0 * a0 + ps0; l1 = l1 * a1 + ps1;
        m0 = m0n; m1 = m1n;
        #pragma unroll
        for (int j = 0; j < 16; j++) {
            oa[j][0] *= a0; oa[j][1] *= a0;
            oa[j][2] *= a1; oa[j][3] *= a1;
        }
        #pragma unroll
        for (int j = 0; j < 8; j++) {
            pw[(wrow + g    ) * APW + j * 4 + t4] = packh2(sa[j][0], sa[j][1]);
            pw[(wrow + 8 + g) * APW + j * 4 + t4] = packh2(sa[j][2], sa[j][3]);
        }
        __syncwarp();

        // ---- wait V, then O += P @ V ----
        if (havenext) { asm volatile("cp.async.wait_group 1;\n"); }
        else          { asm volatile("cp.async.wait_group 0;\n"); }
        __syncthreads();
        #pragma unroll
        for (int kc = 0; kc < 4; kc++) {
            const int kw0 = kc * 8;
            uint32_t af[4], bf[16][2];
            af[0] = pw[(wrow + g    ) * APW + kw0 + t4];
            af[1] = pw[(wrow + 8 + g) * APW + kw0 + t4];
            af[2] = pw[(wrow + g    ) * APW + kw0 + 4 + t4];
            af[3] = pw[(wrow + 8 + g) * APW + kw0 + 4 + t4];
            #pragma unroll
            for (int j = 0; j < 16; j++) {
                bf[j][0] = vst[(j * 8 + g) * AVW + kw0 + t4];
                bf[j][1] = vst[(j * 8 + g) * AVW + kw0 + 4 + t4];
            }
            #pragma unroll
            for (int j = 0; j < 16; j++) mma_fp16(oa[j], af, bf[j]);
        }
        __syncthreads();   // all warps done with V before next tile's load_v
    }

    float i0 = 1.f / l0, i1 = 1.f / l1;
    const int r0 = qbase + wrow + g;
    __half* o0 = out + (size_t)r0 * H_ + h * VHD_;
    __half* o1 = out + (size_t)(r0 + 8) * H_ + h * VHD_;
    #pragma unroll
    for (int j = 0; j < 16; j++) {
        int cc = j * 8 + 2 * t4;
        o0[cc]     = __float2half(oa[j][0] * i0);
        o0[cc + 1] = __float2half(oa[j][1] * i0);
        o1[cc]     = __float2half(oa[j][2] * i1);
        o1[cc + 1] = __float2half(oa[j][3] * i1);
    }
}

// ---------------- silu(comb2.gate) * comb2.up -> fp16 ----------------
__global__ void silu_mul_kernel(const float* __restrict__ comb2,
                                __half* __restrict__ o, int n) {
    int i = blockIdx.x * blockDim.x + threadIdx.x;
    if (i < n) {
        int s = i / FF_, c = i - s * FF_;
        float x = comb2[(size_t)s * NC2_ + c];
        float u = comb2[(size_t)s * NC2_ + FF_ + c];
        float sg = x / (1.f + __expf(-x));
        o[i] = __float2half(sg * u);
    }
}

// ---------------- launcher ----------------
extern "C" void kernel_launch(void* const* d_in, const int* in_sizes, int n_in,
                              void* d_out, int out_size) {
    const float* hidden  = (const float*)d_in[0];
    const float* sinb    = (const float*)d_in[1];
    const float* cosb    = (const float*)d_in[2];
    const float* wq_a    = (const float*)d_in[3];
    const float* q_a_ln  = (const float*)d_in[4];
    const float* wq_b    = (const float*)d_in[5];
    const float* wkv_a   = (const float*)d_in[6];
    const float* kv_a_ln = (const float*)d_in[7];
    const float* wkv_b   = (const float*)d_in[8];
    const float* wo      = (const float*)d_in[9];
    const float* in_ln   = (const float*)d_in[10];
    const float* post_ln = (const float*)d_in[11];
    const float* w_gate  = (const float*)d_in[12];
    const float* w_up    = (const float*)d_in[13];
    const float* w_down  = (const float*)d_in[14];
    const int*   pos     = (const int*)d_in[15];
    float* outp = (float*)d_out;

    float *comb1, *comb2, *qb, *hid2;
    __half *kv16, *kpe16, *xnorm16, *qlat16, *kvn16, *attn16, *ynorm16, *gate16;
    uint32_t *vt, *wqakva16, *wqb16, *wkvb16, *wo16, *wgu16, *wd16;
    cudaGetSymbolAddress((void**)&comb1, g_comb1);
    cudaGetSymbolAddress((void**)&comb2, g_comb2);
    cudaGetSymbolAddress((void**)&qb,    g_q);
    cudaGetSymbolAddress((void**)&hid2,  g_hid2);
    cudaGetSymbolAddress((void**)&kv16,  g_kv16);
    cudaGetSymbolAddress((void**)&kpe16, g_kpe16);
    cudaGetSymbolAddress((void**)&vt,    g_vt);
    cudaGetSymbolAddress((void**)&xnorm16, g_xnorm16);
    cudaGetSymbolAddress((void**)&qlat16,  g_qlat16);
    cudaGetSymbolAddress((void**)&kvn16,   g_kvn16);
    cudaGetSymbolAddress((void**)&attn16,  g_attn16);
    cudaGetSymbolAddress((void**)&ynorm16, g_ynorm16);
    cudaGetSymbolAddress((void**)&gate16,  g_gate16);
    cudaGetSymbolAddress((void**)&wqakva16, g_wqakva16);
    cudaGetSymbolAddress((void**)&wqb16,    g_wqb16);
    cudaGetSymbolAddress((void**)&wkvb16,   g_wkvb16);
    cudaGetSymbolAddress((void**)&wo16,     g_wo16);
    cudaGetSymbolAddress((void**)&wgu16,    g_wgu16);
    cudaGetSymbolAddress((void**)&wd16,     g_wd16);

    const size_t attn_smem = ATT_SMEM_WORDS * sizeof(uint32_t);
    cudaFuncSetAttribute(attn_mma_kernel, cudaFuncAttributeMaxDynamicSharedMemorySize, (int)attn_smem);
    cudaFuncSetAttribute(gemm_fp16<float>,  cudaFuncAttributeMaxDynamicSharedMemorySize, GEMMF_SMEM);
    cudaFuncSetAttribute(gemm_fp16<__half>, cudaFuncAttributeMaxDynamicSharedMemorySize, GEMMF_SMEM);

    // 0) convert weights (pair-interleaved, fused destinations)
    auto cvt = [&](const float* w, uint32_t* o, int K, int Nsrc, int dstStride, int colOff) {
        int n = (K / 2) * Nsrc;
        cvt_pair_kernel<<<(n + 255) / 256, 256>>>(w, o, K / 2, Nsrc, dstStride, colOff);
    };
    cvt(wq_a,   wqakva16, H_,    QLR_,   NC1_, 0);
    cvt(wkv_a,  wqakva16, H_,    CKVD_,  NC1_, QLR_);
    cvt(wq_b,   wqb16,    QLR_,  QDIM_,  QDIM_, 0);
    cvt(wkv_b,  wkvb16,   KVLR_, KVDIM_, KVDIM_, 0);
    cvt(wo,     wo16,     H_,    H_,     H_, 0);
    cvt(w_gate, wgu16,    H_,    FF_,    NC2_, 0);
    cvt(w_up,   wgu16,    H_,    FF_,    NC2_, FF_);
    cvt(w_down, wd16,     FF_,   H_,     H_, 0);

    dim3 blk256(256);
    auto gemm = [&](const __half* A, const uint32_t* Bw, const float* Cadd, float* C,
                    int M, int N, int K) {
        gemm_fp16<float><<<dim3(N / 128, M / 128), blk256, GEMMF_SMEM>>>(A, Bw, Cadd, C, M, N, K);
    };
    auto gemm_h = [&](const __half* A, const uint32_t* Bw, __half* C,
                      int M, int N, int K) {
        gemm_fp16<__half><<<dim3(N / 128, M / 128), blk256, GEMMF_SMEM>>>(A, Bw, nullptr, C, M, N, K);
    };

    // 1) xnorm16 = rms(hidden, in_ln)
    rms_kernel<<<S_, 256>>>(hidden, in_ln, xnorm16, H_, H_, H_);
    // 2+5) comb1 = xnorm16 @ [wq_a | wkv_a]
    gemm(xnorm16, wqakva16, nullptr, comb1, S_, NC1_, H_);
    // 3) qlat16 = rms(comb1[:, :1536], q_a_ln)
    rms_kernel<<<S_, 256>>>(comb1, q_a_ln, qlat16, QLR_, NC1_, QLR_);
    // 6) kvn16 = rms(comb1[:, 1536:2048], kv_a_ln)
    rms_kernel<<<S_, 256>>>(comb1 + QLR_, kv_a_ln, kvn16, KVLR_, NC1_, KVLR_);
    // 4) q = qlat16 @ wq_b  (fp32; rope runs in place)
    gemm(qlat16, wqb16, nullptr, qb, S_, QDIM_, QLR_);
    // 7) kv16 = kvn16 @ wkv_b   (fp16 output)
    gemm_h(kvn16, wkvb16, kv16, S_, KVDIM_, KVLR_);
    // 7b) V transpose pre-pass
    vtr_kernel<<<dim3(S_/64, NH_), 128>>>(kv16, vt);
    // 8) RoPE (q in place fp32; kpe16 out)
    rope_kernel<<<S_, 128>>>(qb, comb1 + QLR_, NC1_, kpe16, cosb, sinb, pos);
    // 9) attention (pipelined fp16)
    attn_mma_kernel<<<dim3(S_/64, NH_), 128, attn_smem>>>(qb, kv16, vt, kpe16, attn16);
    // 10) hid2 = hidden + attn16 @ wo
    gemm(attn16, wo16, hidden, hid2, S_, H_, H_);
    // 11) ynorm16 = rms(hid2, post_ln)
    rms_kernel<<<S_, 256>>>(hid2, post_ln, ynorm16, H_, H_, H_);
    // 12+13) comb2 = ynorm16 @ [w_gate | w_up]
    gemm(ynorm16, wgu16, nullptr, comb2, S_, NC2_, H_);
    // 14) gate16 = silu(comb2.gate) * comb2.up
    {
        int n = S_ * FF_;
        silu_mul_kernel<<<(n + 255) / 256, 256>>>(comb2, gate16, n);
    }
    // 15) out = hid2 + gate16 @ w_down
    gemm(gate16, wd16, hid2, outp, S_, H_, FF_);
}

// round 15
// speedup vs baseline: 1.9843x; 1.0471x over previous
#include <cuda_runtime.h>
#include <cuda_fp16.h>
#include <cuda_bf16.h>
#include <cstdint>
#include <math.h>

// ---------------- problem constants ----------------
#define S_   2048
#define H_   2048
#define NH_  16
#define NOPE_ 128
#define ROPE_ 64
#define QHD_ 192     // NOPE+ROPE
#define VHD_ 128
#define QLR_ 1536
#define KVLR_ 512
#define FF_  8192
#define CKVD_ (KVLR_ + ROPE_)   // 576
#define QDIM_ (NH_*QHD_)        // 3072
#define KVDIM_ (NH_*(NOPE_+VHD_)) // 4096
#define SCALE_ 0.07216878364870323f  // 192^-0.5

#define NC1_ 2176      // combined wq_a(1536) + wkv_a(576) + pad(64)
#define NC2_ 16384     // interleaved gate/up: even col=gate, odd col=up

// ---------------- scratch (static device globals; no runtime alloc) ----------------
__device__ float  g_comb1 [S_*NC1_];    // [:,0:1536]=q_lat, [:,1536:2112]=ckv
__device__ float  g_hid2  [S_*H_];

__device__ __half g_q16   [S_*QDIM_];
__device__ __half g_kv16  [S_*KVDIM_];
__device__ __half g_kpe16 [S_*ROPE_];
__device__ uint32_t g_vt  [NH_*VHD_*(S_/2)];   // V transposed pair-words [h][vd][S/2]

__device__ __half g_xnorm16 [S_*H_];
__device__ __half g_qlat16  [S_*QLR_];
__device__ __half g_kvn16   [S_*KVLR_];
__device__ __half g_attn16  [S_*H_];
__device__ __half g_ynorm16 [S_*H_];
__device__ __half g_gate16  [S_*FF_];

// fp16 weights, k-pair-interleaved: word (p,n) = (w[2p][n], w[2p+1][n])
__device__ uint32_t g_wqakva16 [(H_/2)*NC1_];   // pad cols [2112:2176) stay zero
__device__ uint32_t g_wqb16    [(QLR_/2)*QDIM_];
__device__ uint32_t g_wkvb16   [(KVLR_/2)*KVDIM_];
__device__ uint32_t g_wo16     [(H_/2)*H_];
__device__ uint32_t g_wgu16    [(H_/2)*NC2_];   // column-interleaved gate/up
__device__ uint32_t g_wd16     [(FF_/2)*H_];

// ---------------- helpers ----------------
__device__ __forceinline__ float warp_sum(float v) {
    #pragma unroll
    for (int o = 16; o; o >>= 1) v += __shfl_xor_sync(0xffffffffu, v, o);
    return v;
}

__device__ __forceinline__ void mma_fp16(float* d, const uint32_t* a, const uint32_t* b) {
    asm volatile(
        "mma.sync.aligned.m16n8k16.row.col.f32.f16.f16.f32 "
        "{%0,%1,%2,%3}, {%4,%5,%6,%7}, {%8,%9}, {%0,%1,%2,%3};"
        : "+f"(d[0]), "+f"(d[1]), "+f"(d[2]), "+f"(d[3])
        : "r"(a[0]), "r"(a[1]), "r"(a[2]), "r"(a[3]), "r"(b[0]), "r"(b[1]));
}

__device__ __forceinline__ uint32_t packh2(float lo, float hi) {
    __half2 h = __floats2half2_rn(lo, hi);
    return *(uint32_t*)&h;
}

// ---------------- weight convert: fp32 [K][Nsrc] -> pair words, strided dest ------
__global__ void cvt_pair_kernel(const float* __restrict__ w, uint32_t* __restrict__ o,
                                int K2, int Nsrc, int dstStride, int colOff, int colStride) {
    int idx = blockIdx.x * blockDim.x + threadIdx.x;
    if (idx < K2 * Nsrc) {
        int p = idx / Nsrc, n = idx - p * Nsrc;
        o[(size_t)p * dstStride + colOff + n * colStride] =
            packh2(w[(size_t)(2 * p) * Nsrc + n], w[(size_t)(2 * p + 1) * Nsrc + n]);
    }
}

// ---------------- rmsnorm: one block per row, fp16 output ----------------
__global__ void rms_kernel(const float* __restrict__ in, const float* __restrict__ w,
                           __half* __restrict__ out, int dim, int istride, int ostride) {
    int row = blockIdx.x;
    const float* x = in + (size_t)row * istride;
    __half* y = out + (size_t)row * ostride;
    float s = 0.f;
    for (int i = threadIdx.x; i < dim; i += blockDim.x) { float v = x[i]; s += v * v; }
    __shared__ float red[8];
    int lane = threadIdx.x & 31, wid = threadIdx.x >> 5;
    s = warp_sum(s);
    if (lane == 0) red[wid] = s;
    __syncthreads();
    if (wid == 0) {
        float r = (lane < (int)(blockDim.x >> 5)) ? red[lane] : 0.f;
        r = warp_sum(r);
        if (lane == 0) red[0] = r;
    }
    __syncthreads();
    float inv = rsqrtf(red[0] / (float)dim + 1e-6f);
    for (int i = threadIdx.x; i < dim; i += blockDim.x)
        y[i] = __float2half(x[i] * inv * w[i]);
}

// ---------------- V transpose pre-pass: kv16 V-part -> vt[h][vd][S/2] pair words ----
__global__ void vtr_kernel(const __half* __restrict__ kv16, uint32_t* __restrict__ vt) {
    __shared__ __half sm[64 * 130];
    int h = blockIdx.y, kb = blockIdx.x * 64;
    int t = threadIdx.x;
    for (int idx = t; idx < 64 * 64; idx += 128) {
        int row = idx >> 6, w = idx & 63;
        *(uint32_t*)&sm[row * 130 + 2 * w] =
            *(const uint32_t*)(kv16 + (size_t)(kb + row) * KVDIM_ + h * 256 + 128 + 2 * w);
    }
    __syncthreads();
    for (int idx = t; idx < 128 * 32; idx += 128) {
        int vd = idx >> 5, p = idx & 31;
        __half2 hh = __halves2half2(sm[(2 * p) * 130 + vd], sm[(2 * p + 1) * 130 + vd]);
        vt[((size_t)(h * 128 + vd) << 10) + blockIdx.x * 32 + p] = *(uint32_t*)&hh;
    }
}

// ---------------- fp16 tensor-core GEMM: C = A@B (+ Cadd), fp32 accumulate --------
// SILU variant: B columns interleaved (even=gate, odd=up); epilogue writes
// silu(gate)*up as fp16 at logical column cc/2 with row stride N/2.
#define AP16 20
#define BP16 136
#define GSTAGE (128*AP16 + 16*BP16)

template<typename CT, bool SILU>
__global__ __launch_bounds__(256, 2) void gemm_fp16(
        const __half* __restrict__ A, const uint32_t* __restrict__ Bw,
        const float* __restrict__ Cadd, CT* __restrict__ C,
        int M, int N, int K) {
    extern __shared__ uint32_t smw[];
    const int t = threadIdx.x;
    const int warp = t >> 5, lane = t & 31;
    const int wm = warp >> 1, wn = warp & 1;
    const int g = lane >> 2, t4 = lane & 3;
    const int m0 = blockIdx.y * 128, n0 = blockIdx.x * 128;

    float acc[2][8][4] = {};

    auto load_stage = [&](int st, int kt) {
        uint32_t* as = smw + st * GSTAGE;
        uint32_t* bs = as + 128 * AP16;
        #pragma unroll
        for (int i = 0; i < 2; i++) {
            int id = t + i * 256;
            int row = id >> 2, c = id & 3;
            uint32_t dst = (uint32_t)__cvta_generic_to_shared(as + row * AP16 + c * 4);
            const __half* src = A + (size_t)(m0 + row) * K + kt * 32 + c * 8;
            asm volatile("cp.async.cg.shared.global [%0], [%1], 16;\n" :: "r"(dst), "l"(src));
        }
        #pragma unroll
        for (int i = 0; i < 2; i++) {
            int id = t + i * 256;
            int prow = id >> 5, c = id & 31;
            uint32_t dst = (uint32_t)__cvta_generic_to_shared(bs + prow * BP16 + c * 4);
            const uint32_t* src = Bw + (size_t)(kt * 16 + prow) * N + n0 + c * 4;
            asm volatile("cp.async.cg.shared.global [%0], [%1], 16;\n" :: "r"(dst), "l"(src));
        }
        asm volatile("cp.async.commit_group;\n");
    };

    auto compute = [&](int st) {
        const uint32_t* as = smw + st * GSTAGE;
        const uint32_t* bs = as + 128 * AP16;
        #pragma unroll
        for (int kc = 0; kc < 2; kc++) {
            const int kw = kc * 8;
            uint32_t af[2][4], bf[8][2];
            #pragma unroll
            for (int i = 0; i < 2; i++) {
                int rbase = wm * 32 + i * 16;
                af[i][0] = as[(rbase + g    ) * AP16 + kw + t4];
                af[i][1] = as[(rbase + 8 + g) * AP16 + kw + t4];
                af[i][2] = as[(rbase + g    ) * AP16 + kw + 4 + t4];
                af[i][3] = as[(rbase + 8 + g) * AP16 + kw + 4 + t4];
            }
            #pragma unroll
            for (int j = 0; j < 8; j++) {
                int cbase = wn * 64 + j * 8 + g;
                bf[j][0] = bs[(kw + t4    ) * BP16 + cbase];
                bf[j][1] = bs[(kw + 4 + t4) * BP16 + cbase];
            }
            #pragma unroll
            for (int i = 0; i < 2; i++)
                #pragma unroll
                for (int j = 0; j < 8; j++)
                    mma_fp16(acc[i][j], af[i], bf[j]);
        }
    };

    const int nk = K / 32;
    load_stage(0, 0);
    if (nk > 1) load_stage(1, 1);

    for (int kt = 0; kt < nk; kt++) {
        if (kt + 1 < nk) { asm volatile("cp.async.wait_group 1;\n"); }
        else             { asm volatile("cp.async.wait_group 0;\n"); }
        __syncthreads();
        if (kt + 2 < nk) load_stage((kt + 2) % 3, kt + 2);
        compute(kt % 3);
    }

    #pragma unroll
    for (int i = 0; i < 2; i++) {
        int r0 = m0 + wm * 32 + i * 16 + g;
        #pragma unroll
        for (int j = 0; j < 8; j++) {
            int cc = n0 + wn * 64 + j * 8 + 2 * t4;   // always even
            float v0 = acc[i][j][0], v1 = acc[i][j][1];
            float v2 = acc[i][j][2], v3 = acc[i][j][3];
            if constexpr (SILU) {
                float sg0 = v0 / (1.f + __expf(-v0));
                float sg2 = v2 / (1.f + __expf(-v2));
                C[(size_t)r0 * (N >> 1) + (cc >> 1)]       = (CT)__float2half(sg0 * v1);
                C[(size_t)(r0 + 8) * (N >> 1) + (cc >> 1)] = (CT)__float2half(sg2 * v3);
            } else {
                size_t o0 = (size_t)r0 * N + cc;
                size_t o1 = (size_t)(r0 + 8) * N + cc;
                if (Cadd) { v0 += Cadd[o0]; v1 += Cadd[o0 + 1]; v2 += Cadd[o1]; v3 += Cadd[o1 + 1]; }
                if constexpr (sizeof(CT) == 4) {
                    C[o0] = v0; C[o0 + 1] = v1; C[o1] = v2; C[o1 + 1] = v3;
                } else {
                    *(uint32_t*)&C[o0] = packh2(v0, v1);
                    *(uint32_t*)&C[o1] = packh2(v2, v3);
                }
            }
        }
    }
}

#define GEMMF_SMEM (3 * GSTAGE * 4)

// ---------------- RoPE on fp16 q (in place) + fp16 kpe out ----------------
__global__ void rope_kernel(__half* __restrict__ q16, const float* __restrict__ ckv_base,
                            int ckv_stride, __half* __restrict__ kpe16,
                            const float* __restrict__ cosb, const float* __restrict__ sinb,
                            const int* __restrict__ pos_ids) {
    int s = blockIdx.x;
    int pos = pos_ids[s];
    const float* c  = cosb + (size_t)pos * ROPE_;
    const float* sn = sinb + (size_t)pos * ROPE_;
    int t = threadIdx.x;
    float ox[4], oy[4];
    #pragma unroll
    for (int it = 0; it < 4; it++) {
        int item = t + it * 128;
        int h = item >> 5, i = item & 31;
        __half* base = q16 + (size_t)s * QDIM_ + h * QHD_ + NOPE_;
        float x0 = __half2float(base[2 * i]), x1 = __half2float(base[2 * i + 1]);
        ox[it] = x0 * c[i]      - x1 * sn[i];
        oy[it] = x1 * c[i + 32] + x0 * sn[i + 32];
    }
    __syncthreads();
    #pragma unroll
    for (int it = 0; it < 4; it++) {
        int item = t + it * 128;
        int h = item >> 5, i = item & 31;
        __half* base = q16 + (size_t)s * QDIM_ + h * QHD_ + NOPE_;
        base[i]      = __float2half(ox[it]);
        base[i + 32] = __float2half(oy[it]);
    }
    if (t < 32) {
        const float* kb = ckv_base + (size_t)s * ckv_stride + KVLR_;
        float x0 = kb[2 * t], x1 = kb[2 * t + 1];
        kpe16[(size_t)s * ROPE_ + t]      = __float2half(x0 * c[t]      - x1 * sn[t]);
        kpe16[(size_t)s * ROPE_ + 32 + t] = __float2half(x1 * c[t + 32] + x0 * sn[t + 32]);
    }
}

// ---------------- fp16 flash attention, cp.async pipelined ----------------
#define AQW 100
#define AKW 100
#define AVW 36
#define APW 36
#define ATT_SMEM_WORDS (64*AQW + 2*64*AKW + 128*AVW + 64*APW)   // 104448 B

__global__ __launch_bounds__(128, 2) void attn_mma_kernel(
        const __half* __restrict__ q16, const __half* __restrict__ kv16,
        const uint32_t* __restrict__ vt, const __half* __restrict__ kpe16,
        __half* __restrict__ out) {
    extern __shared__ uint32_t smw[];
    uint32_t* qw  = smw;                     // [64][AQW]
    uint32_t* kst = qw + 64 * AQW;           // 2 x [64][AKW]
    uint32_t* vst = kst + 2 * 64 * AKW;      // [128][AVW]
    uint32_t* pw  = vst + 128 * AVW;         // [64][APW]

    const int h = blockIdx.y;
    const int qblk = (int)gridDim.x - 1 - (int)blockIdx.x;   // heavy blocks first
    const int t = threadIdx.x;
    const int warp = t >> 5, lane = t & 31;
    const int g = lane >> 2, t4 = lane & 3;
    const int qbase = qblk * 64;
    const int wrow = warp * 16;

    auto load_k = [&](int kt, int st) {
        uint32_t* ks = kst + st * 64 * AKW;
        const int kbase = kt * 64;
        for (int idx = t; idx < 64 * 24; idx += 128) {
            int row = idx / 24, c = idx - row * 24;
            uint32_t dst;
            const __half* src;
            if (c < 16) {
                dst = (uint32_t)__cvta_generic_to_shared(ks + row * AKW + c * 4);
                src = kv16 + (size_t)(kbase + row) * KVDIM_ + h * 256 + c * 8;
            } else {
                dst = (uint32_t)__cvta_generic_to_shared(ks + row * AKW + 64 + (c - 16) * 4);
                src = kpe16 + (size_t)(kbase + row) * ROPE_ + (c - 16) * 8;
            }
            asm volatile("cp.async.cg.shared.global [%0], [%1], 16;\n" :: "r"(dst), "l"(src));
        }
        asm volatile("cp.async.commit_group;\n");
    };
    auto load_v = [&](int kt) {
        const uint32_t* base = vt + ((size_t)(h * 128) << 10) + kt * 32;
        for (int idx = t; idx < 128 * 8; idx += 128) {
            int vd = idx >> 3, c = idx & 7;
            uint32_t dst = (uint32_t)__cvta_generic_to_shared(vst + vd * AVW + c * 4);
            const uint32_t* src = base + ((size_t)vd << 10) + c * 4;
            asm volatile("cp.async.cg.shared.global [%0], [%1], 16;\n" :: "r"(dst), "l"(src));
        }
        asm volatile("cp.async.commit_group;\n");
    };

    // K(0) and Q in flight together
    load_k(0, 0);
    for (int idx = t; idx < 64 * 24; idx += 128) {
        int row = idx / 24, c = idx - row * 24;
        uint32_t dst = (uint32_t)__cvta_generic_to_shared(qw + row * AQW + c * 4);
        const __half* src = q16 + (size_t)(qbase + row) * QDIM_ + h * QHD_ + c * 8;
        asm volatile("cp.async.cg.shared.global [%0], [%1], 16;\n" :: "r"(dst), "l"(src));
    }
    asm volatile("cp.async.commit_group;\n");

    float oa[16][4];
    #pragma unroll
    for (int j = 0; j < 16; j++)
        #pragma unroll
        for (int c = 0; c < 4; c++) oa[j][c] = 0.f;
    float m0 = -1e30f, m1 = -1e30f, l0 = 0.f, l1 = 0.f;

    for (int kt = 0; kt <= qblk; kt++) {
        const int kbase = kt * 64;
        const bool havenext = (kt + 1 <= qblk);
        asm volatile("cp.async.wait_group 0;\n");   // K(kt) (+Q at kt=0) arrived
        __syncthreads();
        load_v(kt);                                 // overlaps S compute
        if (havenext) load_k(kt + 1, (kt + 1) & 1);

        // ---- S = Q @ K^T ----
        const uint32_t* ks = kst + (kt & 1) * 64 * AKW;
        float sa[8][4];
        #pragma unroll
        for (int j = 0; j < 8; j++)
            #pragma unroll
            for (int c = 0; c < 4; c++) sa[j][c] = 0.f;
        #pragma unroll
        for (int kc = 0; kc < 12; kc++) {
            const int kw0 = kc * 8;
            uint32_t af[4], bf[8][2];
            af[0] = qw[(wrow + g    ) * AQW + kw0 + t4];
            af[1] = qw[(wrow + 8 + g) * AQW + kw0 + t4];
            af[2] = qw[(wrow + g    ) * AQW + kw0 + 4 + t4];
            af[3] = qw[(wrow + 8 + g) * AQW + kw0 + 4 + t4];
            #pragma unroll
            for (int j = 0; j < 8; j++) {
                bf[j][0] = ks[(j * 8 + g) * AKW + kw0 + t4];
                bf[j][1] = ks[(j * 8 + g) * AKW + kw0 + 4 + t4];
            }
            #pragma unroll
            for (int j = 0; j < 8; j++) mma_fp16(sa[j], af, bf[j]);
        }

        // ---- mask + scale ----
        const int r0 = qbase + wrow + g;
        const int r1 = r0 + 8;
        const bool diag = (kt == qblk);
        #pragma unroll
        for (int j = 0; j < 8; j++) {
            int c0 = kbase + j * 8 + 2 * t4, c1 = c0 + 1;
            sa[j][0] *= SCALE_; sa[j][1] *= SCALE_;
            sa[j][2] *= SCALE_; sa[j][3] *= SCALE_;
            if (diag) {
                if (c0 > r0) sa[j][0] = -1e30f;
                if (c1 > r0) sa[j][1] = -1e30f;
                if (c0 > r1) sa[j][2] = -1e30f;
                if (c1 > r1) sa[j][3] = -1e30f;
            }
        }

        // ---- online softmax ----
        float tm0 = -1e30f, tm1 = -1e30f;
        #pragma unroll
        for (int j = 0; j < 8; j++) {
            tm0 = fmaxf(tm0, fmaxf(sa[j][0], sa[j][1]));
            tm1 = fmaxf(tm1, fmaxf(sa[j][2], sa[j][3]));
        }
        tm0 = fmaxf(tm0, __shfl_xor_sync(0xffffffffu, tm0, 1));
        tm0 = fmaxf(tm0, __shfl_xor_sync(0xffffffffu, tm0, 2));
        tm1 = fmaxf(tm1, __shfl_xor_sync(0xffffffffu, tm1, 1));
        tm1 = fmaxf(tm1, __shfl_xor_sync(0xffffffffu, tm1, 2));
        float m0n = fmaxf(m0, tm0), m1n = fmaxf(m1, tm1);
        float a0 = __expf(m0 - m0n), a1 = __expf(m1 - m1n);
        float ps0 = 0.f, ps1 = 0.f;
        #pragma unroll
        for (int j = 0; j < 8; j++) {
            sa[j][0] = __expf(sa[j][0] - m0n); sa[j][1] = __expf(sa[j][1] - m0n);
            sa[j][2] = __expf(sa[j][2] - m1n); sa[j][3] = __expf(sa[j][3] - m1n);
            ps0 += sa[j][0] + sa[j][1];
            ps1 += sa[j][2] + sa[j][3];
        }
        ps0 += __shfl_xor_sync(0xffffffffu, ps0, 1);
        ps0 += __shfl_xor_sync(0xffffffffu, ps0, 2);
        ps1 += __shfl_xor_sync(0xffffffffu, ps1, 1);
        ps1 += __shfl_xor_sync(0xffffffffu, ps1, 2);
        l0 = l0 * a0 + ps0; l1 = l1 * a1 + ps1;
        m0 = m0n; m1 = m1n;
        #pragma unroll
        for (int j = 0; j < 16; j++) {
            oa[j][0] *= a0; oa[j][1] *= a0;
            oa[j][2] *= a1; oa[j][3] *= a1;
        }
        #pragma unroll
        for (int j = 0; j < 8; j++) {
            pw[(wrow + g    ) * APW + j * 4 + t4] = packh2(sa[j][0], sa[j][1]);
            pw[(wrow + 8 + g) * APW + j * 4 + t4] = packh2(sa[j][2], sa[j][3]);
        }
        __syncwarp();

        // ---- wait V, then O += P @ V ----
        if (havenext) { asm volatile("cp.async.wait_group 1;\n"); }
        else          { asm volatile("cp.async.wait_group 0;\n"); }
        __syncthreads();
        #pragma unroll
        for (int kc = 0; kc < 4; kc++) {
            const int kw0 = kc * 8;
            uint32_t af[4], bf[16][2];
            af[0] = pw[(wrow + g    ) * APW + kw0 + t4];
            af[1] = pw[(wrow + 8 + g) * APW + kw0 + t4];
            af[2] = pw[(wrow + g    ) * APW + kw0 + 4 + t4];
            af[3] = pw[(wrow + 8 + g) * APW + kw0 + 4 + t4];
            #pragma unroll
            for (int j = 0; j < 16; j++) {
                bf[j][0] = vst[(j * 8 + g) * AVW + kw0 + t4];
                bf[j][1] = vst[(j * 8 + g) * AVW + kw0 + 4 + t4];
            }
            #pragma unroll
            for (int j = 0; j < 16; j++) mma_fp16(oa[j], af, bf[j]);
        }
        __syncthreads();   // all warps done with V before next tile's load_v
    }

    float i0 = 1.f / l0, i1 = 1.f / l1;
    const int r0 = qbase + wrow + g;
    __half* o0 = out + (size_t)r0 * H_ + h * VHD_;
    __half* o1 = out + (size_t)(r0 + 8) * H_ + h * VHD_;
    #pragma unroll
    for (int j = 0; j < 16; j++) {
        int cc = j * 8 + 2 * t4;
        o0[cc]     = __float2half(oa[j][0] * i0);
        o0[cc + 1] = __float2half(oa[j][1] * i0);
        o1[cc]     = __float2half(oa[j][2] * i1);
        o1[cc + 1] = __float2half(oa[j][3] * i1);
    }
}

// ---------------- launcher ----------------
extern "C" void kernel_launch(void* const* d_in, const int* in_sizes, int n_in,
                              void* d_out, int out_size) {
    const float* hidden  = (const float*)d_in[0];
    const float* sinb    = (const float*)d_in[1];
    const float* cosb    = (const float*)d_in[2];
    const float* wq_a    = (const float*)d_in[3];
    const float* q_a_ln  = (const float*)d_in[4];
    const float* wq_b    = (const float*)d_in[5];
    const float* wkv_a   = (const float*)d_in[6];
    const float* kv_a_ln = (const float*)d_in[7];
    const float* wkv_b   = (const float*)d_in[8];
    const float* wo      = (const float*)d_in[9];
    const float* in_ln   = (const float*)d_in[10];
    const float* post_ln = (const float*)d_in[11];
    const float* w_gate  = (const float*)d_in[12];
    const float* w_up    = (const float*)d_in[13];
    const float* w_down  = (const float*)d_in[14];
    const int*   pos     = (const int*)d_in[15];
    float* outp = (float*)d_out;

    float *comb1, *hid2;
    __half *q16, *kv16, *kpe16, *xnorm16, *qlat16, *kvn16, *attn16, *ynorm16, *gate16;
    uint32_t *vt, *wqakva16, *wqb16, *wkvb16, *wo16, *wgu16, *wd16;
    cudaGetSymbolAddress((void**)&comb1, g_comb1);
    cudaGetSymbolAddress((void**)&hid2,  g_hid2);
    cudaGetSymbolAddress((void**)&q16,   g_q16);
    cudaGetSymbolAddress((void**)&kv16,  g_kv16);
    cudaGetSymbolAddress((void**)&kpe16, g_kpe16);
    cudaGetSymbolAddress((void**)&vt,    g_vt);
    cudaGetSymbolAddress((void**)&xnorm16, g_xnorm16);
    cudaGetSymbolAddress((void**)&qlat16,  g_qlat16);
    cudaGetSymbolAddress((void**)&kvn16,   g_kvn16);
    cudaGetSymbolAddress((void**)&attn16,  g_attn16);
    cudaGetSymbolAddress((void**)&ynorm16, g_ynorm16);
    cudaGetSymbolAddress((void**)&gate16,  g_gate16);
    cudaGetSymbolAddress((void**)&wqakva16, g_wqakva16);
    cudaGetSymbolAddress((void**)&wqb16,    g_wqb16);
    cudaGetSymbolAddress((void**)&wkvb16,   g_wkvb16);
    cudaGetSymbolAddress((void**)&wo16,     g_wo16);
    cudaGetSymbolAddress((void**)&wgu16,    g_wgu16);
    cudaGetSymbolAddress((void**)&wd16,     g_wd16);

    const size_t attn_smem = ATT_SMEM_WORDS * sizeof(uint32_t);
    cudaFuncSetAttribute(attn_mma_kernel, cudaFuncAttributeMaxDynamicSharedMemorySize, (int)attn_smem);
    cudaFuncSetAttribute((gemm_fp16<float, false>),  cudaFuncAttributeMaxDynamicSharedMemorySize, GEMMF_SMEM);
    cudaFuncSetAttribute((gemm_fp16<__half, false>), cudaFuncAttributeMaxDynamicSharedMemorySize, GEMMF_SMEM);
    cudaFuncSetAttribute((gemm_fp16<__half, true>),  cudaFuncAttributeMaxDynamicSharedMemorySize, GEMMF_SMEM);

    // 0) convert weights (pair-interleaved; gate/up column-interleaved)
    auto cvt = [&](const float* w, uint32_t* o, int K, int Nsrc, int dstStride,
                   int colOff, int colStride) {
        int n = (K / 2) * Nsrc;
        cvt_pair_kernel<<<(n + 255) / 256, 256>>>(w, o, K / 2, Nsrc, dstStride, colOff, colStride);
    };
    cvt(wq_a,   wqakva16, H_,    QLR_,   NC1_,   0,    1);
    cvt(wkv_a,  wqakva16, H_,    CKVD_,  NC1_,   QLR_, 1);
    cvt(wq_b,   wqb16,    QLR_,  QDIM_,  QDIM_,  0,    1);
    cvt(wkv_b,  wkvb16,   KVLR_, KVDIM_, KVDIM_, 0,    1);
    cvt(wo,     wo16,     H_,    H_,     H_,     0,    1);
    cvt(w_gate, wgu16,    H_,    FF_,    NC2_,   0,    2);   // even cols
    cvt(w_up,   wgu16,    H_,    FF_,    NC2_,   1,    2);   // odd cols
    cvt(w_down, wd16,     FF_,   H_,     H_,     0,    1);

    dim3 blk256(256);
    auto gemm = [&](const __half* A, const uint32_t* Bw, const float* Cadd, float* C,
                    int M, int N, int K) {
        gemm_fp16<float, false><<<dim3(N / 128, M / 128), blk256, GEMMF_SMEM>>>(A, Bw, Cadd, C, M, N, K);
    };
    auto gemm_h = [&](const __half* A, const uint32_t* Bw, __half* C,
                      int M, int N, int K) {
        gemm_fp16<__half, false><<<dim3(N / 128, M / 128), blk256, GEMMF_SMEM>>>(A, Bw, nullptr, C, M, N, K);
    };

    // 1) xnorm16 = rms(hidden, in_ln)
    rms_kernel<<<S_, 256>>>(hidden, in_ln, xnorm16, H_, H_, H_);
    // 2+5) comb1 = xnorm16 @ [wq_a | wkv_a]
    gemm(xnorm16, wqakva16, nullptr, comb1, S_, NC1_, H_);
    // 3) qlat16 = rms(comb1[:, :1536], q_a_ln)
    rms_kernel<<<S_, 256>>>(comb1, q_a_ln, qlat16, QLR_, NC1_, QLR_);
    // 6) kvn16 = rms(comb1[:, 1536:2048], kv_a_ln)
    rms_kernel<<<S_, 256>>>(comb1 + QLR_, kv_a_ln, kvn16, KVLR_, NC1_, KVLR_);
    // 4) q16 = qlat16 @ wq_b   (fp16 out; rope in place)
    gemm_h(qlat16, wqb16, q16, S_, QDIM_, QLR_);
    // 7) kv16 = kvn16 @ wkv_b  (fp16 out)
    gemm_h(kvn16, wkvb16, kv16, S_, KVDIM_, KVLR_);
    // 7b) V transpose pre-pass
    vtr_kernel<<<dim3(S_/64, NH_), 128>>>(kv16, vt);
    // 8) RoPE (q16 in place; kpe16 out)
    rope_kernel<<<S_, 128>>>(q16, comb1 + QLR_, NC1_, kpe16, cosb, sinb, pos);
    // 9) attention (pipelined fp16)
    attn_mma_kernel<<<dim3(S_/64, NH_), 128, attn_smem>>>(q16, kv16, vt, kpe16, attn16);
    // 10) hid2 = hidden + attn16 @ wo
    gemm(attn16, wo16, hidden, hid2, S_, H_, H_);
    // 11) ynorm16 = rms(hid2, post_ln)
    rms_kernel<<<S_, 256>>>(hid2, post_ln, ynorm16, H_, H_, H_);
    // 12+13+14) gate16 = silu(ynorm16 @ w_gate) * (ynorm16 @ w_up)   [fused epilogue]
    gemm_fp16<__half, true><<<dim3(NC2_/128, S_/128), blk256, GEMMF_SMEM>>>(
        ynorm16, wgu16, nullptr, gate16, S_, NC2_, H_);
    // 15) out = hid2 + gate16 @ w_down
    gemm(gate16, wd16, hid2, outp, S_, H_, FF_);
}

// round 16
// speedup vs baseline: 2.0901x; 1.0533x over previous
#include <cuda_runtime.h>
#include <cuda_fp16.h>
#include <cuda_bf16.h>
#include <cstdint>
#include <math.h>

// ---------------- problem constants ----------------
#define S_   2048
#define H_   2048
#define NH_  16
#define NOPE_ 128
#define ROPE_ 64
#define QHD_ 192     // NOPE+ROPE
#define VHD_ 128
#define QLR_ 1536
#define KVLR_ 512
#define FF_  8192
#define CKVD_ (KVLR_ + ROPE_)   // 576
#define QDIM_ (NH_*QHD_)        // 3072
#define KVDIM_ (NH_*(NOPE_+VHD_)) // 4096
#define SCALE_ 0.07216878364870323f      // 192^-0.5
#define SCALEL2_ 0.10412921980692487f    // SCALE_ * log2(e)

#define NC1_ 2176      // combined wq_a(1536) + wkv_a(576) + pad(64)
#define NC2_ 16384     // interleaved gate/up: even col=gate, odd col=up

// ---------------- scratch (static device globals; no runtime alloc) ----------------
__device__ float  g_hid2  [S_*H_];

__device__ __half g_comb1 [S_*NC1_];    // [:,0:1536]=q_lat, [:,1536:2112]=ckv (fp16)
__device__ __half g_q16   [S_*QDIM_];
__device__ __half g_kv16  [S_*KVDIM_];
__device__ __half g_kpe16 [S_*ROPE_];
__device__ uint32_t g_vt  [NH_*VHD_*(S_/2)];   // V transposed pair-words [h][vd][S/2]

__device__ __half g_xnorm16 [S_*H_];
__device__ __half g_qlat16  [S_*QLR_];
__device__ __half g_kvn16   [S_*KVLR_];
__device__ __half g_attn16  [S_*H_];
__device__ __half g_ynorm16 [S_*H_];
__device__ __half g_gate16  [S_*FF_];

// fp16 weights, k-pair-interleaved: word (p,n) = (w[2p][n], w[2p+1][n])
__device__ uint32_t g_wqakva16 [(H_/2)*NC1_];   // pad cols [2112:2176) stay zero
__device__ uint32_t g_wqb16    [(QLR_/2)*QDIM_];
__device__ uint32_t g_wkvb16   [(KVLR_/2)*KVDIM_];
__device__ uint32_t g_wo16     [(H_/2)*H_];
__device__ uint32_t g_wgu16    [(H_/2)*NC2_];   // column-interleaved gate/up
__device__ uint32_t g_wd16     [(FF_/2)*H_];

// ---------------- helpers ----------------
__device__ __forceinline__ float warp_sum(float v) {
    #pragma unroll
    for (int o = 16; o; o >>= 1) v += __shfl_xor_sync(0xffffffffu, v, o);
    return v;
}

__device__ __forceinline__ void mma_fp16(float* d, const uint32_t* a, const uint32_t* b) {
    asm volatile(
        "mma.sync.aligned.m16n8k16.row.col.f32.f16.f16.f32 "
        "{%0,%1,%2,%3}, {%4,%5,%6,%7}, {%8,%9}, {%0,%1,%2,%3};"
        : "+f"(d[0]), "+f"(d[1]), "+f"(d[2]), "+f"(d[3])
        : "r"(a[0]), "r"(a[1]), "r"(a[2]), "r"(a[3]), "r"(b[0]), "r"(b[1]));
}

__device__ __forceinline__ uint32_t packh2(float lo, float hi) {
    __half2 h = __floats2half2_rn(lo, hi);
    return *(uint32_t*)&h;
}

__device__ __forceinline__ float ld_f(const float* p)  { return *p; }
__device__ __forceinline__ float ld_f(const __half* p) { return __half2float(*p); }

// ---------------- vectorized weight convert: fp32 [K][Nsrc] -> pair words ----------
__global__ void cvt_pair_v4(const float* __restrict__ w, uint32_t* __restrict__ o,
                            int K2, int N4, int Nsrc, int dstStride, int colOff) {
    int idx = blockIdx.x * blockDim.x + threadIdx.x;
    if (idx < K2 * N4) {
        int p = idx / N4, n = (idx - p * N4) * 4;
        float4 a = *(const float4*)&w[(size_t)(2 * p) * Nsrc + n];
        float4 b = *(const float4*)&w[(size_t)(2 * p + 1) * Nsrc + n];
        uint4 r = { packh2(a.x, b.x), packh2(a.y, b.y), packh2(a.z, b.z), packh2(a.w, b.w) };
        *(uint4*)&o[(size_t)p * dstStride + colOff + n] = r;
    }
}

// gate/up fused convert: contiguous uint4 writes into the interleaved layout
__global__ void cvt_gu_kernel(const float* __restrict__ wg, const float* __restrict__ wu,
                              uint32_t* __restrict__ o) {
    int idx = blockIdx.x * blockDim.x + threadIdx.x;     // over (H/2) * (FF/2)
    if (idx < (H_ / 2) * (FF_ / 2)) {
        int p = idx / (FF_ / 2), n = (idx - p * (FF_ / 2)) * 2;
        float2 g0 = *(const float2*)&wg[(size_t)(2 * p) * FF_ + n];
        float2 g1 = *(const float2*)&wg[(size_t)(2 * p + 1) * FF_ + n];
        float2 u0 = *(const float2*)&wu[(size_t)(2 * p) * FF_ + n];
        float2 u1 = *(const float2*)&wu[(size_t)(2 * p + 1) * FF_ + n];
        uint4 r = { packh2(g0.x, g1.x), packh2(u0.x, u1.x),
                    packh2(g0.y, g1.y), packh2(u0.y, u1.y) };
        *(uint4*)&o[(size_t)p * NC2_ + 2 * n] = r;
    }
}

// ---------------- rmsnorm: one block per row, fp16 output, templated input ----------
template<typename IT>
__global__ void rms_kernel(const IT* __restrict__ in, const float* __restrict__ w,
                           __half* __restrict__ out, int dim, int istride, int ostride) {
    int row = blockIdx.x;
    const IT* x = in + (size_t)row * istride;
    __half* y = out + (size_t)row * ostride;
    float s = 0.f;
    for (int i = threadIdx.x; i < dim; i += blockDim.x) { float v = ld_f(x + i); s += v * v; }
    __shared__ float red[8];
    int lane = threadIdx.x & 31, wid = threadIdx.x >> 5;
    s = warp_sum(s);
    if (lane == 0) red[wid] = s;
    __syncthreads();
    if (wid == 0) {
        float r = (lane < (int)(blockDim.x >> 5)) ? red[lane] : 0.f;
        r = warp_sum(r);
        if (lane == 0) red[0] = r;
    }
    __syncthreads();
    float inv = rsqrtf(red[0] / (float)dim + 1e-6f);
    for (int i = threadIdx.x; i < dim; i += blockDim.x)
        y[i] = __float2half(ld_f(x + i) * inv * w[i]);
}

// ---------------- V transpose pre-pass: kv16 V-part -> vt[h][vd][S/2] pair words ----
__global__ void vtr_kernel(const __half* __restrict__ kv16, uint32_t* __restrict__ vt) {
    __shared__ __half sm[64 * 130];
    int h = blockIdx.y, kb = blockIdx.x * 64;
    int t = threadIdx.x;
    for (int idx = t; idx < 64 * 64; idx += 128) {
        int row = idx >> 6, w = idx & 63;
        *(uint32_t*)&sm[row * 130 + 2 * w] =
            *(const uint32_t*)(kv16 + (size_t)(kb + row) * KVDIM_ + h * 256 + 128 + 2 * w);
    }
    __syncthreads();
    for (int idx = t; idx < 128 * 32; idx += 128) {
        int vd = idx >> 5, p = idx & 31;
        __half2 hh = __halves2half2(sm[(2 * p) * 130 + vd], sm[(2 * p + 1) * 130 + vd]);
        vt[((size_t)(h * 128 + vd) << 10) + blockIdx.x * 32 + p] = *(uint32_t*)&hh;
    }
}

// ---------------- fp16 tensor-core GEMM: C = A@B (+ Cadd), fp32 accumulate --------
#define AP16 20
#define BP16 136
#define GSTAGE (128*AP16 + 16*BP16)

template<typename CT, bool SILU>
__global__ __launch_bounds__(256, 2) void gemm_fp16(
        const __half* __restrict__ A, const uint32_t* __restrict__ Bw,
        const float* __restrict__ Cadd, CT* __restrict__ C,
        int M, int N, int K) {
    extern __shared__ uint32_t smw[];
    const int t = threadIdx.x;
    const int warp = t >> 5, lane = t & 31;
    const int wm = warp >> 1, wn = warp & 1;
    const int g = lane >> 2, t4 = lane & 3;
    const int m0 = blockIdx.y * 128, n0 = blockIdx.x * 128;

    float acc[2][8][4] = {};

    auto load_stage = [&](int st, int kt) {
        uint32_t* as = smw + st * GSTAGE;
        uint32_t* bs = as + 128 * AP16;
        #pragma unroll
        for (int i = 0; i < 2; i++) {
            int id = t + i * 256;
            int row = id >> 2, c = id & 3;
            uint32_t dst = (uint32_t)__cvta_generic_to_shared(as + row * AP16 + c * 4);
            const __half* src = A + (size_t)(m0 + row) * K + kt * 32 + c * 8;
            asm volatile("cp.async.cg.shared.global [%0], [%1], 16;\n" :: "r"(dst), "l"(src));
        }
        #pragma unroll
        for (int i = 0; i < 2; i++) {
            int id = t + i * 256;
            int prow = id >> 5, c = id & 31;
            uint32_t dst = (uint32_t)__cvta_generic_to_shared(bs + prow * BP16 + c * 4);
            const uint32_t* src = Bw + (size_t)(kt * 16 + prow) * N + n0 + c * 4;
            asm volatile("cp.async.cg.shared.global [%0], [%1], 16;\n" :: "r"(dst), "l"(src));
        }
        asm volatile("cp.async.commit_group;\n");
    };

    auto compute = [&](int st) {
        const uint32_t* as = smw + st * GSTAGE;
        const uint32_t* bs = as + 128 * AP16;
        #pragma unroll
        for (int kc = 0; kc < 2; kc++) {
            const int kw = kc * 8;
            uint32_t af[2][4], bf[8][2];
            #pragma unroll
            for (int i = 0; i < 2; i++) {
                int rbase = wm * 32 + i * 16;
                af[i][0] = as[(rbase + g    ) * AP16 + kw + t4];
                af[i][1] = as[(rbase + 8 + g) * AP16 + kw + t4];
                af[i][2] = as[(rbase + g    ) * AP16 + kw + 4 + t4];
                af[i][3] = as[(rbase + 8 + g) * AP16 + kw + 4 + t4];
            }
            #pragma unroll
            for (int j = 0; j < 8; j++) {
                int cbase = wn * 64 + j * 8 + g;
                bf[j][0] = bs[(kw + t4    ) * BP16 + cbase];
                bf[j][1] = bs[(kw + 4 + t4) * BP16 + cbase];
            }
            #pragma unroll
            for (int i = 0; i < 2; i++)
                #pragma unroll
                for (int j = 0; j < 8; j++)
                    mma_fp16(acc[i][j], af[i], bf[j]);
        }
    };

    const int nk = K / 32;
    load_stage(0, 0);
    if (nk > 1) load_stage(1, 1);

    for (int kt = 0; kt < nk; kt++) {
        if (kt + 1 < nk) { asm volatile("cp.async.wait_group 1;\n"); }
        else             { asm volatile("cp.async.wait_group 0;\n"); }
        __syncthreads();
        if (kt + 2 < nk) load_stage((kt + 2) % 3, kt + 2);
        compute(kt % 3);
    }

    #pragma unroll
    for (int i = 0; i < 2; i++) {
        int r0 = m0 + wm * 32 + i * 16 + g;
        #pragma unroll
        for (int j = 0; j < 8; j++) {
            int cc = n0 + wn * 64 + j * 8 + 2 * t4;   // always even
            float v0 = acc[i][j][0], v1 = acc[i][j][1];
            float v2 = acc[i][j][2], v3 = acc[i][j][3];
            if constexpr (SILU) {
                float sg0 = v0 / (1.f + __expf(-v0));
                float sg2 = v2 / (1.f + __expf(-v2));
                C[(size_t)r0 * (N >> 1) + (cc >> 1)]       = (CT)__float2half(sg0 * v1);
                C[(size_t)(r0 + 8) * (N >> 1) + (cc >> 1)] = (CT)__float2half(sg2 * v3);
            } else {
                size_t o0 = (size_t)r0 * N + cc;
                size_t o1 = (size_t)(r0 + 8) * N + cc;
                if (Cadd) { v0 += Cadd[o0]; v1 += Cadd[o0 + 1]; v2 += Cadd[o1]; v3 += Cadd[o1 + 1]; }
                if constexpr (sizeof(CT) == 4) {
                    C[o0] = v0; C[o0 + 1] = v1; C[o1] = v2; C[o1 + 1] = v3;
                } else {
                    *(uint32_t*)&C[o0] = packh2(v0, v1);
                    *(uint32_t*)&C[o1] = packh2(v2, v3);
                }
            }
        }
    }
}

#define GEMMF_SMEM (3 * GSTAGE * 4)

// ---------------- RoPE on fp16 q (in place) + fp16 kpe out (fp16 ckv source) -------
__global__ void rope_kernel(__half* __restrict__ q16, const __half* __restrict__ ckv_base,
                            int ckv_stride, __half* __restrict__ kpe16,
                            const float* __restrict__ cosb, const float* __restrict__ sinb,
                            const int* __restrict__ pos_ids) {
    int s = blockIdx.x;
    int pos = pos_ids[s];
    const float* c  = cosb + (size_t)pos * ROPE_;
    const float* sn = sinb + (size_t)pos * ROPE_;
    int t = threadIdx.x;
    float ox[4], oy[4];
    #pragma unroll
    for (int it = 0; it < 4; it++) {
        int item = t + it * 128;
        int h = item >> 5, i = item & 31;
        __half* base = q16 + (size_t)s * QDIM_ + h * QHD_ + NOPE_;
        float x0 = __half2float(base[2 * i]), x1 = __half2float(base[2 * i + 1]);
        ox[it] = x0 * c[i]      - x1 * sn[i];
        oy[it] = x1 * c[i + 32] + x0 * sn[i + 32];
    }
    __syncthreads();
    #pragma unroll
    for (int it = 0; it < 4; it++) {
        int item = t + it * 128;
        int h = item >> 5, i = item & 31;
        __half* base = q16 + (size_t)s * QDIM_ + h * QHD_ + NOPE_;
        base[i]      = __float2half(ox[it]);
        base[i + 32] = __float2half(oy[it]);
    }
    if (t < 32) {
        const __half* kb = ckv_base + (size_t)s * ckv_stride + KVLR_;
        float x0 = __half2float(kb[2 * t]), x1 = __half2float(kb[2 * t + 1]);
        kpe16[(size_t)s * ROPE_ + t]      = __float2half(x0 * c[t]      - x1 * sn[t]);
        kpe16[(size_t)s * ROPE_ + 32 + t] = __float2half(x1 * c[t + 32] + x0 * sn[t + 32]);
    }
}

// ---------------- fp16 flash attention, cp.async pipelined, log2-domain softmax ----
#define AQW 100
#define AKW 100
#define AVW 36
#define APW 36
#define ATT_SMEM_WORDS (64*AQW + 2*64*AKW + 128*AVW + 64*APW)   // 104448 B

__global__ __launch_bounds__(128, 2) void attn_mma_kernel(
        const __half* __restrict__ q16, const __half* __restrict__ kv16,
        const uint32_t* __restrict__ vt, const __half* __restrict__ kpe16,
        __half* __restrict__ out) {
    extern __shared__ uint32_t smw[];
    uint32_t* qw  = smw;                     // [64][AQW]
    uint32_t* kst = qw + 64 * AQW;           // 2 x [64][AKW]
    uint32_t* vst = kst + 2 * 64 * AKW;      // [128][AVW]
    uint32_t* pw  = vst + 128 * AVW;         // [64][APW]

    const int h = blockIdx.y;
    const int qblk = (int)gridDim.x - 1 - (int)blockIdx.x;   // heavy blocks first
    const int t = threadIdx.x;
    const int warp = t >> 5, lane = t & 31;
    const int g = lane >> 2, t4 = lane & 3;
    const int qbase = qblk * 64;
    const int wrow = warp * 16;

    auto load_k = [&](int kt, int st) {
        uint32_t* ks = kst + st * 64 * AKW;
        const int kbase = kt * 64;
        for (int idx = t; idx < 64 * 24; idx += 128) {
            int row = idx / 24, c = idx - row * 24;
            uint32_t dst;
            const __half* src;
            if (c < 16) {
                dst = (uint32_t)__cvta_generic_to_shared(ks + row * AKW + c * 4);
                src = kv16 + (size_t)(kbase + row) * KVDIM_ + h * 256 + c * 8;
            } else {
                dst = (uint32_t)__cvta_generic_to_shared(ks + row * AKW + 64 + (c - 16) * 4);
                src = kpe16 + (size_t)(kbase + row) * ROPE_ + (c - 16) * 8;
            }
            asm volatile("cp.async.cg.shared.global [%0], [%1], 16;\n" :: "r"(dst), "l"(src));
        }
        asm volatile("cp.async.commit_group;\n");
    };
    auto load_v = [&](int kt) {
        const uint32_t* base = vt + ((size_t)(h * 128) << 10) + kt * 32;
        for (int idx = t; idx < 128 * 8; idx += 128) {
            int vd = idx >> 3, c = idx & 7;
            uint32_t dst = (uint32_t)__cvta_generic_to_shared(vst + vd * AVW + c * 4);
            const uint32_t* src = base + ((size_t)vd << 10) + c * 4;
            asm volatile("cp.async.cg.shared.global [%0], [%1], 16;\n" :: "r"(dst), "l"(src));
        }
        asm volatile("cp.async.commit_group;\n");
    };

    // K(0) and Q in flight together
    load_k(0, 0);
    for (int idx = t; idx < 64 * 24; idx += 128) {
        int row = idx / 24, c = idx - row * 24;
        uint32_t dst = (uint32_t)__cvta_generic_to_shared(qw + row * AQW + c * 4);
        const __half* src = q16 + (size_t)(qbase + row) * QDIM_ + h * QHD_ + c * 8;
        asm volatile("cp.async.cg.shared.global [%0], [%1], 16;\n" :: "r"(dst), "l"(src));
    }
    asm volatile("cp.async.commit_group;\n");

    float oa[16][4];
    #pragma unroll
    for (int j = 0; j < 16; j++)
        #pragma unroll
        for (int c = 0; c < 4; c++) oa[j][c] = 0.f;
    float m0 = -1e30f, m1 = -1e30f, l0 = 0.f, l1 = 0.f;

    for (int kt = 0; kt <= qblk; kt++) {
        const int kbase = kt * 64;
        const bool havenext = (kt + 1 <= qblk);
        asm volatile("cp.async.wait_group 0;\n");   // K(kt) (+Q at kt=0) arrived
        __syncthreads();
        load_v(kt);                                 // overlaps S compute
        if (havenext) load_k(kt + 1, (kt + 1) & 1);

        // ---- S = Q @ K^T ----
        const uint32_t* ks = kst + (kt & 1) * 64 * AKW;
        float sa[8][4];
        #pragma unroll
        for (int j = 0; j < 8; j++)
            #pragma unroll
            for (int c = 0; c < 4; c++) sa[j][c] = 0.f;
        #pragma unroll
        for (int kc = 0; kc < 12; kc++) {
            const int kw0 = kc * 8;
            uint32_t af[4], bf[8][2];
            af[0] = qw[(wrow + g    ) * AQW + kw0 + t4];
            af[1] = qw[(wrow + 8 + g) * AQW + kw0 + t4];
            af[2] = qw[(wrow + g    ) * AQW + kw0 + 4 + t4];
            af[3] = qw[(wrow + 8 + g) * AQW + kw0 + 4 + t4];
            #pragma unroll
            for (int j = 0; j < 8; j++) {
                bf[j][0] = ks[(j * 8 + g) * AKW + kw0 + t4];
                bf[j][1] = ks[(j * 8 + g) * AKW + kw0 + 4 + t4];
            }
            #pragma unroll
            for (int j = 0; j < 8; j++) mma_fp16(sa[j], af, bf[j]);
        }

        // ---- mask + scale (log2 domain) ----
        const int r0 = qbase + wrow + g;
        const int r1 = r0 + 8;
        const bool diag = (kt == qblk);
        #pragma unroll
        for (int j = 0; j < 8; j++) {
            int c0 = kbase + j * 8 + 2 * t4, c1 = c0 + 1;
            sa[j][0] *= SCALEL2_; sa[j][1] *= SCALEL2_;
            sa[j][2] *= SCALEL2_; sa[j][3] *= SCALEL2_;
            if (diag) {
                if (c0 > r0) sa[j][0] = -1e30f;
                if (c1 > r0) sa[j][1] = -1e30f;
                if (c0 > r1) sa[j][2] = -1e30f;
                if (c1 > r1) sa[j][3] = -1e30f;
            }
        }

        // ---- online softmax (exp2) ----
        float tm0 = -1e30f, tm1 = -1e30f;
        #pragma unroll
        for (int j = 0; j < 8; j++) {
            tm0 = fmaxf(tm0, fmaxf(sa[j][0], sa[j][1]));
            tm1 = fmaxf(tm1, fmaxf(sa[j][2], sa[j][3]));
        }
        tm0 = fmaxf(tm0, __shfl_xor_sync(0xffffffffu, tm0, 1));
        tm0 = fmaxf(tm0, __shfl_xor_sync(0xffffffffu, tm0, 2));
        tm1 = fmaxf(tm1, __shfl_xor_sync(0xffffffffu, tm1, 1));
        tm1 = fmaxf(tm1, __shfl_xor_sync(0xffffffffu, tm1, 2));
        float m0n = fmaxf(m0, tm0), m1n = fmaxf(m1, tm1);
        float a0 = exp2f(m0 - m0n), a1 = exp2f(m1 - m1n);
        float ps0 = 0.f, ps1 = 0.f;
        #pragma unroll
        for (int j = 0; j < 8; j++) {
            sa[j][0] = exp2f(sa[j][0] - m0n); sa[j][1] = exp2f(sa[j][1] - m0n);
            sa[j][2] = exp2f(sa[j][2] - m1n); sa[j][3] = exp2f(sa[j][3] - m1n);
            ps0 += sa[j][0] + sa[j][1];
            ps1 += sa[j][2] + sa[j][3];
        }
        ps0 += __shfl_xor_sync(0xffffffffu, ps0, 1);
        ps0 += __shfl_xor_sync(0xffffffffu, ps0, 2);
        ps1 += __shfl_xor_sync(0xffffffffu, ps1, 1);
        ps1 += __shfl_xor_sync(0xffffffffu, ps1, 2);
        l0 = l0 * a0 + ps0; l1 = l1 * a1 + ps1;
        m0 = m0n; m1 = m1n;
        #pragma unroll
        for (int j = 0; j < 16; j++) {
            oa[j][0] *= a0; oa[j][1] *= a0;
            oa[j][2] *= a1; oa[j][3] *= a1;
        }
        #pragma unroll
        for (int j = 0; j < 8; j++) {
            pw[(wrow + g    ) * APW + j * 4 + t4] = packh2(sa[j][0], sa[j][1]);
            pw[(wrow + 8 + g) * APW + j * 4 + t4] = packh2(sa[j][2], sa[j][3]);
        }
        __syncwarp();

        // ---- wait V, then O += P @ V ----
        if (havenext) { asm volatile("cp.async.wait_group 1;\n"); }
        else          { asm volatile("cp.async.wait_group 0;\n"); }
        __syncthreads();
        #pragma unroll
        for (int kc = 0; kc < 4; kc++) {
            const int kw0 = kc * 8;
            uint32_t af[4], bf[16][2];
            af[0] = pw[(wrow + g    ) * APW + kw0 + t4];
            af[1] = pw[(wrow + 8 + g) * APW + kw0 + t4];
            af[2] = pw[(wrow + g    ) * APW + kw0 + 4 + t4];
            af[3] = pw[(wrow + 8 + g) * APW + kw0 + 4 + t4];
            #pragma unroll
            for (int j = 0; j < 16; j++) {
                bf[j][0] = vst[(j * 8 + g) * AVW + kw0 + t4];
                bf[j][1] = vst[(j * 8 + g) * AVW + kw0 + 4 + t4];
            }
            #pragma unroll
            for (int j = 0; j < 16; j++) mma_fp16(oa[j], af, bf[j]);
        }
        __syncthreads();   // all warps done with V before next tile's load_v
    }

    float i0 = 1.f / l0, i1 = 1.f / l1;
    const int r0 = qbase + wrow + g;
    __half* o0 = out + (size_t)r0 * H_ + h * VHD_;
    __half* o1 = out + (size_t)(r0 + 8) * H_ + h * VHD_;
    #pragma unroll
    for (int j = 0; j < 16; j++) {
        int cc = j * 8 + 2 * t4;
        o0[cc]     = __float2half(oa[j][0] * i0);
        o0[cc + 1] = __float2half(oa[j][1] * i0);
        o1[cc]     = __float2half(oa[j][2] * i1);
        o1[cc + 1] = __float2half(oa[j][3] * i1);
    }
}

// ---------------- launcher ----------------
extern "C" void kernel_launch(void* const* d_in, const int* in_sizes, int n_in,
                              void* d_out, int out_size) {
    const float* hidden  = (const float*)d_in[0];
    const float* sinb    = (const float*)d_in[1];
    const float* cosb    = (const float*)d_in[2];
    const float* wq_a    = (const float*)d_in[3];
    const float* q_a_ln  = (const float*)d_in[4];
    const float* wq_b    = (const float*)d_in[5];
    const float* wkv_a   = (const float*)d_in[6];
    const float* kv_a_ln = (const float*)d_in[7];
    const float* wkv_b   = (const float*)d_in[8];
    const float* wo      = (const float*)d_in[9];
    const float* in_ln   = (const float*)d_in[10];
    const float* post_ln = (const float*)d_in[11];
    const float* w_gate  = (const float*)d_in[12];
    const float* w_up    = (const float*)d_in[13];
    const float* w_down  = (const float*)d_in[14];
    const int*   pos     = (const int*)d_in[15];
    float* outp = (float*)d_out;

    float *hid2;
    __half *comb1, *q16, *kv16, *kpe16, *xnorm16, *qlat16, *kvn16, *attn16, *ynorm16, *gate16;
    uint32_t *vt, *wqakva16, *wqb16, *wkvb16, *wo16, *wgu16, *wd16;
    cudaGetSymbolAddress((void**)&hid2,  g_hid2);
    cudaGetSymbolAddress((void**)&comb1, g_comb1);
    cudaGetSymbolAddress((void**)&q16,   g_q16);
    cudaGetSymbolAddress((void**)&kv16,  g_kv16);
    cudaGetSymbolAddress((void**)&kpe16, g_kpe16);
    cudaGetSymbolAddress((void**)&vt,    g_vt);
    cudaGetSymbolAddress((void**)&xnorm16, g_xnorm16);
    cudaGetSymbolAddress((void**)&qlat16,  g_qlat16);
    cudaGetSymbolAddress((void**)&kvn16,   g_kvn16);
    cudaGetSymbolAddress((void**)&attn16,  g_attn16);
    cudaGetSymbolAddress((void**)&ynorm16, g_ynorm16);
    cudaGetSymbolAddress((void**)&gate16,  g_gate16);
    cudaGetSymbolAddress((void**)&wqakva16, g_wqakva16);
    cudaGetSymbolAddress((void**)&wqb16,    g_wqb16);
    cudaGetSymbolAddress((void**)&wkvb16,   g_wkvb16);
    cudaGetSymbolAddress((void**)&wo16,     g_wo16);
    cudaGetSymbolAddress((void**)&wgu16,    g_wgu16);
    cudaGetSymbolAddress((void**)&wd16,     g_wd16);

    const size_t attn_smem = ATT_SMEM_WORDS * sizeof(uint32_t);
    cudaFuncSetAttribute(attn_mma_kernel, cudaFuncAttributeMaxDynamicSharedMemorySize, (int)attn_smem);
    cudaFuncSetAttribute((gemm_fp16<float, false>),  cudaFuncAttributeMaxDynamicSharedMemorySize, GEMMF_SMEM);
    cudaFuncSetAttribute((gemm_fp16<__half, false>), cudaFuncAttributeMaxDynamicSharedMemorySize, GEMMF_SMEM);
    cudaFuncSetAttribute((gemm_fp16<__half, true>),  cudaFuncAttributeMaxDynamicSharedMemorySize, GEMMF_SMEM);

    // 0) convert weights (vectorized; gate/up fused-interleaved)
    auto cvt4 = [&](const float* w, uint32_t* o, int K, int Nsrc, int dstStride, int colOff) {
        int n = (K / 2) * (Nsrc / 4);
        cvt_pair_v4<<<(n + 255) / 256, 256>>>(w, o, K / 2, Nsrc / 4, Nsrc, dstStride, colOff);
    };
    cvt4(wq_a,   wqakva16, H_,    QLR_,   NC1_,   0);
    cvt4(wkv_a,  wqakva16, H_,    CKVD_,  NC1_,   QLR_);
    cvt4(wq_b,   wqb16,    QLR_,  QDIM_,  QDIM_,  0);
    cvt4(wkv_b,  wkvb16,   KVLR_, KVDIM_, KVDIM_, 0);
    cvt4(wo,     wo16,     H_,    H_,     H_,     0);
    cvt4(w_down, wd16,     FF_,   H_,     H_,     0);
    {
        int n = (H_ / 2) * (FF_ / 2);
        cvt_gu_kernel<<<(n + 255) / 256, 256>>>(w_gate, w_up, wgu16);
    }

    dim3 blk256(256);
    auto gemm = [&](const __half* A, const uint32_t* Bw, const float* Cadd, float* C,
                    int M, int N, int K) {
        gemm_fp16<float, false><<<dim3(N / 128, M / 128), blk256, GEMMF_SMEM>>>(A, Bw, Cadd, C, M, N, K);
    };
    auto gemm_h = [&](const __half* A, const uint32_t* Bw, __half* C,
                      int M, int N, int K) {
        gemm_fp16<__half, false><<<dim3(N / 128, M / 128), blk256, GEMMF_SMEM>>>(A, Bw, nullptr, C, M, N, K);
    };

    // 1) xnorm16 = rms(hidden, in_ln)
    rms_kernel<float><<<S_, 256>>>(hidden, in_ln, xnorm16, H_, H_, H_);
    // 2+5) comb1 = xnorm16 @ [wq_a | wkv_a]   (fp16 out)
    gemm_h(xnorm16, wqakva16, comb1, S_, NC1_, H_);
    // 3) qlat16 = rms(comb1[:, :1536], q_a_ln)
    rms_kernel<__half><<<S_, 256>>>(comb1, q_a_ln, qlat16, QLR_, NC1_, QLR_);
    // 6) kvn16 = rms(comb1[:, 1536:2048], kv_a_ln)
    rms_kernel<__half><<<S_, 256>>>(comb1 + QLR_, kv_a_ln, kvn16, KVLR_, NC1_, KVLR_);
    // 4) q16 = qlat16 @ wq_b   (fp16 out; rope in place)
    gemm_h(qlat16, wqb16, q16, S_, QDIM_, QLR_);
    // 7) kv16 = kvn16 @ wkv_b  (fp16 out)
    gemm_h(kvn16, wkvb16, kv16, S_, KVDIM_, KVLR_);
    // 7b) V transpose pre-pass
    vtr_kernel<<<dim3(S_/64, NH_), 128>>>(kv16, vt);
    // 8) RoPE (q16 in place; kpe16 out)
    rope_kernel<<<S_, 128>>>(q16, comb1 + QLR_, NC1_, kpe16, cosb, sinb, pos);
    // 9) attention (pipelined fp16, exp2 softmax)
    attn_mma_kernel<<<dim3(S_/64, NH_), 128, attn_smem>>>(q16, kv16, vt, kpe16, attn16);
    // 10) hid2 = hidden + attn16 @ wo
    gemm(attn16, wo16, hidden, hid2, S_, H_, H_);
    // 11) ynorm16 = rms(hid2, post_ln)
    rms_kernel<float><<<S_, 256>>>(hid2, post_ln, ynorm16, H_, H_, H_);
    // 12+13+14) gate16 = silu(ynorm16 @ w_gate) * (ynorm16 @ w_up)   [fused epilogue]
    gemm_fp16<__half, true><<<dim3(NC2_/128, S_/128), blk256, GEMMF_SMEM>>>(
        ynorm16, wgu16, nullptr, gate16, S_, NC2_, H_);
    // 15) out = hid2 + gate16 @ w_down
    gemm(gate16, wd16, hid2, outp, S_, H_, FF_);
}

// round 17
// speedup vs baseline: 2.1150x; 1.0119x over previous
#include <cuda_runtime.h>
#include <cuda_fp16.h>
#include <cuda_bf16.h>
#include <cstdint>
#include <math.h>

// ---------------- problem constants ----------------
#define S_   2048
#define H_   2048
#define NH_  16
#define NOPE_ 128
#define ROPE_ 64
#define QHD_ 192     // NOPE+ROPE
#define VHD_ 128
#define QLR_ 1536
#define KVLR_ 512
#define FF_  8192
#define CKVD_ (KVLR_ + ROPE_)   // 576
#define QDIM_ (NH_*QHD_)        // 3072
#define KVDIM_ (NH_*(NOPE_+VHD_)) // 4096
#define SCALE_ 0.07216878364870323f      // 192^-0.5
#define SCALEL2_ 0.10412921980692487f    // SCALE_ * log2(e)

#define NC1_ 2176      // combined wq_a(1536) + wkv_a(576) + pad(64)
#define NC2_ 16384     // interleaved gate/up: even col=gate, odd col=up

// ---------------- scratch (static device globals; no runtime alloc) ----------------
__device__ float  g_hid2  [S_*H_];

__device__ __half g_comb1 [S_*NC1_];    // [:,0:1536]=q_lat, [:,1536:2112]=ckv (fp16)
__device__ __half g_q16   [S_*QDIM_];
__device__ __half g_kv16  [S_*KVDIM_];
__device__ __half g_kpe16 [S_*ROPE_];
__device__ uint32_t g_vt  [NH_*VHD_*(S_/2)];   // V transposed pair-words [h][vd][S/2]

__device__ __half g_xnorm16 [S_*H_];
__device__ __half g_qlat16  [S_*QLR_];
__device__ __half g_kvn16   [S_*KVLR_];
__device__ __half g_attn16  [S_*H_];
__device__ __half g_ynorm16 [S_*H_];
__device__ __half g_gate16  [S_*FF_];

// fp16 weights, k-pair-interleaved: word (p,n) = (w[2p][n], w[2p+1][n])
__device__ uint32_t g_wqakva16 [(H_/2)*NC1_];   // pad cols [2112:2176) stay zero
__device__ uint32_t g_wqb16    [(QLR_/2)*QDIM_];
__device__ uint32_t g_wkvb16   [(KVLR_/2)*KVDIM_];
__device__ uint32_t g_wo16     [(H_/2)*H_];
__device__ uint32_t g_wgu16    [(H_/2)*NC2_];   // column-interleaved gate/up
__device__ uint32_t g_wd16     [(FF_/2)*H_];

// ---------------- helpers ----------------
__device__ __forceinline__ float warp_sum(float v) {
    #pragma unroll
    for (int o = 16; o; o >>= 1) v += __shfl_xor_sync(0xffffffffu, v, o);
    return v;
}

__device__ __forceinline__ void mma_fp16(float* d, const uint32_t* a, const uint32_t* b) {
    asm volatile(
        "mma.sync.aligned.m16n8k16.row.col.f32.f16.f16.f32 "
        "{%0,%1,%2,%3}, {%4,%5,%6,%7}, {%8,%9}, {%0,%1,%2,%3};"
        : "+f"(d[0]), "+f"(d[1]), "+f"(d[2]), "+f"(d[3])
        : "r"(a[0]), "r"(a[1]), "r"(a[2]), "r"(a[3]), "r"(b[0]), "r"(b[1]));
}

__device__ __forceinline__ uint32_t packh2(float lo, float hi) {
    __half2 h = __floats2half2_rn(lo, hi);
    return *(uint32_t*)&h;
}

__device__ __forceinline__ float ld_f(const float* p)  { return *p; }
__device__ __forceinline__ float ld_f(const __half* p) { return __half2float(*p); }

// ---------------- vectorized weight convert: fp32 [K][Nsrc] -> pair words ----------
__global__ void cvt_pair_v4(const float* __restrict__ w, uint32_t* __restrict__ o,
                            int K2, int N4, int Nsrc, int dstStride, int colOff) {
    int idx = blockIdx.x * blockDim.x + threadIdx.x;
    if (idx < K2 * N4) {
        int p = idx / N4, n = (idx - p * N4) * 4;
        float4 a = *(const float4*)&w[(size_t)(2 * p) * Nsrc + n];
        float4 b = *(const float4*)&w[(size_t)(2 * p + 1) * Nsrc + n];
        uint4 r = { packh2(a.x, b.x), packh2(a.y, b.y), packh2(a.z, b.z), packh2(a.w, b.w) };
        *(uint4*)&o[(size_t)p * dstStride + colOff + n] = r;
    }
}

// gate/up fused convert: contiguous uint4 writes into the interleaved layout
__global__ void cvt_gu_kernel(const float* __restrict__ wg, const float* __restrict__ wu,
                              uint32_t* __restrict__ o) {
    int idx = blockIdx.x * blockDim.x + threadIdx.x;     // over (H/2) * (FF/2)
    if (idx < (H_ / 2) * (FF_ / 2)) {
        int p = idx / (FF_ / 2), n = (idx - p * (FF_ / 2)) * 2;
        float2 g0 = *(const float2*)&wg[(size_t)(2 * p) * FF_ + n];
        float2 g1 = *(const float2*)&wg[(size_t)(2 * p + 1) * FF_ + n];
        float2 u0 = *(const float2*)&wu[(size_t)(2 * p) * FF_ + n];
        float2 u1 = *(const float2*)&wu[(size_t)(2 * p + 1) * FF_ + n];
        uint4 r = { packh2(g0.x, g1.x), packh2(u0.x, u1.x),
                    packh2(g0.y, g1.y), packh2(u0.y, u1.y) };
        *(uint4*)&o[(size_t)p * NC2_ + 2 * n] = r;
    }
}

// ---------------- rmsnorm: one block per row, fp16 output, templated input ----------
template<typename IT>
__global__ void rms_kernel(const IT* __restrict__ in, const float* __restrict__ w,
                           __half* __restrict__ out, int dim, int istride, int ostride) {
    int row = blockIdx.x;
    const IT* x = in + (size_t)row * istride;
    __half* y = out + (size_t)row * ostride;
    float s = 0.f;
    for (int i = threadIdx.x; i < dim; i += blockDim.x) { float v = ld_f(x + i); s += v * v; }
    __shared__ float red[8];
    int lane = threadIdx.x & 31, wid = threadIdx.x >> 5;
    s = warp_sum(s);
    if (lane == 0) red[wid] = s;
    __syncthreads();
    if (wid == 0) {
        float r = (lane < (int)(blockDim.x >> 5)) ? red[lane] : 0.f;
        r = warp_sum(r);
        if (lane == 0) red[0] = r;
    }
    __syncthreads();
    float inv = rsqrtf(red[0] / (float)dim + 1e-6f);
    for (int i = threadIdx.x; i < dim; i += blockDim.x)
        y[i] = __float2half(ld_f(x + i) * inv * w[i]);
}

// dual rmsnorm on comb1: blockIdx.y==0 -> qlat16 (dim 1536), ==1 -> kvn16 (dim 512)
__global__ void rms_dual_kernel(const __half* __restrict__ comb1,
                                const float* __restrict__ w0, const float* __restrict__ w1,
                                __half* __restrict__ o0, __half* __restrict__ o1) {
    int row = blockIdx.x;
    int seg = blockIdx.y;
    const __half* x = comb1 + (size_t)row * NC1_ + (seg ? QLR_ : 0);
    const float* w = seg ? w1 : w0;
    __half* y = (seg ? o1 + (size_t)row * KVLR_ : o0 + (size_t)row * QLR_);
    int dim = seg ? KVLR_ : QLR_;
    float s = 0.f;
    for (int i = threadIdx.x; i < dim; i += blockDim.x) { float v = ld_f(x + i); s += v * v; }
    __shared__ float red[8];
    int lane = threadIdx.x & 31, wid = threadIdx.x >> 5;
    s = warp_sum(s);
    if (lane == 0) red[wid] = s;
    __syncthreads();
    if (wid == 0) {
        float r = (lane < (int)(blockDim.x >> 5)) ? red[lane] : 0.f;
        r = warp_sum(r);
        if (lane == 0) red[0] = r;
    }
    __syncthreads();
    float inv = rsqrtf(red[0] / (float)dim + 1e-6f);
    for (int i = threadIdx.x; i < dim; i += blockDim.x)
        y[i] = __float2half(ld_f(x + i) * inv * w[i]);
}

// ---------------- V transpose pre-pass: kv16 V-part -> vt[h][vd][S/2] pair words ----
__global__ void vtr_kernel(const __half* __restrict__ kv16, uint32_t* __restrict__ vt) {
    __shared__ __half sm[64 * 130];
    int h = blockIdx.y, kb = blockIdx.x * 64;
    int t = threadIdx.x;
    for (int idx = t; idx < 64 * 64; idx += 128) {
        int row = idx >> 6, w = idx & 63;
        *(uint32_t*)&sm[row * 130 + 2 * w] =
            *(const uint32_t*)(kv16 + (size_t)(kb + row) * KVDIM_ + h * 256 + 128 + 2 * w);
    }
    __syncthreads();
    for (int idx = t; idx < 128 * 32; idx += 128) {
        int vd = idx >> 5, p = idx & 31;
        __half2 hh = __halves2half2(sm[(2 * p) * 130 + vd], sm[(2 * p + 1) * 130 + vd]);
        vt[((size_t)(h * 128 + vd) << 10) + blockIdx.x * 32 + p] = *(uint32_t*)&hh;
    }
}

// ---------------- fp16 tensor-core GEMM body (shared) ----------------
#define AP16 20
#define BP16 136
#define GSTAGE (128*AP16 + 16*BP16)
#define GEMMF_SMEM (3 * GSTAGE * 4)

template<typename CT, bool SILU>
__device__ __forceinline__ void gemm_body(
        const __half* __restrict__ A, const uint32_t* __restrict__ Bw,
        const float* __restrict__ Cadd, CT* __restrict__ C,
        int N, int K, int m0, int n0, uint32_t* smw) {
    const int t = threadIdx.x;
    const int warp = t >> 5, lane = t & 31;
    const int wm = warp >> 1, wn = warp & 1;
    const int g = lane >> 2, t4 = lane & 3;

    float acc[2][8][4] = {};

    auto load_stage = [&](int st, int kt) {
        uint32_t* as = smw + st * GSTAGE;
        uint32_t* bs = as + 128 * AP16;
        #pragma unroll
        for (int i = 0; i < 2; i++) {
            int id = t + i * 256;
            int row = id >> 2, c = id & 3;
            uint32_t dst = (uint32_t)__cvta_generic_to_shared(as + row * AP16 + c * 4);
            const __half* src = A + (size_t)(m0 + row) * K + kt * 32 + c * 8;
            asm volatile("cp.async.cg.shared.global [%0], [%1], 16;\n" :: "r"(dst), "l"(src));
        }
        #pragma unroll
        for (int i = 0; i < 2; i++) {
            int id = t + i * 256;
            int prow = id >> 5, c = id & 31;
            uint32_t dst = (uint32_t)__cvta_generic_to_shared(bs + prow * BP16 + c * 4);
            const uint32_t* src = Bw + (size_t)(kt * 16 + prow) * N + n0 + c * 4;
            asm volatile("cp.async.cg.shared.global [%0], [%1], 16;\n" :: "r"(dst), "l"(src));
        }
        asm volatile("cp.async.commit_group;\n");
    };

    auto compute = [&](int st) {
        const uint32_t* as = smw + st * GSTAGE;
        const uint32_t* bs = as + 128 * AP16;
        #pragma unroll
        for (int kc = 0; kc < 2; kc++) {
            const int kw = kc * 8;
            uint32_t af[2][4], bf[8][2];
            #pragma unroll
            for (int i = 0; i < 2; i++) {
                int rbase = wm * 32 + i * 16;
                af[i][0] = as[(rbase + g    ) * AP16 + kw + t4];
                af[i][1] = as[(rbase + 8 + g) * AP16 + kw + t4];
                af[i][2] = as[(rbase + g    ) * AP16 + kw + 4 + t4];
                af[i][3] = as[(rbase + 8 + g) * AP16 + kw + 4 + t4];
            }
            #pragma unroll
            for (int j = 0; j < 8; j++) {
                int cbase = wn * 64 + j * 8 + g;
                bf[j][0] = bs[(kw + t4    ) * BP16 + cbase];
                bf[j][1] = bs[(kw + 4 + t4) * BP16 + cbase];
            }
            #pragma unroll
            for (int i = 0; i < 2; i++)
                #pragma unroll
                for (int j = 0; j < 8; j++)
                    mma_fp16(acc[i][j], af[i], bf[j]);
        }
    };

    const int nk = K / 32;
    load_stage(0, 0);
    if (nk > 1) load_stage(1, 1);

    for (int kt = 0; kt < nk; kt++) {
        if (kt + 1 < nk) { asm volatile("cp.async.wait_group 1;\n"); }
        else             { asm volatile("cp.async.wait_group 0;\n"); }
        __syncthreads();
        if (kt + 2 < nk) load_stage((kt + 2) % 3, kt + 2);
        compute(kt % 3);
    }

    #pragma unroll
    for (int i = 0; i < 2; i++) {
        int r0 = m0 + wm * 32 + i * 16 + g;
        #pragma unroll
        for (int j = 0; j < 8; j++) {
            int cc = n0 + wn * 64 + j * 8 + 2 * t4;   // always even
            float v0 = acc[i][j][0], v1 = acc[i][j][1];
            float v2 = acc[i][j][2], v3 = acc[i][j][3];
            if constexpr (SILU) {
                float sg0 = v0 / (1.f + __expf(-v0));
                float sg2 = v2 / (1.f + __expf(-v2));
                C[(size_t)r0 * (N >> 1) + (cc >> 1)]       = (CT)__float2half(sg0 * v1);
                C[(size_t)(r0 + 8) * (N >> 1) + (cc >> 1)] = (CT)__float2half(sg2 * v3);
            } else {
                size_t o0 = (size_t)r0 * N + cc;
                size_t o1 = (size_t)(r0 + 8) * N + cc;
                if (Cadd) { v0 += Cadd[o0]; v1 += Cadd[o0 + 1]; v2 += Cadd[o1]; v3 += Cadd[o1 + 1]; }
                if constexpr (sizeof(CT) == 4) {
                    C[o0] = v0; C[o0 + 1] = v1; C[o1] = v2; C[o1 + 1] = v3;
                } else {
                    *(uint32_t*)&C[o0] = packh2(v0, v1);
                    *(uint32_t*)&C[o1] = packh2(v2, v3);
                }
            }
        }
    }
}

template<typename CT, bool SILU>
__global__ __launch_bounds__(256, 2) void gemm_fp16(
        const __half* __restrict__ A, const uint32_t* __restrict__ Bw,
        const float* __restrict__ Cadd, CT* __restrict__ C,
        int M, int N, int K) {
    extern __shared__ uint32_t smw[];
    gemm_body<CT, SILU>(A, Bw, Cadd, C, N, K, blockIdx.y * 128, blockIdx.x * 128, smw);
}

// dual independent GEMMs (both fp16 out, no Cadd) packed into one grid.
// blockIdx.x < nt1 -> GEMM1 column tiles, else GEMM2.
__global__ __launch_bounds__(256, 2) void gemm_dual_h(
        const __half* __restrict__ A1, const uint32_t* __restrict__ B1,
        __half* __restrict__ C1, int N1, int K1, int nt1,
        const __half* __restrict__ A2, const uint32_t* __restrict__ B2,
        __half* __restrict__ C2, int N2, int K2) {
    extern __shared__ uint32_t smw[];
    if ((int)blockIdx.x < nt1) {
        gemm_body<__half, false>(A1, B1, nullptr, C1, N1, K1,
                                 blockIdx.y * 128, blockIdx.x * 128, smw);
    } else {
        gemm_body<__half, false>(A2, B2, nullptr, C2, N2, K2,
                                 blockIdx.y * 128, (blockIdx.x - nt1) * 128, smw);
    }
}

// ---------------- RoPE on fp16 q (in place) + fp16 kpe out (fp16 ckv source) -------
__global__ void rope_kernel(__half* __restrict__ q16, const __half* __restrict__ ckv_base,
                            int ckv_stride, __half* __restrict__ kpe16,
                            const float* __restrict__ cosb, const float* __restrict__ sinb,
                            const int* __restrict__ pos_ids) {
    int s = blockIdx.x;
    int pos = pos_ids[s];
    const float* c  = cosb + (size_t)pos * ROPE_;
    const float* sn = sinb + (size_t)pos * ROPE_;
    int t = threadIdx.x;
    float ox[4], oy[4];
    #pragma unroll
    for (int it = 0; it < 4; it++) {
        int item = t + it * 128;
        int h = item >> 5, i = item & 31;
        __half* base = q16 + (size_t)s * QDIM_ + h * QHD_ + NOPE_;
        float x0 = __half2float(base[2 * i]), x1 = __half2float(base[2 * i + 1]);
        ox[it] = x0 * c[i]      - x1 * sn[i];
        oy[it] = x1 * c[i + 32] + x0 * sn[i + 32];
    }
    __syncthreads();
    #pragma unroll
    for (int it = 0; it < 4; it++) {
        int item = t + it * 128;
        int h = item >> 5, i = item & 31;
        __half* base = q16 + (size_t)s * QDIM_ + h * QHD_ + NOPE_;
        base[i]      = __float2half(ox[it]);
        base[i + 32] = __float2half(oy[it]);
    }
    if (t < 32) {
        const __half* kb = ckv_base + (size_t)s * ckv_stride + KVLR_;
        float x0 = __half2float(kb[2 * t]), x1 = __half2float(kb[2 * t + 1]);
        kpe16[(size_t)s * ROPE_ + t]      = __float2half(x0 * c[t]      - x1 * sn[t]);
        kpe16[(size_t)s * ROPE_ + 32 + t] = __float2half(x1 * c[t + 32] + x0 * sn[t + 32]);
    }
}

// ---------------- fp16 flash attention, cp.async pipelined, log2-domain softmax ----
#define AQW 100
#define AKW 100
#define AVW 36
#define APW 36
#define ATT_SMEM_WORDS (64*AQW + 2*64*AKW + 128*AVW + 64*APW)   // 104448 B

__global__ __launch_bounds__(128, 2) void attn_mma_kernel(
        const __half* __restrict__ q16, const __half* __restrict__ kv16,
        const uint32_t* __restrict__ vt, const __half* __restrict__ kpe16,
        __half* __restrict__ out) {
    extern __shared__ uint32_t smw[];
    uint32_t* qw  = smw;                     // [64][AQW]
    uint32_t* kst = qw + 64 * AQW;           // 2 x [64][AKW]
    uint32_t* vst = kst + 2 * 64 * AKW;      // [128][AVW]
    uint32_t* pw  = vst + 128 * AVW;         // [64][APW]

    const int h = blockIdx.y;
    const int qblk = (int)gridDim.x - 1 - (int)blockIdx.x;   // heavy blocks first
    const int t = threadIdx.x;
    const int warp = t >> 5, lane = t & 31;
    const int g = lane >> 2, t4 = lane & 3;
    const int qbase = qblk * 64;
    const int wrow = warp * 16;

    auto load_k = [&](int kt, int st) {
        uint32_t* ks = kst + st * 64 * AKW;
        const int kbase = kt * 64;
        for (int idx = t; idx < 64 * 24; idx += 128) {
            int row = idx / 24, c = idx - row * 24;
            uint32_t dst;
            const __half* src;
            if (c < 16) {
                dst = (uint32_t)__cvta_generic_to_shared(ks + row * AKW + c * 4);
                src = kv16 + (size_t)(kbase + row) * KVDIM_ + h * 256 + c * 8;
            } else {
                dst = (uint32_t)__cvta_generic_to_shared(ks + row * AKW + 64 + (c - 16) * 4);
                src = kpe16 + (size_t)(kbase + row) * ROPE_ + (c - 16) * 8;
            }
            asm volatile("cp.async.cg.shared.global [%0], [%1], 16;\n" :: "r"(dst), "l"(src));
        }
        asm volatile("cp.async.commit_group;\n");
    };
    auto load_v = [&](int kt) {
        const uint32_t* base = vt + ((size_t)(h * 128) << 10) + kt * 32;
        for (int idx = t; idx < 128 * 8; idx += 128) {
            int vd = idx >> 3, c = idx & 7;
            uint32_t dst = (uint32_t)__cvta_generic_to_shared(vst + vd * AVW + c * 4);
            const uint32_t* src = base + ((size_t)vd << 10) + c * 4;
            asm volatile("cp.async.cg.shared.global [%0], [%1], 16;\n" :: "r"(dst), "l"(src));
        }
        asm volatile("cp.async.commit_group;\n");
    };

    // K(0) and Q in flight together
    load_k(0, 0);
    for (int idx = t; idx < 64 * 24; idx += 128) {
        int row = idx / 24, c = idx - row * 24;
        uint32_t dst = (uint32_t)__cvta_generic_to_shared(qw + row * AQW + c * 4);
        const __half* src = q16 + (size_t)(qbase + row) * QDIM_ + h * QHD_ + c * 8;
        asm volatile("cp.async.cg.shared.global [%0], [%1], 16;\n" :: "r"(dst), "l"(src));
    }
    asm volatile("cp.async.commit_group;\n");

    float oa[16][4];
    #pragma unroll
    for (int j = 0; j < 16; j++)
        #pragma unroll
        for (int c = 0; c < 4; c++) oa[j][c] = 0.f;
    float m0 = -1e30f, m1 = -1e30f, l0 = 0.f, l1 = 0.f;

    for (int kt = 0; kt <= qblk; kt++) {
        const int kbase = kt * 64;
        const bool havenext = (kt + 1 <= qblk);
        asm volatile("cp.async.wait_group 0;\n");   // K(kt) (+Q at kt=0) arrived
        __syncthreads();
        load_v(kt);                                 // overlaps S compute
        if (havenext) load_k(kt + 1, (kt + 1) & 1);

        // ---- S = Q @ K^T ----
        const uint32_t* ks = kst + (kt & 1) * 64 * AKW;
        float sa[8][4];
        #pragma unroll
        for (int j = 0; j < 8; j++)
            #pragma unroll
            for (int c = 0; c < 4; c++) sa[j][c] = 0.f;
        #pragma unroll
        for (int kc = 0; kc < 12; kc++) {
            const int kw0 = kc * 8;
            uint32_t af[4], bf[8][2];
            af[0] = qw[(wrow + g    ) * AQW + kw0 + t4];
            af[1] = qw[(wrow + 8 + g) * AQW + kw0 + t4];
            af[2] = qw[(wrow + g    ) * AQW + kw0 + 4 + t4];
            af[3] = qw[(wrow + 8 + g) * AQW + kw0 + 4 + t4];
            #pragma unroll
            for (int j = 0; j < 8; j++) {
                bf[j][0] = ks[(j * 8 + g) * AKW + kw0 + t4];
                bf[j][1] = ks[(j * 8 + g) * AKW + kw0 + 4 + t4];
            }
            #pragma unroll
            for (int j = 0; j < 8; j++) mma_fp16(sa[j], af, bf[j]);
        }

        // ---- mask + scale (log2 domain) ----
        const int r0 = qbase + wrow + g;
        const int r1 = r0 + 8;
        const bool diag = (kt == qblk);
        #pragma unroll
        for (int j = 0; j < 8; j++) {
            int c0 = kbase + j * 8 + 2 * t4, c1 = c0 + 1;
            sa[j][0] *= SCALEL2_; sa[j][1] *= SCALEL2_;
            sa[j][2] *= SCALEL2_; sa[j][3] *= SCALEL2_;
            if (diag) {
                if (c0 > r0) sa[j][0] = -1e30f;
                if (c1 > r0) sa[j][1] = -1e30f;
                if (c0 > r1) sa[j][2] = -1e30f;
                if (c1 > r1) sa[j][3] = -1e30f;
            }
        }

        // ---- online softmax (exp2) ----
        float tm0 = -1e30f, tm1 = -1e30f;
        #pragma unroll
        for (int j = 0; j < 8; j++) {
            tm0 = fmaxf(tm0, fmaxf(sa[j][0], sa[j][1]));
            tm1 = fmaxf(tm1, fmaxf(sa[j][2], sa[j][3]));
        }
        tm0 = fmaxf(tm0, __shfl_xor_sync(0xffffffffu, tm0, 1));
        tm0 = fmaxf(tm0, __shfl_xor_sync(0xffffffffu, tm0, 2));
        tm1 = fmaxf(tm1, __shfl_xor_sync(0xffffffffu, tm1, 1));
        tm1 = fmaxf(tm1, __shfl_xor_sync(0xffffffffu, tm1, 2));
        float m0n = fmaxf(m0, tm0), m1n = fmaxf(m1, tm1);
        float a0 = exp2f(m0 - m0n), a1 = exp2f(m1 - m1n);
        float ps0 = 0.f, ps1 = 0.f;
        #pragma unroll
        for (int j = 0; j < 8; j++) {
            sa[j][0] = exp2f(sa[j][0] - m0n); sa[j][1] = exp2f(sa[j][1] - m0n);
            sa[j][2] = exp2f(sa[j][2] - m1n); sa[j][3] = exp2f(sa[j][3] - m1n);
            ps0 += sa[j][0] + sa[j][1];
            ps1 += sa[j][2] + sa[j][3];
        }
        ps0 += __shfl_xor_sync(0xffffffffu, ps0, 1);
        ps0 += __shfl_xor_sync(0xffffffffu, ps0, 2);
        ps1 += __shfl_xor_sync(0xffffffffu, ps1, 1);
        ps1 += __shfl_xor_sync(0xffffffffu, ps1, 2);
        l0 = l0 * a0 + ps0; l1 = l1 * a1 + ps1;
        m0 = m0n; m1 = m1n;
        #pragma unroll
        for (int j = 0; j < 16; j++) {
            oa[j][0] *= a0; oa[j][1] *= a0;
            oa[j][2] *= a1; oa[j][3] *= a1;
        }
        #pragma unroll
        for (int j = 0; j < 8; j++) {
            pw[(wrow + g    ) * APW + j * 4 + t4] = packh2(sa[j][0], sa[j][1]);
            pw[(wrow + 8 + g) * APW + j * 4 + t4] = packh2(sa[j][2], sa[j][3]);
        }
        __syncwarp();

        // ---- wait V, then O += P @ V ----
        if (havenext) { asm volatile("cp.async.wait_group 1;\n"); }
        else          { asm volatile("cp.async.wait_group 0;\n"); }
        __syncthreads();
        #pragma unroll
        for (int kc = 0; kc < 4; kc++) {
            const int kw0 = kc * 8;
            uint32_t af[4], bf[16][2];
            af[0] = pw[(wrow + g    ) * APW + kw0 + t4];
            af[1] = pw[(wrow + 8 + g) * APW + kw0 + t4];
            af[2] = pw[(wrow + g    ) * APW + kw0 + 4 + t4];
            af[3] = pw[(wrow + 8 + g) * APW + kw0 + 4 + t4];
            #pragma unroll
            for (int j = 0; j < 16; j++) {
                bf[j][0] = vst[(j * 8 + g) * AVW + kw0 + t4];
                bf[j][1] = vst[(j * 8 + g) * AVW + kw0 + 4 + t4];
            }
            #pragma unroll
            for (int j = 0; j < 16; j++) mma_fp16(oa[j], af, bf[j]);
        }
        __syncthreads();   // all warps done with V before next tile's load_v
    }

    float i0 = 1.f / l0, i1 = 1.f / l1;
    const int r0 = qbase + wrow + g;
    __half* o0 = out + (size_t)r0 * H_ + h * VHD_;
    __half* o1 = out + (size_t)(r0 + 8) * H_ + h * VHD_;
    #pragma unroll
    for (int j = 0; j < 16; j++) {
        int cc = j * 8 + 2 * t4;
        o0[cc]     = __float2half(oa[j][0] * i0);
        o0[cc + 1] = __float2half(oa[j][1] * i0);
        o1[cc]     = __float2half(oa[j][2] * i1);
        o1[cc + 1] = __float2half(oa[j][3] * i1);
    }
}

// ---------------- launcher ----------------
extern "C" void kernel_launch(void* const* d_in, const int* in_sizes, int n_in,
                              void* d_out, int out_size) {
    const float* hidden  = (const float*)d_in[0];
    const float* sinb    = (const float*)d_in[1];
    const float* cosb    = (const float*)d_in[2];
    const float* wq_a    = (const float*)d_in[3];
    const float* q_a_ln  = (const float*)d_in[4];
    const float* wq_b    = (const float*)d_in[5];
    const float* wkv_a   = (const float*)d_in[6];
    const float* kv_a_ln = (const float*)d_in[7];
    const float* wkv_b   = (const float*)d_in[8];
    const float* wo      = (const float*)d_in[9];
    const float* in_ln   = (const float*)d_in[10];
    const float* post_ln = (const float*)d_in[11];
    const float* w_gate  = (const float*)d_in[12];
    const float* w_up    = (const float*)d_in[13];
    const float* w_down  = (const float*)d_in[14];
    const int*   pos     = (const int*)d_in[15];
    float* outp = (float*)d_out;

    float *hid2;
    __half *comb1, *q16, *kv16, *kpe16, *xnorm16, *qlat16, *kvn16, *attn16, *ynorm16, *gate16;
    uint32_t *vt, *wqakva16, *wqb16, *wkvb16, *wo16, *wgu16, *wd16;
    cudaGetSymbolAddress((void**)&hid2,  g_hid2);
    cudaGetSymbolAddress((void**)&comb1, g_comb1);
    cudaGetSymbolAddress((void**)&q16,   g_q16);
    cudaGetSymbolAddress((void**)&kv16,  g_kv16);
    cudaGetSymbolAddress((void**)&kpe16, g_kpe16);
    cudaGetSymbolAddress((void**)&vt,    g_vt);
    cudaGetSymbolAddress((void**)&xnorm16, g_xnorm16);
    cudaGetSymbolAddress((void**)&qlat16,  g_qlat16);
    cudaGetSymbolAddress((void**)&kvn16,   g_kvn16);
    cudaGetSymbolAddress((void**)&attn16,  g_attn16);
    cudaGetSymbolAddress((void**)&ynorm16, g_ynorm16);
    cudaGetSymbolAddress((void**)&gate16,  g_gate16);
    cudaGetSymbolAddress((void**)&wqakva16, g_wqakva16);
    cudaGetSymbolAddress((void**)&wqb16,    g_wqb16);
    cudaGetSymbolAddress((void**)&wkvb16,   g_wkvb16);
    cudaGetSymbolAddress((void**)&wo16,     g_wo16);
    cudaGetSymbolAddress((void**)&wgu16,    g_wgu16);
    cudaGetSymbolAddress((void**)&wd16,     g_wd16);

    const size_t attn_smem = ATT_SMEM_WORDS * sizeof(uint32_t);
    cudaFuncSetAttribute(attn_mma_kernel, cudaFuncAttributeMaxDynamicSharedMemorySize, (int)attn_smem);
    cudaFuncSetAttribute((gemm_fp16<float, false>),  cudaFuncAttributeMaxDynamicSharedMemorySize, GEMMF_SMEM);
    cudaFuncSetAttribute((gemm_fp16<__half, false>), cudaFuncAttributeMaxDynamicSharedMemorySize, GEMMF_SMEM);
    cudaFuncSetAttribute((gemm_fp16<__half, true>),  cudaFuncAttributeMaxDynamicSharedMemorySize, GEMMF_SMEM);
    cudaFuncSetAttribute(gemm_dual_h, cudaFuncAttributeMaxDynamicSharedMemorySize, GEMMF_SMEM);

    // 0) convert weights (vectorized; gate/up fused-interleaved)
    auto cvt4 = [&](const float* w, uint32_t* o, int K, int Nsrc, int dstStride, int colOff) {
        int n = (K / 2) * (Nsrc / 4);
        cvt_pair_v4<<<(n + 255) / 256, 256>>>(w, o, K / 2, Nsrc / 4, Nsrc, dstStride, colOff);
    };
    cvt4(wq_a,   wqakva16, H_,    QLR_,   NC1_,   0);
    cvt4(wkv_a,  wqakva16, H_,    CKVD_,  NC1_,   QLR_);
    cvt4(wq_b,   wqb16,    QLR_,  QDIM_,  QDIM_,  0);
    cvt4(wkv_b,  wkvb16,   KVLR_, KVDIM_, KVDIM_, 0);
    cvt4(wo,     wo16,     H_,    H_,     H_,     0);
    cvt4(w_down, wd16,     FF_,   H_,     H_,     0);
    {
        int n = (H_ / 2) * (FF_ / 2);
        cvt_gu_kernel<<<(n + 255) / 256, 256>>>(w_gate, w_up, wgu16);
    }

    dim3 blk256(256);
    auto gemm = [&](const __half* A, const uint32_t* Bw, const float* Cadd, float* C,
                    int M, int N, int K) {
        gemm_fp16<float, false><<<dim3(N / 128, M / 128), blk256, GEMMF_SMEM>>>(A, Bw, Cadd, C, M, N, K);
    };
    auto gemm_h = [&](const __half* A, const uint32_t* Bw, __half* C,
                      int M, int N, int K) {
        gemm_fp16<__half, false><<<dim3(N / 128, M / 128), blk256, GEMMF_SMEM>>>(A, Bw, nullptr, C, M, N, K);
    };

    // 1) xnorm16 = rms(hidden, in_ln)
    rms_kernel<float><<<S_, 256>>>(hidden, in_ln, xnorm16, H_, H_, H_);
    // 2+5) comb1 = xnorm16 @ [wq_a | wkv_a]   (fp16 out)
    gemm_h(xnorm16, wqakva16, comb1, S_, NC1_, H_);
    // 3+6) qlat16 / kvn16 = rms(comb1 segments)   (one launch)
    rms_dual_kernel<<<dim3(S_, 2), 256>>>(comb1, q_a_ln, kv_a_ln, qlat16, kvn16);
    // 4+7) q16 = qlat16 @ wq_b  AND  kv16 = kvn16 @ wkv_b   (one packed launch)
    gemm_dual_h<<<dim3(QDIM_/128 + KVDIM_/128, S_/128), blk256, GEMMF_SMEM>>>(
        qlat16, wqb16, q16, QDIM_, QLR_, QDIM_/128,
        kvn16, wkvb16, kv16, KVDIM_, KVLR_);
    // 7b) V transpose pre-pass
    vtr_kernel<<<dim3(S_/64, NH_), 128>>>(kv16, vt);
    // 8) RoPE (q16 in place; kpe16 out)
    rope_kernel<<<S_, 128>>>(q16, comb1 + QLR_, NC1_, kpe16, cosb, sinb, pos);
    // 9) attention (pipelined fp16, exp2 softmax)
    attn_mma_kernel<<<dim3(S_/64, NH_), 128, attn_smem>>>(q16, kv16, vt, kpe16, attn16);
    // 10) hid2 = hidden + attn16 @ wo
    gemm(attn16, wo16, hidden, hid2, S_, H_, H_);
    // 11) ynorm16 = rms(hid2, post_ln)
    rms_kernel<float><<<S_, 256>>>(hid2, post_ln, ynorm16, H_, H_, H_);
    // 12+13+14) gate16 = silu(ynorm16 @ w_gate) * (ynorm16 @ w_up)   [fused epilogue]
    gemm_fp16<__half, true><<<dim3(NC2_/128, S_/128), blk256, GEMMF_SMEM>>>(
        ynorm16, wgu16, nullptr, gate16, S_, NC2_, H_);
    // 15) out = hid2 + gate16 @ w_down
    gemm(gate16, wd16, hid2, outp, S_, H_, FF_);
}